// round 2
// baseline (speedup 1.0000x reference)
#include <cuda_runtime.h>
#include <cstdint>
#include <cstddef>

// Problem dims (fixed): B=4096, T=32, H=16, HS=32, E=512
//   M = B*T = 131072, N = H*HS = 512, K = E = 512
#define MDIM 131072
#define NDIM 512
#define KDIM 512

// Single scratch buffer: attention output in proj-ready transposed layout
//   Ot[(b*32 + d)*512 + h*32 + t]
__device__ float g_Ot[(size_t)MDIM * NDIM];

// ---------------------------------------------------------------------------
// TF32 helpers
// ---------------------------------------------------------------------------
__device__ __forceinline__ uint32_t tf32_rna(float x) {
    uint32_t y;
    asm("cvt.rna.tf32.f32 %0, %1;" : "=r"(y) : "f"(x));
    return y;
}

__device__ __forceinline__ void mma_tf32(float c[4], const uint32_t a[4], const uint32_t b[2]) {
    asm volatile(
        "mma.sync.aligned.m16n8k8.row.col.f32.tf32.tf32.f32 "
        "{%0,%1,%2,%3}, {%4,%5,%6,%7}, {%8,%9}, {%0,%1,%2,%3};\n"
        : "+f"(c[0]), "+f"(c[1]), "+f"(c[2]), "+f"(c[3])
        : "r"(a[0]), "r"(a[1]), "r"(a[2]), "r"(a[3]), "r"(b[0]), "r"(b[1]));
}

// ===========================================================================
// Fused QKV GEMM + attention.
// Grid: (NDIM/64, MDIM/128) = (8, 1024). Block: 256 threads = 8 warps (4x2).
// Block computes Q,K,V tiles [128 rows x 64 cols] via tf32 mma, i.e.
// 4 batches x 2 heads. Warp (wm, wn) owns exactly batch (b0+wm), head
// (h0+wn): a complete 32x32 Q/K/V set -> attention is warp-local.
// Dynamic smem (union):
//   GEMM phase:  xs[128*20] + ws[3][64*20]          = 25.6 KB
//   Attn  phase: per-warp bufs 8 * 3 * 32*33 floats = 101.4 KB  (total size)
// ===========================================================================
#define BK 16
#define SST 20           // 16 + 4 pad
#define ATS 33           // 32 + 1 pad
#define FUSED_SMEM_BYTES (8 * 3 * 32 * ATS * 4)

extern "C" __global__ void __launch_bounds__(256, 1) fused_qkv_attn(
    const float* __restrict__ X,
    const float* __restrict__ Wq, const float* __restrict__ Wk,
    const float* __restrict__ Wv, float* __restrict__ Ot)
{
    extern __shared__ float smem[];
    // GEMM-phase views
    float* xs = smem;                       // [128][SST]
    float* ws = smem + 128 * SST;           // [3][64][SST]

    const int tid  = threadIdx.x;
    const int lane = tid & 31;
    const int warp = tid >> 5;
    const int wm   = warp & 3;    // batch within block (row stripe 32)
    const int wn   = warp >> 2;   // head within block  (col stripe 32)
    const int g    = lane >> 2;   // 0..7
    const int t4   = lane & 3;    // 0..3

    const int m0 = blockIdx.y * 128;
    const int n0 = blockIdx.x * 64;

    // global load mapping
    const int ldrow = tid >> 1;          // 0..127 (x rows)
    const int ldcol = (tid & 1) * 8;     // 0 or 8
    const int wrow  = tid >> 2;          // 0..63  (w rows)
    const int wcol  = (tid & 3) * 4;     // 0,4,8,12

    const float* Xg  = X  + (size_t)(m0 + ldrow) * KDIM + ldcol;
    const float* Wg[3];
    Wg[0] = Wq + (size_t)(n0 + wrow) * KDIM + wcol;
    Wg[1] = Wk + (size_t)(n0 + wrow) * KDIM + wcol;
    Wg[2] = Wv + (size_t)(n0 + wrow) * KDIM + wcol;

    // accumulators: [matrix][mi][ni][reg]  (warp tile 32x32 per matrix)
    float acc[3][2][4][4];
    #pragma unroll
    for (int m = 0; m < 3; m++)
        #pragma unroll
        for (int mi = 0; mi < 2; mi++)
            #pragma unroll
            for (int ni = 0; ni < 4; ni++)
                #pragma unroll
                for (int r = 0; r < 4; r++) acc[m][mi][ni][r] = 0.f;

    for (int kt = 0; kt < KDIM; kt += BK) {
        // stage x tile (2 float4 per thread) and w tiles (1 float4 each)
        float4 a0 = *(const float4*)(Xg + kt);
        float4 a1 = *(const float4*)(Xg + kt + 4);
        float4 w0 = *(const float4*)(Wg[0] + kt);
        float4 w1 = *(const float4*)(Wg[1] + kt);
        float4 w2 = *(const float4*)(Wg[2] + kt);

        // tf32-round in registers
        a0.x = __uint_as_float(tf32_rna(a0.x)); a0.y = __uint_as_float(tf32_rna(a0.y));
        a0.z = __uint_as_float(tf32_rna(a0.z)); a0.w = __uint_as_float(tf32_rna(a0.w));
        a1.x = __uint_as_float(tf32_rna(a1.x)); a1.y = __uint_as_float(tf32_rna(a1.y));
        a1.z = __uint_as_float(tf32_rna(a1.z)); a1.w = __uint_as_float(tf32_rna(a1.w));
        w0.x = __uint_as_float(tf32_rna(w0.x)); w0.y = __uint_as_float(tf32_rna(w0.y));
        w0.z = __uint_as_float(tf32_rna(w0.z)); w0.w = __uint_as_float(tf32_rna(w0.w));
        w1.x = __uint_as_float(tf32_rna(w1.x)); w1.y = __uint_as_float(tf32_rna(w1.y));
        w1.z = __uint_as_float(tf32_rna(w1.z)); w1.w = __uint_as_float(tf32_rna(w1.w));
        w2.x = __uint_as_float(tf32_rna(w2.x)); w2.y = __uint_as_float(tf32_rna(w2.y));
        w2.z = __uint_as_float(tf32_rna(w2.z)); w2.w = __uint_as_float(tf32_rna(w2.w));

        __syncthreads();
        *(float4*)(&xs[ldrow * SST + ldcol])     = a0;
        *(float4*)(&xs[ldrow * SST + ldcol + 4]) = a1;
        *(float4*)(&ws[0 * 64 * SST + wrow * SST + wcol]) = w0;
        *(float4*)(&ws[1 * 64 * SST + wrow * SST + wcol]) = w1;
        *(float4*)(&ws[2 * 64 * SST + wrow * SST + wcol]) = w2;
        __syncthreads();

        #pragma unroll
        for (int kk = 0; kk < BK; kk += 8) {
            uint32_t af[2][4];
            #pragma unroll
            for (int mi = 0; mi < 2; mi++) {
                const int r = (wm * 32 + mi * 16 + g) * SST + kk + t4;
                af[mi][0] = __float_as_uint(xs[r]);
                af[mi][1] = __float_as_uint(xs[r + 8 * SST]);
                af[mi][2] = __float_as_uint(xs[r + 4]);
                af[mi][3] = __float_as_uint(xs[r + 8 * SST + 4]);
            }
            #pragma unroll
            for (int m = 0; m < 3; m++) {
                #pragma unroll
                for (int ni = 0; ni < 4; ni++) {
                    uint32_t bf[2];
                    const int r = m * 64 * SST + (wn * 32 + ni * 8 + g) * SST + kk + t4;
                    bf[0] = __float_as_uint(ws[r]);
                    bf[1] = __float_as_uint(ws[r + 4]);
                    #pragma unroll
                    for (int mi = 0; mi < 2; mi++)
                        mma_tf32(acc[m][mi][ni], af[mi], bf);
                }
            }
        }
    }

    // --- phase switch: all warps done reading GEMM smem before reuse ---
    __syncthreads();

    // per-warp attention buffers (union with GEMM smem region)
    float* aw = smem + warp * (3 * 32 * ATS);
    float* Qb = aw;
    float* Kb = aw + 32 * ATS;
    float* Vb = aw + 2 * 32 * ATS;
    float* bufs[3] = {Qb, Kb, Vb};

    #pragma unroll
    for (int m = 0; m < 3; m++) {
        #pragma unroll
        for (int mi = 0; mi < 2; mi++) {
            #pragma unroll
            for (int ni = 0; ni < 4; ni++) {
                const int r = mi * 16 + g;
                const int c = ni * 8 + t4 * 2;
                bufs[m][r * ATS + c]           = acc[m][mi][ni][0];
                bufs[m][r * ATS + c + 1]       = acc[m][mi][ni][1];
                bufs[m][(r + 8) * ATS + c]     = acc[m][mi][ni][2];
                bufs[m][(r + 8) * ATS + c + 1] = acc[m][mi][ni][3];
            }
        }
    }
    __syncwarp();

    // warp-local causal attention: lane = query index t
    float q[32];
    #pragma unroll
    for (int d = 0; d < 32; d++) q[d] = Qb[lane * ATS + d];

    const float scale = 0.17677669529663689f;  // 32^-0.5
    float s[32];
    #pragma unroll
    for (int j = 0; j < 32; j++) {
        float a = 0.f;
        #pragma unroll
        for (int d = 0; d < 32; d++) a = fmaf(q[d], Kb[j * ATS + d], a);
        s[j] = (j <= lane) ? a * scale : -1e30f;
    }

    float mx = -1e30f;
    #pragma unroll
    for (int j = 0; j < 32; j++) mx = fmaxf(mx, s[j]);
    float sum = 0.f;
    #pragma unroll
    for (int j = 0; j < 32; j++) { float e = __expf(s[j] - mx); s[j] = e; sum += e; }
    const float inv = 1.0f / sum;

    float o[32];
    #pragma unroll
    for (int d = 0; d < 32; d++) o[d] = 0.f;
    #pragma unroll
    for (int j = 0; j < 32; j++) {
        const float p = s[j];
        #pragma unroll
        for (int d = 0; d < 32; d++) o[d] = fmaf(p, Vb[j * ATS + d], o[d]);
    }

    // write Ot[(b*32+d)*512 + h*32 + t]  (t = lane -> coalesced)
    const int b = blockIdx.y * 4 + wm;
    const int h = blockIdx.x * 2 + wn;
    #pragma unroll
    for (int d = 0; d < 32; d++)
        Ot[(size_t)(b * 32 + d) * 512 + h * 32 + lane] = o[d] * inv;
}

// ===========================================================================
// Projection NT GEMM: out[m,e] = sum_k Ot[m,k] * Wp[e,k] + bp[e]
// BM=128, BN=128, BK=16, 256 threads, warp tile 32x64 (4x2), tf32 mma.
// ===========================================================================
#define PBM 128
#define PBN 128

__global__ void __launch_bounds__(256) proj_gemm_tf32(
    const float* __restrict__ A, const float* __restrict__ Bw,
    float* __restrict__ C, const float* __restrict__ bias)
{
    __shared__ float As[PBM * SST];
    __shared__ float Bs[PBN * SST];

    const int tid  = threadIdx.x;
    const int lane = tid & 31;
    const int warp = tid >> 5;
    const int wm   = warp & 3;
    const int wn   = warp >> 2;
    const int g    = lane >> 2;
    const int t4   = lane & 3;

    const int m0 = blockIdx.y * PBM;
    const int n0 = blockIdx.x * PBN;

    const int ldrow = tid >> 1;
    const int ldcol = (tid & 1) * 8;

    const float* Ag = A  + (size_t)(m0 + ldrow) * KDIM + ldcol;
    const float* Bg = Bw + (size_t)(n0 + ldrow) * KDIM + ldcol;

    float acc[2][8][4];
    #pragma unroll
    for (int mi = 0; mi < 2; mi++)
        #pragma unroll
        for (int ni = 0; ni < 8; ni++)
            #pragma unroll
            for (int r = 0; r < 4; r++) acc[mi][ni][r] = 0.f;

    for (int kt = 0; kt < KDIM; kt += BK) {
        float4 a0 = *(const float4*)(Ag + kt);
        float4 a1 = *(const float4*)(Ag + kt + 4);
        float4 b0 = *(const float4*)(Bg + kt);
        float4 b1 = *(const float4*)(Bg + kt + 4);

        a0.x = __uint_as_float(tf32_rna(a0.x)); a0.y = __uint_as_float(tf32_rna(a0.y));
        a0.z = __uint_as_float(tf32_rna(a0.z)); a0.w = __uint_as_float(tf32_rna(a0.w));
        a1.x = __uint_as_float(tf32_rna(a1.x)); a1.y = __uint_as_float(tf32_rna(a1.y));
        a1.z = __uint_as_float(tf32_rna(a1.z)); a1.w = __uint_as_float(tf32_rna(a1.w));
        b0.x = __uint_as_float(tf32_rna(b0.x)); b0.y = __uint_as_float(tf32_rna(b0.y));
        b0.z = __uint_as_float(tf32_rna(b0.z)); b0.w = __uint_as_float(tf32_rna(b0.w));
        b1.x = __uint_as_float(tf32_rna(b1.x)); b1.y = __uint_as_float(tf32_rna(b1.y));
        b1.z = __uint_as_float(tf32_rna(b1.z)); b1.w = __uint_as_float(tf32_rna(b1.w));

        __syncthreads();
        *(float4*)(&As[ldrow * SST + ldcol])     = a0;
        *(float4*)(&As[ldrow * SST + ldcol + 4]) = a1;
        *(float4*)(&Bs[ldrow * SST + ldcol])     = b0;
        *(float4*)(&Bs[ldrow * SST + ldcol + 4]) = b1;
        __syncthreads();

        #pragma unroll
        for (int kk = 0; kk < BK; kk += 8) {
            uint32_t af[2][4];
            #pragma unroll
            for (int mi = 0; mi < 2; mi++) {
                const int r = (wm * 32 + mi * 16 + g) * SST + kk + t4;
                af[mi][0] = __float_as_uint(As[r]);
                af[mi][1] = __float_as_uint(As[r + 8 * SST]);
                af[mi][2] = __float_as_uint(As[r + 4]);
                af[mi][3] = __float_as_uint(As[r + 8 * SST + 4]);
            }
            uint32_t bf[8][2];
            #pragma unroll
            for (int ni = 0; ni < 8; ni++) {
                const int r = (wn * 64 + ni * 8 + g) * SST + kk + t4;
                bf[ni][0] = __float_as_uint(Bs[r]);
                bf[ni][1] = __float_as_uint(Bs[r + 4]);
            }
            #pragma unroll
            for (int mi = 0; mi < 2; mi++)
                #pragma unroll
                for (int ni = 0; ni < 8; ni++)
                    mma_tf32(acc[mi][ni], af[mi], bf[ni]);
        }
    }

    #pragma unroll
    for (int mi = 0; mi < 2; mi++) {
        #pragma unroll
        for (int ni = 0; ni < 8; ni++) {
            const int m = m0 + wm * 32 + mi * 16 + g;
            const int n = n0 + wn * 64 + ni * 8 + t4 * 2;
            const float bv0 = bias[n];
            const float bv1 = bias[n + 1];
            float2 v01 = make_float2(acc[mi][ni][0] + bv0, acc[mi][ni][1] + bv1);
            float2 v23 = make_float2(acc[mi][ni][2] + bv0, acc[mi][ni][3] + bv1);
            *(float2*)(&C[(size_t)m * NDIM + n])       = v01;
            *(float2*)(&C[(size_t)(m + 8) * NDIM + n]) = v23;
        }
    }
}

// ---------------------------------------------------------------------------
// Launch: fused QKV+attention, then proj GEMM straight into d_out.
// Graph-capturable: kernel launches + attribute set only.
// ---------------------------------------------------------------------------
extern "C" void kernel_launch(void* const* d_in, const int* in_sizes, int n_in,
                              void* d_out, int out_size) {
    const float* x  = (const float*)d_in[0];
    const float* Wq = (const float*)d_in[1];
    const float* Wk = (const float*)d_in[2];
    const float* Wv = (const float*)d_in[3];
    const float* Wp = (const float*)d_in[4];
    const float* bp = (const float*)d_in[5];
    float* out = (float*)d_out;

    float* go;
    cudaGetSymbolAddress((void**)&go, g_Ot);

    static bool attr_set = false;
    if (!attr_set) {
        cudaFuncSetAttribute(fused_qkv_attn,
                             cudaFuncAttributeMaxDynamicSharedMemorySize,
                             FUSED_SMEM_BYTES);
        attr_set = true;
    }

    dim3 fgrid(NDIM / 64, MDIM / 128);   // (8, 1024)
    fused_qkv_attn<<<fgrid, 256, FUSED_SMEM_BYTES>>>(x, Wq, Wk, Wv, go);

    dim3 pgrid(NDIM / PBN, MDIM / PBM);  // (4, 1024)
    proj_gemm_tf32<<<pgrid, 256>>>(go, Wp, out, bp);
}

// round 3
// speedup vs baseline: 1.2300x; 1.2300x over previous
#include <cuda_runtime.h>
#include <cstdint>
#include <cstddef>

// Problem dims (fixed): B=4096, T=32, H=16, HS=32, E=512
//   M = B*T = 131072, N = H*HS = 512, K = E = 512
#define MDIM 131072
#define NDIM 512
#define KDIM 512

// Scratch: pre-rounded (tf32) inputs + attention output (proj-ready layout,
// already tf32-rounded at write time).
__device__ float g_Xr[(size_t)MDIM * KDIM];
__device__ float g_Ot[(size_t)MDIM * NDIM];
__device__ float g_Wq[NDIM * KDIM];
__device__ float g_Wk[NDIM * KDIM];
__device__ float g_Wv[NDIM * KDIM];
__device__ float g_Wp[NDIM * KDIM];

// ---------------------------------------------------------------------------
// helpers
// ---------------------------------------------------------------------------
__device__ __forceinline__ uint32_t tf32_rna(float x) {
    uint32_t y;
    asm("cvt.rna.tf32.f32 %0, %1;" : "=r"(y) : "f"(x));
    return y;
}

__device__ __forceinline__ void mma_tf32(float c[4], const uint32_t a[4], const uint32_t b[2]) {
    asm volatile(
        "mma.sync.aligned.m16n8k8.row.col.f32.tf32.tf32.f32 "
        "{%0,%1,%2,%3}, {%4,%5,%6,%7}, {%8,%9}, {%0,%1,%2,%3};\n"
        : "+f"(c[0]), "+f"(c[1]), "+f"(c[2]), "+f"(c[3])
        : "r"(a[0]), "r"(a[1]), "r"(a[2]), "r"(a[3]), "r"(b[0]), "r"(b[1]));
}

__device__ __forceinline__ void cp_async16(uint32_t smem_addr, const void* gptr) {
    asm volatile("cp.async.cg.shared.global [%0], [%1], 16;\n"
                 :: "r"(smem_addr), "l"(gptr));
}
__device__ __forceinline__ void cp_async_commit() {
    asm volatile("cp.async.commit_group;\n" ::: "memory");
}
template <int N>
__device__ __forceinline__ void cp_async_wait() {
    asm volatile("cp.async.wait_group %0;\n" :: "n"(N) : "memory");
}

// ---------------------------------------------------------------------------
// Pre-round pass: out[i] = tf32_rna(in[i]), float4-vectorized.
// ---------------------------------------------------------------------------
__global__ void __launch_bounds__(256) round_tf32_kernel(
    const float4* __restrict__ in, float4* __restrict__ out, int n4)
{
    int i = blockIdx.x * 256 + threadIdx.x;
    if (i < n4) {
        float4 v = in[i];
        v.x = __uint_as_float(tf32_rna(v.x));
        v.y = __uint_as_float(tf32_rna(v.y));
        v.z = __uint_as_float(tf32_rna(v.z));
        v.w = __uint_as_float(tf32_rna(v.w));
        out[i] = v;
    }
}

// ===========================================================================
// Fused QKV GEMM + attention (inputs pre-rounded to tf32).
// Grid: (8, 1024). Block: 256 threads = 8 warps (4 batch x 2 head).
// 3-stage cp.async pipeline, BK=16.
// smem union: GEMM pipeline 3*6400 floats (76.8 KB) / attention 101.4 KB.
// ===========================================================================
#define BK 16
#define SST 20           // 16 + 4 pad (floats); 80B rows, 16B-aligned
#define ATS 33
#define NSTAGE 3
#define FUSED_STAGE_FLOATS (128 * SST + 3 * 64 * SST)   // 6400
#define FUSED_SMEM_BYTES (8 * 3 * 32 * ATS * 4)          // 101376

extern "C" __global__ void __launch_bounds__(256, 1) fused_qkv_attn(
    const float* __restrict__ X,
    const float* __restrict__ Wq, const float* __restrict__ Wk,
    const float* __restrict__ Wv, float* __restrict__ Ot)
{
    extern __shared__ float smem[];

    const int tid  = threadIdx.x;
    const int lane = tid & 31;
    const int warp = tid >> 5;
    const int wm   = warp & 3;
    const int wn   = warp >> 2;
    const int g    = lane >> 2;
    const int t4   = lane & 3;

    const int m0 = blockIdx.y * 128;
    const int n0 = blockIdx.x * 64;

    // load mappings
    const int ldrow = tid >> 1;        // x rows 0..127
    const int ldcol = (tid & 1) * 8;   // 0 or 8
    const int wrow  = tid >> 2;        // w rows 0..63
    const int wcol  = (tid & 3) * 4;   // 0,4,8,12

    const float* Xg = X + (size_t)(m0 + ldrow) * KDIM + ldcol;
    const float* Wg[3];
    Wg[0] = Wq + (size_t)(n0 + wrow) * KDIM + wcol;
    Wg[1] = Wk + (size_t)(n0 + wrow) * KDIM + wcol;
    Wg[2] = Wv + (size_t)(n0 + wrow) * KDIM + wcol;

    const uint32_t smem_u = (uint32_t)__cvta_generic_to_shared(smem);
    const uint32_t xs_off = (ldrow * SST + ldcol) * 4;
    const uint32_t ws_off = (128 * SST + wrow * SST + wcol) * 4;

    float acc[3][2][4][4];
    #pragma unroll
    for (int m = 0; m < 3; m++)
        #pragma unroll
        for (int mi = 0; mi < 2; mi++)
            #pragma unroll
            for (int ni = 0; ni < 4; ni++)
                #pragma unroll
                for (int r = 0; r < 4; r++) acc[m][mi][ni][r] = 0.f;

    const int NT = KDIM / BK;   // 32

    // prologue: stages 0..NSTAGE-2
    #pragma unroll
    for (int s = 0; s < NSTAGE - 1; s++) {
        const uint32_t base = smem_u + s * (FUSED_STAGE_FLOATS * 4);
        const int kt = s * BK;
        cp_async16(base + xs_off,      Xg + kt);
        cp_async16(base + xs_off + 16, Xg + kt + 4);
        #pragma unroll
        for (int m = 0; m < 3; m++)
            cp_async16(base + ws_off + m * (64 * SST * 4), Wg[m] + kt);
        cp_async_commit();
    }

    for (int i = 0; i < NT; i++) {
        cp_async_wait<NSTAGE - 2>();
        __syncthreads();

        // issue loads for tile i+NSTAGE-1 into slot (i-1)%NSTAGE (now free)
        const int lt = i + NSTAGE - 1;
        if (lt < NT) {
            const int slot = lt % NSTAGE;
            const uint32_t base = smem_u + slot * (FUSED_STAGE_FLOATS * 4);
            const int kt = lt * BK;
            cp_async16(base + xs_off,      Xg + kt);
            cp_async16(base + xs_off + 16, Xg + kt + 4);
            #pragma unroll
            for (int m = 0; m < 3; m++)
                cp_async16(base + ws_off + m * (64 * SST * 4), Wg[m] + kt);
        }
        cp_async_commit();

        // compute tile i from slot i%NSTAGE
        const float* xs = smem + (i % NSTAGE) * FUSED_STAGE_FLOATS;
        const float* ws = xs + 128 * SST;

        #pragma unroll
        for (int kk = 0; kk < BK; kk += 8) {
            uint32_t af[2][4];
            #pragma unroll
            for (int mi = 0; mi < 2; mi++) {
                const int r = (wm * 32 + mi * 16 + g) * SST + kk + t4;
                af[mi][0] = __float_as_uint(xs[r]);
                af[mi][1] = __float_as_uint(xs[r + 8 * SST]);
                af[mi][2] = __float_as_uint(xs[r + 4]);
                af[mi][3] = __float_as_uint(xs[r + 8 * SST + 4]);
            }
            #pragma unroll
            for (int m = 0; m < 3; m++) {
                #pragma unroll
                for (int ni = 0; ni < 4; ni++) {
                    uint32_t bf[2];
                    const int r = m * 64 * SST + (wn * 32 + ni * 8 + g) * SST + kk + t4;
                    bf[0] = __float_as_uint(ws[r]);
                    bf[1] = __float_as_uint(ws[r + 4]);
                    #pragma unroll
                    for (int mi = 0; mi < 2; mi++)
                        mma_tf32(acc[m][mi][ni], af[mi], bf);
                }
            }
        }
    }

    // --- phase switch ---
    cp_async_wait<0>();
    __syncthreads();

    float* aw = smem + warp * (3 * 32 * ATS);
    float* Qb = aw;
    float* Kb = aw + 32 * ATS;
    float* Vb = aw + 2 * 32 * ATS;
    float* bufs[3] = {Qb, Kb, Vb};

    #pragma unroll
    for (int m = 0; m < 3; m++) {
        #pragma unroll
        for (int mi = 0; mi < 2; mi++) {
            #pragma unroll
            for (int ni = 0; ni < 4; ni++) {
                const int r = mi * 16 + g;
                const int c = ni * 8 + t4 * 2;
                bufs[m][r * ATS + c]           = acc[m][mi][ni][0];
                bufs[m][r * ATS + c + 1]       = acc[m][mi][ni][1];
                bufs[m][(r + 8) * ATS + c]     = acc[m][mi][ni][2];
                bufs[m][(r + 8) * ATS + c + 1] = acc[m][mi][ni][3];
            }
        }
    }
    __syncwarp();

    // warp-local causal attention: lane = query index t
    float q[32];
    #pragma unroll
    for (int d = 0; d < 32; d++) q[d] = Qb[lane * ATS + d];

    const float scale = 0.17677669529663689f;  // 32^-0.5
    float s[32];
    #pragma unroll
    for (int j = 0; j < 32; j++) {
        float a = 0.f;
        #pragma unroll
        for (int d = 0; d < 32; d++) a = fmaf(q[d], Kb[j * ATS + d], a);
        s[j] = (j <= lane) ? a * scale : -1e30f;
    }

    float mx = -1e30f;
    #pragma unroll
    for (int j = 0; j < 32; j++) mx = fmaxf(mx, s[j]);
    float sum = 0.f;
    #pragma unroll
    for (int j = 0; j < 32; j++) { float e = __expf(s[j] - mx); s[j] = e; sum += e; }
    const float inv = 1.0f / sum;

    float o[32];
    #pragma unroll
    for (int d = 0; d < 32; d++) o[d] = 0.f;
    #pragma unroll
    for (int j = 0; j < 32; j++) {
        const float p = s[j];
        #pragma unroll
        for (int d = 0; d < 32; d++) o[d] = fmaf(p, Vb[j * ATS + d], o[d]);
    }

    // write Ot[(b*32+d)*512 + h*32 + t], pre-rounded to tf32 for the proj GEMM
    const int b = blockIdx.y * 4 + wm;
    const int h = blockIdx.x * 2 + wn;
    #pragma unroll
    for (int d = 0; d < 32; d++)
        Ot[(size_t)(b * 32 + d) * 512 + h * 32 + lane] =
            __uint_as_float(tf32_rna(o[d] * inv));
}

// ===========================================================================
// Projection NT GEMM (inputs pre-rounded): out = Ot @ Wp^T + bp
// BM=BN=128, BK=16, 256 threads, warp tile 32x64, 3-stage cp.async.
// ===========================================================================
#define PROJ_STAGE_FLOATS (2 * 128 * SST)   // As + Bs per stage = 5120
#define PROJ_SMEM_BYTES (NSTAGE * PROJ_STAGE_FLOATS * 4)  // 61440

__global__ void __launch_bounds__(256, 2) proj_gemm_tf32(
    const float* __restrict__ A, const float* __restrict__ Bw,
    float* __restrict__ C, const float* __restrict__ bias)
{
    extern __shared__ float smem[];

    const int tid  = threadIdx.x;
    const int lane = tid & 31;
    const int warp = tid >> 5;
    const int wm   = warp & 3;
    const int wn   = warp >> 2;
    const int g    = lane >> 2;
    const int t4   = lane & 3;

    const int m0 = blockIdx.y * 128;
    const int n0 = blockIdx.x * 128;

    const int ldrow = tid >> 1;
    const int ldcol = (tid & 1) * 8;

    const float* Ag = A  + (size_t)(m0 + ldrow) * KDIM + ldcol;
    const float* Bg = Bw + (size_t)(n0 + ldrow) * KDIM + ldcol;

    const uint32_t smem_u = (uint32_t)__cvta_generic_to_shared(smem);
    const uint32_t as_off = (ldrow * SST + ldcol) * 4;
    const uint32_t bs_off = (128 * SST + ldrow * SST + ldcol) * 4;

    float acc[2][8][4];
    #pragma unroll
    for (int mi = 0; mi < 2; mi++)
        #pragma unroll
        for (int ni = 0; ni < 8; ni++)
            #pragma unroll
            for (int r = 0; r < 4; r++) acc[mi][ni][r] = 0.f;

    const int NT = KDIM / BK;

    #pragma unroll
    for (int s = 0; s < NSTAGE - 1; s++) {
        const uint32_t base = smem_u + s * (PROJ_STAGE_FLOATS * 4);
        const int kt = s * BK;
        cp_async16(base + as_off,      Ag + kt);
        cp_async16(base + as_off + 16, Ag + kt + 4);
        cp_async16(base + bs_off,      Bg + kt);
        cp_async16(base + bs_off + 16, Bg + kt + 4);
        cp_async_commit();
    }

    for (int i = 0; i < NT; i++) {
        cp_async_wait<NSTAGE - 2>();
        __syncthreads();

        const int lt = i + NSTAGE - 1;
        if (lt < NT) {
            const int slot = lt % NSTAGE;
            const uint32_t base = smem_u + slot * (PROJ_STAGE_FLOATS * 4);
            const int kt = lt * BK;
            cp_async16(base + as_off,      Ag + kt);
            cp_async16(base + as_off + 16, Ag + kt + 4);
            cp_async16(base + bs_off,      Bg + kt);
            cp_async16(base + bs_off + 16, Bg + kt + 4);
        }
        cp_async_commit();

        const float* As = smem + (i % NSTAGE) * PROJ_STAGE_FLOATS;
        const float* Bs = As + 128 * SST;

        #pragma unroll
        for (int kk = 0; kk < BK; kk += 8) {
            uint32_t af[2][4];
            #pragma unroll
            for (int mi = 0; mi < 2; mi++) {
                const int r = (wm * 32 + mi * 16 + g) * SST + kk + t4;
                af[mi][0] = __float_as_uint(As[r]);
                af[mi][1] = __float_as_uint(As[r + 8 * SST]);
                af[mi][2] = __float_as_uint(As[r + 4]);
                af[mi][3] = __float_as_uint(As[r + 8 * SST + 4]);
            }
            uint32_t bf[8][2];
            #pragma unroll
            for (int ni = 0; ni < 8; ni++) {
                const int r = (wn * 64 + ni * 8 + g) * SST + kk + t4;
                bf[ni][0] = __float_as_uint(Bs[r]);
                bf[ni][1] = __float_as_uint(Bs[r + 4]);
            }
            #pragma unroll
            for (int mi = 0; mi < 2; mi++)
                #pragma unroll
                for (int ni = 0; ni < 8; ni++)
                    mma_tf32(acc[mi][ni], af[mi], bf[ni]);
        }
    }

    #pragma unroll
    for (int mi = 0; mi < 2; mi++) {
        #pragma unroll
        for (int ni = 0; ni < 8; ni++) {
            const int m = m0 + wm * 32 + mi * 16 + g;
            const int n = n0 + wn * 64 + ni * 8 + t4 * 2;
            const float bv0 = bias[n];
            const float bv1 = bias[n + 1];
            float2 v01 = make_float2(acc[mi][ni][0] + bv0, acc[mi][ni][1] + bv1);
            float2 v23 = make_float2(acc[mi][ni][2] + bv0, acc[mi][ni][3] + bv1);
            *(float2*)(&C[(size_t)m * NDIM + n])       = v01;
            *(float2*)(&C[(size_t)(m + 8) * NDIM + n]) = v23;
        }
    }
}

// ---------------------------------------------------------------------------
// Launch
// ---------------------------------------------------------------------------
extern "C" void kernel_launch(void* const* d_in, const int* in_sizes, int n_in,
                              void* d_out, int out_size) {
    const float* x  = (const float*)d_in[0];
    const float* Wq = (const float*)d_in[1];
    const float* Wk = (const float*)d_in[2];
    const float* Wv = (const float*)d_in[3];
    const float* Wp = (const float*)d_in[4];
    const float* bp = (const float*)d_in[5];
    float* out = (float*)d_out;

    float *gx, *go, *gwq, *gwk, *gwv, *gwp;
    cudaGetSymbolAddress((void**)&gx,  g_Xr);
    cudaGetSymbolAddress((void**)&go,  g_Ot);
    cudaGetSymbolAddress((void**)&gwq, g_Wq);
    cudaGetSymbolAddress((void**)&gwk, g_Wk);
    cudaGetSymbolAddress((void**)&gwv, g_Wv);
    cudaGetSymbolAddress((void**)&gwp, g_Wp);

    static bool attr_set = false;
    if (!attr_set) {
        cudaFuncSetAttribute(fused_qkv_attn,
                             cudaFuncAttributeMaxDynamicSharedMemorySize,
                             FUSED_SMEM_BYTES);
        cudaFuncSetAttribute(proj_gemm_tf32,
                             cudaFuncAttributeMaxDynamicSharedMemorySize,
                             PROJ_SMEM_BYTES);
        attr_set = true;
    }

    // pre-round inputs to tf32 (RNA) once
    const int xn4 = (MDIM * KDIM) / 4;       // 16777216
    const int wn4 = (NDIM * KDIM) / 4;       // 65536
    round_tf32_kernel<<<xn4 / 256, 256>>>((const float4*)x,  (float4*)gx,  xn4);
    round_tf32_kernel<<<wn4 / 256, 256>>>((const float4*)Wq, (float4*)gwq, wn4);
    round_tf32_kernel<<<wn4 / 256, 256>>>((const float4*)Wk, (float4*)gwk, wn4);
    round_tf32_kernel<<<wn4 / 256, 256>>>((const float4*)Wv, (float4*)gwv, wn4);
    round_tf32_kernel<<<wn4 / 256, 256>>>((const float4*)Wp, (float4*)gwp, wn4);

    dim3 fgrid(NDIM / 64, MDIM / 128);   // (8, 1024)
    fused_qkv_attn<<<fgrid, 256, FUSED_SMEM_BYTES>>>(gx, gwq, gwk, gwv, go);

    dim3 pgrid(NDIM / 128, MDIM / 128);  // (4, 1024)
    proj_gemm_tf32<<<pgrid, 256, PROJ_SMEM_BYTES>>>(go, gwp, out, bp);
}

// round 4
// speedup vs baseline: 1.3346x; 1.0850x over previous
#include <cuda_runtime.h>
#include <cstdint>
#include <cstddef>

// Problem dims (fixed): B=4096, T=32, H=16, HS=32, E=512
//   M = B*T = 131072, N = H*HS = 512, K = E = 512
#define MDIM 131072
#define NDIM 512
#define KDIM 512

// Scratch: pre-rounded (tf32) inputs + attention output (proj-ready layout,
// already tf32-rounded at write time).
__device__ float g_Xr[(size_t)MDIM * KDIM];
__device__ float g_Ot[(size_t)MDIM * NDIM];
__device__ float g_Wq[NDIM * KDIM];
__device__ float g_Wk[NDIM * KDIM];
__device__ float g_Wv[NDIM * KDIM];
__device__ float g_Wp[NDIM * KDIM];

// ---------------------------------------------------------------------------
// helpers
// ---------------------------------------------------------------------------
__device__ __forceinline__ uint32_t tf32_rna(float x) {
    uint32_t y;
    asm("cvt.rna.tf32.f32 %0, %1;" : "=r"(y) : "f"(x));
    return y;
}
__device__ __forceinline__ float tf32f(float x) {
    return __uint_as_float(tf32_rna(x));
}

__device__ __forceinline__ void mma_tf32(float c[4], const uint32_t a[4], const uint32_t b[2]) {
    asm volatile(
        "mma.sync.aligned.m16n8k8.row.col.f32.tf32.tf32.f32 "
        "{%0,%1,%2,%3}, {%4,%5,%6,%7}, {%8,%9}, {%0,%1,%2,%3};\n"
        : "+f"(c[0]), "+f"(c[1]), "+f"(c[2]), "+f"(c[3])
        : "r"(a[0]), "r"(a[1]), "r"(a[2]), "r"(a[3]), "r"(b[0]), "r"(b[1]));
}

__device__ __forceinline__ void cp_async16(uint32_t smem_addr, const void* gptr) {
    asm volatile("cp.async.cg.shared.global [%0], [%1], 16;\n"
                 :: "r"(smem_addr), "l"(gptr));
}
__device__ __forceinline__ void cp_async_commit() {
    asm volatile("cp.async.commit_group;\n" ::: "memory");
}
template <int N>
__device__ __forceinline__ void cp_async_wait() {
    asm volatile("cp.async.wait_group %0;\n" :: "n"(N) : "memory");
}

// ---------------------------------------------------------------------------
// Pre-round pass: out[i] = tf32_rna(in[i]), float4-vectorized.
// ---------------------------------------------------------------------------
__global__ void __launch_bounds__(256) round_tf32_kernel(
    const float4* __restrict__ in, float4* __restrict__ out, int n4)
{
    int i = blockIdx.x * 256 + threadIdx.x;
    if (i < n4) {
        float4 v = in[i];
        v.x = tf32f(v.x); v.y = tf32f(v.y);
        v.z = tf32f(v.z); v.w = tf32f(v.w);
        out[i] = v;
    }
}

// ===========================================================================
// Fused QKV GEMM + tensor-core attention (inputs pre-rounded to tf32).
// Grid: (8, 1024). Block: 256 threads = 8 warps (4 batch x 2 head).
// GEMM: 3-stage cp.async pipeline, BK=16, warp tile 32x32 per matrix x3.
// Attention: S = Q K^T via m16n8k8 MMAs, register softmax (shfl over t4
// quad), P via smem (reuse Qb), PV via MMAs, O transposed via smem (reuse Kb).
// ===========================================================================
#define BK 16
#define SST 20           // GEMM smem row stride (16 + 4 pad)
#define ATS2 36          // attention tile stride (32 + 4 pad): frag-load conflict-free
#define NSTAGE 3
#define FUSED_STAGE_FLOATS (128 * SST + 3 * 64 * SST)   // 6400
#define FUSED_SMEM_BYTES (8 * 3 * 32 * ATS2 * 4)        // 110592

extern "C" __global__ void __launch_bounds__(256, 1) fused_qkv_attn(
    const float* __restrict__ X,
    const float* __restrict__ Wq, const float* __restrict__ Wk,
    const float* __restrict__ Wv, float* __restrict__ Ot)
{
    extern __shared__ float smem[];

    const int tid  = threadIdx.x;
    const int lane = tid & 31;
    const int warp = tid >> 5;
    const int wm   = warp & 3;
    const int wn   = warp >> 2;
    const int g    = lane >> 2;
    const int t4   = lane & 3;

    const int m0 = blockIdx.y * 128;
    const int n0 = blockIdx.x * 64;

    const int ldrow = tid >> 1;        // x rows 0..127
    const int ldcol = (tid & 1) * 8;   // 0 or 8
    const int wrow  = tid >> 2;        // w rows 0..63
    const int wcol  = (tid & 3) * 4;   // 0,4,8,12

    const float* Xg = X + (size_t)(m0 + ldrow) * KDIM + ldcol;
    const float* Wg[3];
    Wg[0] = Wq + (size_t)(n0 + wrow) * KDIM + wcol;
    Wg[1] = Wk + (size_t)(n0 + wrow) * KDIM + wcol;
    Wg[2] = Wv + (size_t)(n0 + wrow) * KDIM + wcol;

    const uint32_t smem_u = (uint32_t)__cvta_generic_to_shared(smem);
    const uint32_t xs_off = (ldrow * SST + ldcol) * 4;
    const uint32_t ws_off = (128 * SST + wrow * SST + wcol) * 4;

    float acc[3][2][4][4];
    #pragma unroll
    for (int m = 0; m < 3; m++)
        #pragma unroll
        for (int mi = 0; mi < 2; mi++)
            #pragma unroll
            for (int ni = 0; ni < 4; ni++)
                #pragma unroll
                for (int r = 0; r < 4; r++) acc[m][mi][ni][r] = 0.f;

    const int NT = KDIM / BK;   // 32

    #pragma unroll
    for (int s = 0; s < NSTAGE - 1; s++) {
        const uint32_t base = smem_u + s * (FUSED_STAGE_FLOATS * 4);
        const int kt = s * BK;
        cp_async16(base + xs_off,      Xg + kt);
        cp_async16(base + xs_off + 16, Xg + kt + 4);
        #pragma unroll
        for (int m = 0; m < 3; m++)
            cp_async16(base + ws_off + m * (64 * SST * 4), Wg[m] + kt);
        cp_async_commit();
    }

    for (int i = 0; i < NT; i++) {
        cp_async_wait<NSTAGE - 2>();
        __syncthreads();

        const int lt = i + NSTAGE - 1;
        if (lt < NT) {
            const int slot = lt % NSTAGE;
            const uint32_t base = smem_u + slot * (FUSED_STAGE_FLOATS * 4);
            const int kt = lt * BK;
            cp_async16(base + xs_off,      Xg + kt);
            cp_async16(base + xs_off + 16, Xg + kt + 4);
            #pragma unroll
            for (int m = 0; m < 3; m++)
                cp_async16(base + ws_off + m * (64 * SST * 4), Wg[m] + kt);
        }
        cp_async_commit();

        const float* xs = smem + (i % NSTAGE) * FUSED_STAGE_FLOATS;
        const float* ws = xs + 128 * SST;

        #pragma unroll
        for (int kk = 0; kk < BK; kk += 8) {
            uint32_t af[2][4];
            #pragma unroll
            for (int mi = 0; mi < 2; mi++) {
                const int r = (wm * 32 + mi * 16 + g) * SST + kk + t4;
                af[mi][0] = __float_as_uint(xs[r]);
                af[mi][1] = __float_as_uint(xs[r + 8 * SST]);
                af[mi][2] = __float_as_uint(xs[r + 4]);
                af[mi][3] = __float_as_uint(xs[r + 8 * SST + 4]);
            }
            #pragma unroll
            for (int m = 0; m < 3; m++) {
                #pragma unroll
                for (int ni = 0; ni < 4; ni++) {
                    uint32_t bf[2];
                    const int r = m * 64 * SST + (wn * 32 + ni * 8 + g) * SST + kk + t4;
                    bf[0] = __float_as_uint(ws[r]);
                    bf[1] = __float_as_uint(ws[r + 4]);
                    #pragma unroll
                    for (int mi = 0; mi < 2; mi++)
                        mma_tf32(acc[m][mi][ni], af[mi], bf);
                }
            }
        }
    }

    // --- phase switch: drain pipeline, repurpose smem as attention tiles ---
    cp_async_wait<0>();
    __syncthreads();

    float* aw = smem + warp * (3 * 32 * ATS2);
    float* Qb = aw;                 // later reused as P
    float* Kb = aw + 32 * ATS2;     // later reused as O
    float* Vb = aw + 2 * 32 * ATS2;
    float* bufs[3] = {Qb, Kb, Vb};

    // dump Q,K,V (tf32-rounded) to per-warp tiles: [t/s][d], stride 36
    #pragma unroll
    for (int m = 0; m < 3; m++) {
        #pragma unroll
        for (int mi = 0; mi < 2; mi++) {
            #pragma unroll
            for (int ni = 0; ni < 4; ni++) {
                const int r = mi * 16 + g;
                const int c = ni * 8 + t4 * 2;
                *(float2*)&bufs[m][r * ATS2 + c] =
                    make_float2(tf32f(acc[m][mi][ni][0]), tf32f(acc[m][mi][ni][1]));
                *(float2*)&bufs[m][(r + 8) * ATS2 + c] =
                    make_float2(tf32f(acc[m][mi][ni][2]), tf32f(acc[m][mi][ni][3]));
            }
        }
    }
    __syncwarp();

    // ---- S = Q K^T (m16n8k8 over d=32) ----
    float sacc[2][4][4];
    #pragma unroll
    for (int mi = 0; mi < 2; mi++)
        #pragma unroll
        for (int ni = 0; ni < 4; ni++)
            #pragma unroll
            for (int r = 0; r < 4; r++) sacc[mi][ni][r] = 0.f;

    #pragma unroll
    for (int kk = 0; kk < 32; kk += 8) {
        uint32_t af[2][4];
        #pragma unroll
        for (int mi = 0; mi < 2; mi++) {
            const int r = (mi * 16 + g) * ATS2 + kk + t4;
            af[mi][0] = __float_as_uint(Qb[r]);
            af[mi][1] = __float_as_uint(Qb[r + 8 * ATS2]);
            af[mi][2] = __float_as_uint(Qb[r + 4]);
            af[mi][3] = __float_as_uint(Qb[r + 8 * ATS2 + 4]);
        }
        #pragma unroll
        for (int ni = 0; ni < 4; ni++) {
            uint32_t bf[2];
            const int r = (ni * 8 + g) * ATS2 + kk + t4;
            bf[0] = __float_as_uint(Kb[r]);
            bf[1] = __float_as_uint(Kb[r + 4]);
            #pragma unroll
            for (int mi = 0; mi < 2; mi++)
                mma_tf32(sacc[mi][ni], af[mi], bf);
        }
    }

    // ---- mask + scale + softmax (rows live across the 4-lane t4 group) ----
    const float scale = 0.17677669529663689f;  // 32^-0.5
    float rmax[2][2] = {{-1e30f, -1e30f}, {-1e30f, -1e30f}};
    #pragma unroll
    for (int mi = 0; mi < 2; mi++)
        #pragma unroll
        for (int ni = 0; ni < 4; ni++)
            #pragma unroll
            for (int j = 0; j < 4; j++) {
                const int row = mi * 16 + g + (j >> 1) * 8;
                const int col = ni * 8 + t4 * 2 + (j & 1);
                float v = (col <= row) ? sacc[mi][ni][j] * scale : -1e30f;
                sacc[mi][ni][j] = v;
                rmax[mi][j >> 1] = fmaxf(rmax[mi][j >> 1], v);
            }
    #pragma unroll
    for (int mi = 0; mi < 2; mi++)
        #pragma unroll
        for (int h8 = 0; h8 < 2; h8++) {
            float m = rmax[mi][h8];
            m = fmaxf(m, __shfl_xor_sync(0xffffffffu, m, 1));
            m = fmaxf(m, __shfl_xor_sync(0xffffffffu, m, 2));
            rmax[mi][h8] = m;
        }
    float rsum[2][2] = {{0.f, 0.f}, {0.f, 0.f}};
    #pragma unroll
    for (int mi = 0; mi < 2; mi++)
        #pragma unroll
        for (int ni = 0; ni < 4; ni++)
            #pragma unroll
            for (int j = 0; j < 4; j++) {
                float e = __expf(sacc[mi][ni][j] - rmax[mi][j >> 1]);
                sacc[mi][ni][j] = e;
                rsum[mi][j >> 1] += e;
            }
    float inv[2][2];
    #pragma unroll
    for (int mi = 0; mi < 2; mi++)
        #pragma unroll
        for (int h8 = 0; h8 < 2; h8++) {
            float s = rsum[mi][h8];
            s += __shfl_xor_sync(0xffffffffu, s, 1);
            s += __shfl_xor_sync(0xffffffffu, s, 2);
            inv[mi][h8] = 1.0f / s;
        }

    // ---- store unnormalized P (tf32) into Qb (Q dead) ----
    __syncwarp();
    #pragma unroll
    for (int mi = 0; mi < 2; mi++)
        #pragma unroll
        for (int ni = 0; ni < 4; ni++) {
            const int r = mi * 16 + g;
            const int c = ni * 8 + t4 * 2;
            *(float2*)&Qb[r * ATS2 + c] =
                make_float2(tf32f(sacc[mi][ni][0]), tf32f(sacc[mi][ni][1]));
            *(float2*)&Qb[(r + 8) * ATS2 + c] =
                make_float2(tf32f(sacc[mi][ni][2]), tf32f(sacc[mi][ni][3]));
        }
    __syncwarp();

    // ---- O = P V (m16n8k8 over s=32); B-frag reads V[s][d] transposed ----
    float oacc[2][4][4];
    #pragma unroll
    for (int mi = 0; mi < 2; mi++)
        #pragma unroll
        for (int ni = 0; ni < 4; ni++)
            #pragma unroll
            for (int r = 0; r < 4; r++) oacc[mi][ni][r] = 0.f;

    #pragma unroll
    for (int kk = 0; kk < 32; kk += 8) {
        uint32_t af[2][4];
        #pragma unroll
        for (int mi = 0; mi < 2; mi++) {
            const int r = (mi * 16 + g) * ATS2 + kk + t4;
            af[mi][0] = __float_as_uint(Qb[r]);
            af[mi][1] = __float_as_uint(Qb[r + 8 * ATS2]);
            af[mi][2] = __float_as_uint(Qb[r + 4]);
            af[mi][3] = __float_as_uint(Qb[r + 8 * ATS2 + 4]);
        }
        #pragma unroll
        for (int ni = 0; ni < 4; ni++) {
            uint32_t bf[2];
            bf[0] = __float_as_uint(Vb[(kk + t4) * ATS2 + ni * 8 + g]);
            bf[1] = __float_as_uint(Vb[(kk + 4 + t4) * ATS2 + ni * 8 + g]);
            #pragma unroll
            for (int mi = 0; mi < 2; mi++)
                mma_tf32(oacc[mi][ni], af[mi], bf);
        }
    }

    // ---- normalize, round to tf32, dump O to Kb (K dead), store coalesced ----
    __syncwarp();
    #pragma unroll
    for (int mi = 0; mi < 2; mi++)
        #pragma unroll
        for (int ni = 0; ni < 4; ni++) {
            const int r = mi * 16 + g;
            const int c = ni * 8 + t4 * 2;
            *(float2*)&Kb[r * ATS2 + c] =
                make_float2(tf32f(oacc[mi][ni][0] * inv[mi][0]),
                            tf32f(oacc[mi][ni][1] * inv[mi][0]));
            *(float2*)&Kb[(r + 8) * ATS2 + c] =
                make_float2(tf32f(oacc[mi][ni][2] * inv[mi][1]),
                            tf32f(oacc[mi][ni][3] * inv[mi][1]));
        }
    __syncwarp();

    // Ot[(b*32+d)*512 + h*32 + t], t = lane -> coalesced along lanes
    const int b = blockIdx.y * 4 + wm;
    const int h = blockIdx.x * 2 + wn;
    #pragma unroll
    for (int d4 = 0; d4 < 8; d4++) {
        float4 v = *(const float4*)&Kb[lane * ATS2 + d4 * 4];
        Ot[(size_t)(b * 32 + d4 * 4 + 0) * 512 + h * 32 + lane] = v.x;
        Ot[(size_t)(b * 32 + d4 * 4 + 1) * 512 + h * 32 + lane] = v.y;
        Ot[(size_t)(b * 32 + d4 * 4 + 2) * 512 + h * 32 + lane] = v.z;
        Ot[(size_t)(b * 32 + d4 * 4 + 3) * 512 + h * 32 + lane] = v.w;
    }
}

// ===========================================================================
// Projection NT GEMM (inputs pre-rounded): out = Ot @ Wp^T + bp
// BM=BN=128, BK=16, 256 threads, warp tile 32x64, 3-stage cp.async.
// ===========================================================================
#define PROJ_STAGE_FLOATS (2 * 128 * SST)   // 5120
#define PROJ_SMEM_BYTES (NSTAGE * PROJ_STAGE_FLOATS * 4)  // 61440

__global__ void __launch_bounds__(256, 2) proj_gemm_tf32(
    const float* __restrict__ A, const float* __restrict__ Bw,
    float* __restrict__ C, const float* __restrict__ bias)
{
    extern __shared__ float smem[];

    const int tid  = threadIdx.x;
    const int lane = tid & 31;
    const int warp = tid >> 5;
    const int wm   = warp & 3;
    const int wn   = warp >> 2;
    const int g    = lane >> 2;
    const int t4   = lane & 3;

    const int m0 = blockIdx.y * 128;
    const int n0 = blockIdx.x * 128;

    const int ldrow = tid >> 1;
    const int ldcol = (tid & 1) * 8;

    const float* Ag = A  + (size_t)(m0 + ldrow) * KDIM + ldcol;
    const float* Bg = Bw + (size_t)(n0 + ldrow) * KDIM + ldcol;

    const uint32_t smem_u = (uint32_t)__cvta_generic_to_shared(smem);
    const uint32_t as_off = (ldrow * SST + ldcol) * 4;
    const uint32_t bs_off = (128 * SST + ldrow * SST + ldcol) * 4;

    float acc[2][8][4];
    #pragma unroll
    for (int mi = 0; mi < 2; mi++)
        #pragma unroll
        for (int ni = 0; ni < 8; ni++)
            #pragma unroll
            for (int r = 0; r < 4; r++) acc[mi][ni][r] = 0.f;

    const int NT = KDIM / BK;

    #pragma unroll
    for (int s = 0; s < NSTAGE - 1; s++) {
        const uint32_t base = smem_u + s * (PROJ_STAGE_FLOATS * 4);
        const int kt = s * BK;
        cp_async16(base + as_off,      Ag + kt);
        cp_async16(base + as_off + 16, Ag + kt + 4);
        cp_async16(base + bs_off,      Bg + kt);
        cp_async16(base + bs_off + 16, Bg + kt + 4);
        cp_async_commit();
    }

    for (int i = 0; i < NT; i++) {
        cp_async_wait<NSTAGE - 2>();
        __syncthreads();

        const int lt = i + NSTAGE - 1;
        if (lt < NT) {
            const int slot = lt % NSTAGE;
            const uint32_t base = smem_u + slot * (PROJ_STAGE_FLOATS * 4);
            const int kt = lt * BK;
            cp_async16(base + as_off,      Ag + kt);
            cp_async16(base + as_off + 16, Ag + kt + 4);
            cp_async16(base + bs_off,      Bg + kt);
            cp_async16(base + bs_off + 16, Bg + kt + 4);
        }
        cp_async_commit();

        const float* As = smem + (i % NSTAGE) * PROJ_STAGE_FLOATS;
        const float* Bs = As + 128 * SST;

        #pragma unroll
        for (int kk = 0; kk < BK; kk += 8) {
            uint32_t af[2][4];
            #pragma unroll
            for (int mi = 0; mi < 2; mi++) {
                const int r = (wm * 32 + mi * 16 + g) * SST + kk + t4;
                af[mi][0] = __float_as_uint(As[r]);
                af[mi][1] = __float_as_uint(As[r + 8 * SST]);
                af[mi][2] = __float_as_uint(As[r + 4]);
                af[mi][3] = __float_as_uint(As[r + 8 * SST + 4]);
            }
            uint32_t bf[8][2];
            #pragma unroll
            for (int ni = 0; ni < 8; ni++) {
                const int r = (wn * 64 + ni * 8 + g) * SST + kk + t4;
                bf[ni][0] = __float_as_uint(Bs[r]);
                bf[ni][1] = __float_as_uint(Bs[r + 4]);
            }
            #pragma unroll
            for (int mi = 0; mi < 2; mi++)
                #pragma unroll
                for (int ni = 0; ni < 8; ni++)
                    mma_tf32(acc[mi][ni], af[mi], bf[ni]);
        }
    }

    #pragma unroll
    for (int mi = 0; mi < 2; mi++) {
        #pragma unroll
        for (int ni = 0; ni < 8; ni++) {
            const int m = m0 + wm * 32 + mi * 16 + g;
            const int n = n0 + wn * 64 + ni * 8 + t4 * 2;
            const float bv0 = bias[n];
            const float bv1 = bias[n + 1];
            float2 v01 = make_float2(acc[mi][ni][0] + bv0, acc[mi][ni][1] + bv1);
            float2 v23 = make_float2(acc[mi][ni][2] + bv0, acc[mi][ni][3] + bv1);
            *(float2*)(&C[(size_t)m * NDIM + n])       = v01;
            *(float2*)(&C[(size_t)(m + 8) * NDIM + n]) = v23;
        }
    }
}

// ---------------------------------------------------------------------------
// Launch
// ---------------------------------------------------------------------------
extern "C" void kernel_launch(void* const* d_in, const int* in_sizes, int n_in,
                              void* d_out, int out_size) {
    const float* x  = (const float*)d_in[0];
    const float* Wq = (const float*)d_in[1];
    const float* Wk = (const float*)d_in[2];
    const float* Wv = (const float*)d_in[3];
    const float* Wp = (const float*)d_in[4];
    const float* bp = (const float*)d_in[5];
    float* out = (float*)d_out;

    float *gx, *go, *gwq, *gwk, *gwv, *gwp;
    cudaGetSymbolAddress((void**)&gx,  g_Xr);
    cudaGetSymbolAddress((void**)&go,  g_Ot);
    cudaGetSymbolAddress((void**)&gwq, g_Wq);
    cudaGetSymbolAddress((void**)&gwk, g_Wk);
    cudaGetSymbolAddress((void**)&gwv, g_Wv);
    cudaGetSymbolAddress((void**)&gwp, g_Wp);

    static bool attr_set = false;
    if (!attr_set) {
        cudaFuncSetAttribute(fused_qkv_attn,
                             cudaFuncAttributeMaxDynamicSharedMemorySize,
                             FUSED_SMEM_BYTES);
        cudaFuncSetAttribute(proj_gemm_tf32,
                             cudaFuncAttributeMaxDynamicSharedMemorySize,
                             PROJ_SMEM_BYTES);
        attr_set = true;
    }

    // pre-round inputs to tf32 (RNA) once
    const int xn4 = (MDIM * KDIM) / 4;
    const int wn4 = (NDIM * KDIM) / 4;
    round_tf32_kernel<<<xn4 / 256, 256>>>((const float4*)x,  (float4*)gx,  xn4);
    round_tf32_kernel<<<wn4 / 256, 256>>>((const float4*)Wq, (float4*)gwq, wn4);
    round_tf32_kernel<<<wn4 / 256, 256>>>((const float4*)Wk, (float4*)gwk, wn4);
    round_tf32_kernel<<<wn4 / 256, 256>>>((const float4*)Wv, (float4*)gwv, wn4);
    round_tf32_kernel<<<wn4 / 256, 256>>>((const float4*)Wp, (float4*)gwp, wn4);

    dim3 fgrid(NDIM / 64, MDIM / 128);   // (8, 1024)
    fused_qkv_attn<<<fgrid, 256, FUSED_SMEM_BYTES>>>(gx, gwq, gwk, gwv, go);

    dim3 pgrid(NDIM / 128, MDIM / 128);  // (4, 1024)
    proj_gemm_tf32<<<pgrid, 256, PROJ_SMEM_BYTES>>>(go, gwp, out, bp);
}

// round 7
// speedup vs baseline: 1.5690x; 1.1757x over previous
#include <cuda_runtime.h>
#include <cstdint>
#include <cstddef>

// Problem dims (fixed): B=4096, T=32, H=16, HS=32, E=512
//   M = B*T = 131072, N = H*HS = 512, K = E = 512
#define MDIM 131072
#define NDIM 512
#define KDIM 512

// Scratch: pre-rounded (tf32) inputs + attention output (proj-ready layout).
__device__ float g_Xr[(size_t)MDIM * KDIM];
__device__ float g_Ot[(size_t)MDIM * NDIM];
__device__ float g_Wq[NDIM * KDIM];
__device__ float g_Wk[NDIM * KDIM];
__device__ float g_Wv[NDIM * KDIM];
__device__ float g_Wp[NDIM * KDIM];

// ---------------------------------------------------------------------------
// helpers
// ---------------------------------------------------------------------------
__device__ __forceinline__ uint32_t tf32_rna(float x) {
    uint32_t y;
    asm("cvt.rna.tf32.f32 %0, %1;" : "=r"(y) : "f"(x));
    return y;
}
__device__ __forceinline__ float tf32f(float x) {
    return __uint_as_float(tf32_rna(x));
}

__device__ __forceinline__ void mma_tf32(float c[4], const uint32_t a[4], const uint32_t b[2]) {
    asm volatile(
        "mma.sync.aligned.m16n8k8.row.col.f32.tf32.tf32.f32 "
        "{%0,%1,%2,%3}, {%4,%5,%6,%7}, {%8,%9}, {%0,%1,%2,%3};\n"
        : "+f"(c[0]), "+f"(c[1]), "+f"(c[2]), "+f"(c[3])
        : "r"(a[0]), "r"(a[1]), "r"(a[2]), "r"(a[3]), "r"(b[0]), "r"(b[1]));
}

__device__ __forceinline__ void cp_async16(uint32_t smem_addr, const void* gptr) {
    asm volatile("cp.async.cg.shared.global [%0], [%1], 16;\n"
                 :: "r"(smem_addr), "l"(gptr));
}
__device__ __forceinline__ void cp_async_commit() {
    asm volatile("cp.async.commit_group;\n" ::: "memory");
}
template <int N>
__device__ __forceinline__ void cp_async_wait() {
    asm volatile("cp.async.wait_group %0;\n" :: "n"(N) : "memory");
}

// ---------------------------------------------------------------------------
// Pre-round pass: out[i] = tf32_rna(in[i]), float4-vectorized.
// ---------------------------------------------------------------------------
__global__ void __launch_bounds__(256) round_tf32_kernel(
    const float4* __restrict__ in, float4* __restrict__ out, int n4)
{
    int i = blockIdx.x * 256 + threadIdx.x;
    if (i < n4) {
        float4 v = in[i];
        v.x = tf32f(v.x); v.y = tf32f(v.y);
        v.z = tf32f(v.z); v.w = tf32f(v.w);
        out[i] = v;
    }
}

// ===========================================================================
// Fused QKV GEMM + tensor-core attention (legacy mma.sync tf32).
// Grid (8, 512). Block: 256 threads = 8 warps (4 wm x 2 wn).
// CTA tile: M=256 rows (8 batches), N=64 (2 heads) x 3 matrices.
// Warp tile: WM=64 (mi=0..3), WN=32 per matrix -> 96 MMAs / 80 LDS per
// k-tile (0.83 LDS/MMA vs 1.33 in the 32x32 version).
// Each warp owns 2 attention problems: (batch wm*2+p, head wn), p=0,1.
// After the GEMM all 6 tiles (2p x QKV) are dumped to smem (acc regs die),
// then attention runs per problem.
// smem: GEMM stages 3 x 35840B = 107520 aliased inside the 221184B
// attention region (8 warps x 6 tiles x 32x36 floats).
// ===========================================================================
#define BK 16
#define SST 20              // 16 + 4 pad
#define ATS2 36             // attention tile stride (32 + 4)
#define F_STAGE_FLOATS (256 * SST + 3 * 64 * SST)   // 8960
#define FUSED_SMEM_BYTES (8 * 6 * 32 * ATS2 * 4)    // 221184

extern "C" __global__ void __launch_bounds__(256, 1) fused_qkv_attn(
    const float* __restrict__ X,
    const float* __restrict__ Wq, const float* __restrict__ Wk,
    const float* __restrict__ Wv, float* __restrict__ Ot)
{
    extern __shared__ float smem[];

    const int tid  = threadIdx.x;
    const int lane = tid & 31;
    const int warp = tid >> 5;
    const int wm   = warp & 3;    // 64-row stripe (2 batches)
    const int wn   = warp >> 2;   // head within CTA
    const int g    = lane >> 2;
    const int t4   = lane & 3;

    const int m0 = blockIdx.y * 256;
    const int n0 = blockIdx.x * 64;

    const uint32_t smem_u = (uint32_t)__cvta_generic_to_shared(smem);

    const int lrow = tid >> 2;        // 0..63
    const int lc16 = (tid & 3) * 4;   // 0,4,8,12

    float acc[3][4][4][4];
    #pragma unroll
    for (int m = 0; m < 3; m++)
        #pragma unroll
        for (int mi = 0; mi < 4; mi++)
            #pragma unroll
            for (int ni = 0; ni < 4; ni++)
                #pragma unroll
                for (int r = 0; r < 4; r++) acc[m][mi][ni][r] = 0.f;

    const float* Wg0 = Wq + (size_t)(n0 + lrow) * KDIM + lc16;
    const float* Wg1 = Wk + (size_t)(n0 + lrow) * KDIM + lc16;
    const float* Wg2 = Wv + (size_t)(n0 + lrow) * KDIM + lc16;

    // ---- chunk loader: 4 A-chunks + 3 B-chunks (16B each) per thread ----
    auto load_chunk = [&](int c) {
        const uint32_t st = smem_u + (uint32_t)((c % 3) * F_STAGE_FLOATS) * 4u;
        const int kt = c * BK;
        #pragma unroll
        for (int j = 0; j < 4; j++) {
            const int row = lrow + 64 * j;
            cp_async16(st + (uint32_t)(row * SST + lc16) * 4u,
                       X + (size_t)(m0 + row) * KDIM + kt + lc16);
        }
        cp_async16(st + (uint32_t)(256 * SST + 0 * 64 * SST + lrow * SST + lc16) * 4u, Wg0 + kt);
        cp_async16(st + (uint32_t)(256 * SST + 1 * 64 * SST + lrow * SST + lc16) * 4u, Wg1 + kt);
        cp_async16(st + (uint32_t)(256 * SST + 2 * 64 * SST + lrow * SST + lc16) * 4u, Wg2 + kt);
    };

    const int NT = KDIM / BK;   // 32

    load_chunk(0); cp_async_commit();
    load_chunk(1); cp_async_commit();

    for (int i = 0; i < NT; i++) {
        cp_async_wait<1>();
        __syncthreads();

        const int lt = i + 2;
        if (lt < NT) load_chunk(lt);
        cp_async_commit();

        const float* xs = smem + (i % 3) * F_STAGE_FLOATS;
        const float* ws = xs + 256 * SST;

        #pragma unroll
        for (int kk = 0; kk < BK; kk += 8) {
            uint32_t af[4][4];
            #pragma unroll
            for (int mi = 0; mi < 4; mi++) {
                const int r = (wm * 64 + mi * 16 + g) * SST + kk + t4;
                af[mi][0] = __float_as_uint(xs[r]);
                af[mi][1] = __float_as_uint(xs[r + 8 * SST]);
                af[mi][2] = __float_as_uint(xs[r + 4]);
                af[mi][3] = __float_as_uint(xs[r + 8 * SST + 4]);
            }
            #pragma unroll
            for (int m = 0; m < 3; m++) {
                #pragma unroll
                for (int ni = 0; ni < 4; ni++) {
                    uint32_t bf[2];
                    const int r = m * 64 * SST + (wn * 32 + ni * 8 + g) * SST + kk + t4;
                    bf[0] = __float_as_uint(ws[r]);
                    bf[1] = __float_as_uint(ws[r + 4]);
                    #pragma unroll
                    for (int mi = 0; mi < 4; mi++)
                        mma_tf32(acc[m][mi][ni], af[mi], bf);
                }
            }
        }
    }

    // --- phase switch: all GEMM smem reads done; region becomes attn tiles ---
    cp_async_wait<0>();
    __syncthreads();

    // dump ALL 6 tiles (p=0,1 x Q,K,V) so acc registers die before attention
    float* aw = smem + warp * (6 * 32 * ATS2);
    #pragma unroll
    for (int p = 0; p < 2; p++) {
        #pragma unroll
        for (int m = 0; m < 3; m++) {
            float* buf = aw + (p * 3 + m) * (32 * ATS2);
            #pragma unroll
            for (int miL = 0; miL < 2; miL++) {
                const int mi = p * 2 + miL;
                #pragma unroll
                for (int ni = 0; ni < 4; ni++) {
                    const int r = miL * 16 + g;
                    const int c = ni * 8 + t4 * 2;
                    *(float2*)&buf[r * ATS2 + c] =
                        make_float2(tf32f(acc[m][mi][ni][0]), tf32f(acc[m][mi][ni][1]));
                    *(float2*)&buf[(r + 8) * ATS2 + c] =
                        make_float2(tf32f(acc[m][mi][ni][2]), tf32f(acc[m][mi][ni][3]));
                }
            }
        }
    }
    __syncwarp();

    const float scale = 0.17677669529663689f;  // 32^-0.5

    for (int p = 0; p < 2; p++) {
        float* Qb = aw + (p * 3 + 0) * (32 * ATS2);
        float* Kb = aw + (p * 3 + 1) * (32 * ATS2);
        float* Vb = aw + (p * 3 + 2) * (32 * ATS2);

        // ---- S = Q K^T (m16n8k8 over d=32) ----
        float sacc[2][4][4];
        #pragma unroll
        for (int mi = 0; mi < 2; mi++)
            #pragma unroll
            for (int ni = 0; ni < 4; ni++)
                #pragma unroll
                for (int r = 0; r < 4; r++) sacc[mi][ni][r] = 0.f;

        #pragma unroll
        for (int kk = 0; kk < 32; kk += 8) {
            uint32_t af[2][4];
            #pragma unroll
            for (int mi = 0; mi < 2; mi++) {
                const int r = (mi * 16 + g) * ATS2 + kk + t4;
                af[mi][0] = __float_as_uint(Qb[r]);
                af[mi][1] = __float_as_uint(Qb[r + 8 * ATS2]);
                af[mi][2] = __float_as_uint(Qb[r + 4]);
                af[mi][3] = __float_as_uint(Qb[r + 8 * ATS2 + 4]);
            }
            #pragma unroll
            for (int ni = 0; ni < 4; ni++) {
                uint32_t bf[2];
                const int r = (ni * 8 + g) * ATS2 + kk + t4;
                bf[0] = __float_as_uint(Kb[r]);
                bf[1] = __float_as_uint(Kb[r + 4]);
                #pragma unroll
                for (int mi = 0; mi < 2; mi++)
                    mma_tf32(sacc[mi][ni], af[mi], bf);
            }
        }

        // ---- mask + scale + softmax (rows across t4 quad) ----
        float rmax[2][2] = {{-1e30f, -1e30f}, {-1e30f, -1e30f}};
        #pragma unroll
        for (int mi = 0; mi < 2; mi++)
            #pragma unroll
            for (int ni = 0; ni < 4; ni++)
                #pragma unroll
                for (int j = 0; j < 4; j++) {
                    const int row = mi * 16 + g + (j >> 1) * 8;
                    const int col = ni * 8 + t4 * 2 + (j & 1);
                    float v = (col <= row) ? sacc[mi][ni][j] * scale : -1e30f;
                    sacc[mi][ni][j] = v;
                    rmax[mi][j >> 1] = fmaxf(rmax[mi][j >> 1], v);
                }
        #pragma unroll
        for (int mi = 0; mi < 2; mi++)
            #pragma unroll
            for (int h8 = 0; h8 < 2; h8++) {
                float m = rmax[mi][h8];
                m = fmaxf(m, __shfl_xor_sync(0xffffffffu, m, 1));
                m = fmaxf(m, __shfl_xor_sync(0xffffffffu, m, 2));
                rmax[mi][h8] = m;
            }
        float rsum[2][2] = {{0.f, 0.f}, {0.f, 0.f}};
        #pragma unroll
        for (int mi = 0; mi < 2; mi++)
            #pragma unroll
            for (int ni = 0; ni < 4; ni++)
                #pragma unroll
                for (int j = 0; j < 4; j++) {
                    float e = __expf(sacc[mi][ni][j] - rmax[mi][j >> 1]);
                    sacc[mi][ni][j] = e;
                    rsum[mi][j >> 1] += e;
                }
        float inv[2][2];
        #pragma unroll
        for (int mi = 0; mi < 2; mi++)
            #pragma unroll
            for (int h8 = 0; h8 < 2; h8++) {
                float s = rsum[mi][h8];
                s += __shfl_xor_sync(0xffffffffu, s, 1);
                s += __shfl_xor_sync(0xffffffffu, s, 2);
                inv[mi][h8] = 1.0f / s;
            }

        // ---- unnormalized P (tf32) into Qb (Q dead) ----
        __syncwarp();
        #pragma unroll
        for (int mi = 0; mi < 2; mi++)
            #pragma unroll
            for (int ni = 0; ni < 4; ni++) {
                const int r = mi * 16 + g;
                const int c = ni * 8 + t4 * 2;
                *(float2*)&Qb[r * ATS2 + c] =
                    make_float2(tf32f(sacc[mi][ni][0]), tf32f(sacc[mi][ni][1]));
                *(float2*)&Qb[(r + 8) * ATS2 + c] =
                    make_float2(tf32f(sacc[mi][ni][2]), tf32f(sacc[mi][ni][3]));
            }
        __syncwarp();

        // ---- O = P V (B-frag reads V[s][d] transposed) ----
        float oacc[2][4][4];
        #pragma unroll
        for (int mi = 0; mi < 2; mi++)
            #pragma unroll
            for (int ni = 0; ni < 4; ni++)
                #pragma unroll
                for (int r = 0; r < 4; r++) oacc[mi][ni][r] = 0.f;

        #pragma unroll
        for (int kk = 0; kk < 32; kk += 8) {
            uint32_t af[2][4];
            #pragma unroll
            for (int mi = 0; mi < 2; mi++) {
                const int r = (mi * 16 + g) * ATS2 + kk + t4;
                af[mi][0] = __float_as_uint(Qb[r]);
                af[mi][1] = __float_as_uint(Qb[r + 8 * ATS2]);
                af[mi][2] = __float_as_uint(Qb[r + 4]);
                af[mi][3] = __float_as_uint(Qb[r + 8 * ATS2 + 4]);
            }
            #pragma unroll
            for (int ni = 0; ni < 4; ni++) {
                uint32_t bf[2];
                bf[0] = __float_as_uint(Vb[(kk + t4) * ATS2 + ni * 8 + g]);
                bf[1] = __float_as_uint(Vb[(kk + 4 + t4) * ATS2 + ni * 8 + g]);
                #pragma unroll
                for (int mi = 0; mi < 2; mi++)
                    mma_tf32(oacc[mi][ni], af[mi], bf);
            }
        }

        // ---- normalize, dump O to Kb (K dead), coalesced store ----
        __syncwarp();
        #pragma unroll
        for (int mi = 0; mi < 2; mi++)
            #pragma unroll
            for (int ni = 0; ni < 4; ni++) {
                const int r = mi * 16 + g;
                const int c = ni * 8 + t4 * 2;
                *(float2*)&Kb[r * ATS2 + c] =
                    make_float2(tf32f(oacc[mi][ni][0] * inv[mi][0]),
                                tf32f(oacc[mi][ni][1] * inv[mi][0]));
                *(float2*)&Kb[(r + 8) * ATS2 + c] =
                    make_float2(tf32f(oacc[mi][ni][2] * inv[mi][1]),
                                tf32f(oacc[mi][ni][3] * inv[mi][1]));
            }
        __syncwarp();

        const int b = blockIdx.y * 8 + wm * 2 + p;
        const int h = blockIdx.x * 2 + wn;
        #pragma unroll
        for (int d4 = 0; d4 < 8; d4++) {
            float4 v = *(const float4*)&Kb[lane * ATS2 + d4 * 4];
            Ot[(size_t)(b * 32 + d4 * 4 + 0) * 512 + h * 32 + lane] = v.x;
            Ot[(size_t)(b * 32 + d4 * 4 + 1) * 512 + h * 32 + lane] = v.y;
            Ot[(size_t)(b * 32 + d4 * 4 + 2) * 512 + h * 32 + lane] = v.z;
            Ot[(size_t)(b * 32 + d4 * 4 + 3) * 512 + h * 32 + lane] = v.w;
        }
        __syncwarp();
    }
}

// ===========================================================================
// Projection NT GEMM (unchanged from R4): out = Ot @ Wp^T + bp
// BM=BN=128, BK=16, 256 threads, warp tile 32x64, 3-stage cp.async.
// ===========================================================================
#define NSTAGE 3
#define PROJ_STAGE_FLOATS (2 * 128 * SST)
#define PROJ_SMEM_BYTES (NSTAGE * PROJ_STAGE_FLOATS * 4)

__global__ void __launch_bounds__(256, 2) proj_gemm_tf32(
    const float* __restrict__ A, const float* __restrict__ Bw,
    float* __restrict__ C, const float* __restrict__ bias)
{
    extern __shared__ float smem[];

    const int tid  = threadIdx.x;
    const int lane = tid & 31;
    const int warp = tid >> 5;
    const int wm   = warp & 3;
    const int wn   = warp >> 2;
    const int g    = lane >> 2;
    const int t4   = lane & 3;

    const int m0 = blockIdx.y * 128;
    const int n0 = blockIdx.x * 128;

    const int ldrow = tid >> 1;
    const int ldcol = (tid & 1) * 8;

    const float* Ag = A  + (size_t)(m0 + ldrow) * KDIM + ldcol;
    const float* Bg = Bw + (size_t)(n0 + ldrow) * KDIM + ldcol;

    const uint32_t smem_u = (uint32_t)__cvta_generic_to_shared(smem);
    const uint32_t as_off = (ldrow * SST + ldcol) * 4;
    const uint32_t bs_off = (128 * SST + ldrow * SST + ldcol) * 4;

    float acc[2][8][4];
    #pragma unroll
    for (int mi = 0; mi < 2; mi++)
        #pragma unroll
        for (int ni = 0; ni < 8; ni++)
            #pragma unroll
            for (int r = 0; r < 4; r++) acc[mi][ni][r] = 0.f;

    const int NT = KDIM / BK;

    #pragma unroll
    for (int s = 0; s < NSTAGE - 1; s++) {
        const uint32_t base = smem_u + s * (PROJ_STAGE_FLOATS * 4);
        const int kt = s * BK;
        cp_async16(base + as_off,      Ag + kt);
        cp_async16(base + as_off + 16, Ag + kt + 4);
        cp_async16(base + bs_off,      Bg + kt);
        cp_async16(base + bs_off + 16, Bg + kt + 4);
        cp_async_commit();
    }

    for (int i = 0; i < NT; i++) {
        cp_async_wait<NSTAGE - 2>();
        __syncthreads();

        const int lt = i + NSTAGE - 1;
        if (lt < NT) {
            const int slot = lt % NSTAGE;
            const uint32_t base = smem_u + slot * (PROJ_STAGE_FLOATS * 4);
            const int kt = lt * BK;
            cp_async16(base + as_off,      Ag + kt);
            cp_async16(base + as_off + 16, Ag + kt + 4);
            cp_async16(base + bs_off,      Bg + kt);
            cp_async16(base + bs_off + 16, Bg + kt + 4);
        }
        cp_async_commit();

        const float* As = smem + (i % NSTAGE) * PROJ_STAGE_FLOATS;
        const float* Bs = As + 128 * SST;

        #pragma unroll
        for (int kk = 0; kk < BK; kk += 8) {
            uint32_t af[2][4];
            #pragma unroll
            for (int mi = 0; mi < 2; mi++) {
                const int r = (wm * 32 + mi * 16 + g) * SST + kk + t4;
                af[mi][0] = __float_as_uint(As[r]);
                af[mi][1] = __float_as_uint(As[r + 8 * SST]);
                af[mi][2] = __float_as_uint(As[r + 4]);
                af[mi][3] = __float_as_uint(As[r + 8 * SST + 4]);
            }
            uint32_t bf[8][2];
            #pragma unroll
            for (int ni = 0; ni < 8; ni++) {
                const int r = (wn * 64 + ni * 8 + g) * SST + kk + t4;
                bf[ni][0] = __float_as_uint(Bs[r]);
                bf[ni][1] = __float_as_uint(Bs[r + 4]);
            }
            #pragma unroll
            for (int mi = 0; mi < 2; mi++)
                #pragma unroll
                for (int ni = 0; ni < 8; ni++)
                    mma_tf32(acc[mi][ni], af[mi], bf[ni]);
        }
    }

    #pragma unroll
    for (int mi = 0; mi < 2; mi++) {
        #pragma unroll
        for (int ni = 0; ni < 8; ni++) {
            const int m = m0 + wm * 32 + mi * 16 + g;
            const int n = n0 + wn * 64 + ni * 8 + t4 * 2;
            const float bv0 = bias[n];
            const float bv1 = bias[n + 1];
            float2 v01 = make_float2(acc[mi][ni][0] + bv0, acc[mi][ni][1] + bv1);
            float2 v23 = make_float2(acc[mi][ni][2] + bv0, acc[mi][ni][3] + bv1);
            *(float2*)(&C[(size_t)m * NDIM + n])       = v01;
            *(float2*)(&C[(size_t)(m + 8) * NDIM + n]) = v23;
        }
    }
}

// ---------------------------------------------------------------------------
// Launch
// ---------------------------------------------------------------------------
extern "C" void kernel_launch(void* const* d_in, const int* in_sizes, int n_in,
                              void* d_out, int out_size) {
    const float* x  = (const float*)d_in[0];
    const float* Wq = (const float*)d_in[1];
    const float* Wk = (const float*)d_in[2];
    const float* Wv = (const float*)d_in[3];
    const float* Wp = (const float*)d_in[4];
    const float* bp = (const float*)d_in[5];
    float* out = (float*)d_out;

    float *gx, *go, *gwq, *gwk, *gwv, *gwp;
    cudaGetSymbolAddress((void**)&gx,  g_Xr);
    cudaGetSymbolAddress((void**)&go,  g_Ot);
    cudaGetSymbolAddress((void**)&gwq, g_Wq);
    cudaGetSymbolAddress((void**)&gwk, g_Wk);
    cudaGetSymbolAddress((void**)&gwv, g_Wv);
    cudaGetSymbolAddress((void**)&gwp, g_Wp);

    static bool attr_set = false;
    if (!attr_set) {
        cudaFuncSetAttribute(fused_qkv_attn,
                             cudaFuncAttributeMaxDynamicSharedMemorySize,
                             FUSED_SMEM_BYTES);
        cudaFuncSetAttribute(proj_gemm_tf32,
                             cudaFuncAttributeMaxDynamicSharedMemorySize,
                             PROJ_SMEM_BYTES);
        attr_set = true;
    }

    // pre-round inputs to tf32 (RNA) once
    const int xn4 = (MDIM * KDIM) / 4;
    const int wn4 = (NDIM * KDIM) / 4;
    round_tf32_kernel<<<xn4 / 256, 256>>>((const float4*)x,  (float4*)gx,  xn4);
    round_tf32_kernel<<<wn4 / 256, 256>>>((const float4*)Wq, (float4*)gwq, wn4);
    round_tf32_kernel<<<wn4 / 256, 256>>>((const float4*)Wk, (float4*)gwk, wn4);
    round_tf32_kernel<<<wn4 / 256, 256>>>((const float4*)Wv, (float4*)gwv, wn4);
    round_tf32_kernel<<<wn4 / 256, 256>>>((const float4*)Wp, (float4*)gwp, wn4);

    dim3 fgrid(NDIM / 64, MDIM / 256);   // (8, 512)
    fused_qkv_attn<<<fgrid, 256, FUSED_SMEM_BYTES>>>(gx, gwq, gwk, gwv, go);

    dim3 pgrid(NDIM / 128, MDIM / 128);  // (4, 1024)
    proj_gemm_tf32<<<pgrid, 256, PROJ_SMEM_BYTES>>>(go, gwp, out, bp);
}

// round 9
// speedup vs baseline: 1.6241x; 1.0351x over previous
#include <cuda_runtime.h>
#include <cstdint>
#include <cstddef>

// Problem dims (fixed): B=4096, T=32, H=16, HS=32, E=512
//   M = B*T = 131072, N = H*HS = 512, K = E = 512
#define MDIM 131072
#define NDIM 512
#define KDIM 512

// Scratch: pre-rounded (tf32) inputs + attention output (proj-ready layout).
__device__ float g_Xr[(size_t)MDIM * KDIM];
__device__ float g_Ot[(size_t)MDIM * NDIM];
__device__ float g_Wq[NDIM * KDIM];
__device__ float g_Wk[NDIM * KDIM];
__device__ float g_Wv[NDIM * KDIM];
__device__ float g_Wp[NDIM * KDIM];

// ---------------------------------------------------------------------------
// helpers
// ---------------------------------------------------------------------------
__device__ __forceinline__ uint32_t tf32_rna(float x) {
    uint32_t y;
    asm("cvt.rna.tf32.f32 %0, %1;" : "=r"(y) : "f"(x));
    return y;
}
__device__ __forceinline__ float tf32f(float x) {
    return __uint_as_float(tf32_rna(x));
}

__device__ __forceinline__ void mma_tf32(float c[4], const uint32_t a[4], const uint32_t b[2]) {
    asm volatile(
        "mma.sync.aligned.m16n8k8.row.col.f32.tf32.tf32.f32 "
        "{%0,%1,%2,%3}, {%4,%5,%6,%7}, {%8,%9}, {%0,%1,%2,%3};\n"
        : "+f"(c[0]), "+f"(c[1]), "+f"(c[2]), "+f"(c[3])
        : "r"(a[0]), "r"(a[1]), "r"(a[2]), "r"(a[3]), "r"(b[0]), "r"(b[1]));
}

__device__ __forceinline__ void cp_async16(uint32_t smem_addr, const void* gptr) {
    asm volatile("cp.async.cg.shared.global [%0], [%1], 16;\n"
                 :: "r"(smem_addr), "l"(gptr));
}
__device__ __forceinline__ void cp_async_commit() {
    asm volatile("cp.async.commit_group;\n" ::: "memory");
}
template <int N>
__device__ __forceinline__ void cp_async_wait() {
    asm volatile("cp.async.wait_group %0;\n" :: "n"(N) : "memory");
}

// ---------------------------------------------------------------------------
// Pre-round pass: out[i] = tf32_rna(in[i]), float4-vectorized.
// ---------------------------------------------------------------------------
__global__ void __launch_bounds__(256) round_tf32_kernel(
    const float4* __restrict__ in, float4* __restrict__ out, int n4)
{
    int i = blockIdx.x * 256 + threadIdx.x;
    if (i < n4) {
        float4 v = in[i];
        v.x = tf32f(v.x); v.y = tf32f(v.y);
        v.z = tf32f(v.z); v.w = tf32f(v.w);
        out[i] = v;
    }
}

// ===========================================================================
// Fused QKV GEMM + tensor-core attention (legacy mma.sync tf32).
// Grid (8, 512). Block: 256 threads = 8 warps (4 wm x 2 wn).
// CTA tile: M=256 rows (8 batches), N=64 (2 heads) x 3 matrices.
// Warp tile: WM=64, WN=32 per matrix. BK=32 (16 k-tiles, halved sync count).
// Each warp owns 2 attention problems: (batch wm*2+p, head wn), p=0,1.
// smem: GEMM stages 3 x 64512B = 193536B aliased inside the 221184B
// attention region (8 warps x 6 tiles x 32x36 floats).
// ===========================================================================
#define BK2 32
#define SSTF 36             // 32 + 4 pad (floats); frag banks 4g+t4, conflict-free
#define ATS2 36             // attention tile stride (32 + 4)
#define F_STAGE_FLOATS (256 * SSTF + 3 * 64 * SSTF)   // 16128
#define FUSED_SMEM_BYTES (8 * 6 * 32 * ATS2 * 4)      // 221184

extern "C" __global__ void __launch_bounds__(256, 1) fused_qkv_attn(
    const float* __restrict__ X,
    const float* __restrict__ Wq, const float* __restrict__ Wk,
    const float* __restrict__ Wv, float* __restrict__ Ot)
{
    extern __shared__ float smem[];

    const int tid  = threadIdx.x;
    const int lane = tid & 31;
    const int warp = tid >> 5;
    const int wm   = warp & 3;    // 64-row stripe (2 batches)
    const int wn   = warp >> 2;   // head within CTA
    const int g    = lane >> 2;
    const int t4   = lane & 3;

    const int m0 = blockIdx.y * 256;
    const int n0 = blockIdx.x * 64;

    const uint32_t smem_u = (uint32_t)__cvta_generic_to_shared(smem);

    float acc[3][4][4][4];
    #pragma unroll
    for (int m = 0; m < 3; m++)
        #pragma unroll
        for (int mi = 0; mi < 4; mi++)
            #pragma unroll
            for (int ni = 0; ni < 4; ni++)
                #pragma unroll
                for (int r = 0; r < 4; r++) acc[m][mi][ni][r] = 0.f;

    const float* Wg[3] = {Wq, Wk, Wv};

    // ---- chunk loader: 8 A + 6 B cp.async16 per thread (BK=32 -> 128B/row) ----
    auto load_chunk = [&](int c) {
        const uint32_t st = smem_u + (uint32_t)((c % 3) * F_STAGE_FLOATS) * 4u;
        const int kt = c * BK2;
        #pragma unroll
        for (int j = 0; j < 8; j++) {
            const int idx = tid + 256 * j;
            const int row = idx >> 3, c16 = idx & 7;   // row 0..255, 8x16B per row
            cp_async16(st + (uint32_t)(row * SSTF + c16 * 4) * 4u,
                       X + (size_t)(m0 + row) * KDIM + kt + c16 * 4);
        }
        #pragma unroll
        for (int j = 0; j < 6; j++) {
            const int idx = tid + 256 * j;
            const int m = idx >> 9, row = (idx >> 3) & 63, c16 = idx & 7;
            cp_async16(st + (uint32_t)(256 * SSTF + m * 64 * SSTF + row * SSTF + c16 * 4) * 4u,
                       Wg[m] + (size_t)(n0 + row) * KDIM + kt + c16 * 4);
        }
    };

    const int NT = KDIM / BK2;   // 16

    load_chunk(0); cp_async_commit();
    load_chunk(1); cp_async_commit();

    for (int i = 0; i < NT; i++) {
        cp_async_wait<1>();
        __syncthreads();

        const int lt = i + 2;
        if (lt < NT) load_chunk(lt);
        cp_async_commit();

        const float* xs = smem + (i % 3) * F_STAGE_FLOATS;
        const float* ws = xs + 256 * SSTF;

        #pragma unroll
        for (int kk = 0; kk < BK2; kk += 8) {
            uint32_t af[4][4];
            #pragma unroll
            for (int mi = 0; mi < 4; mi++) {
                const int r = (wm * 64 + mi * 16 + g) * SSTF + kk + t4;
                af[mi][0] = __float_as_uint(xs[r]);
                af[mi][1] = __float_as_uint(xs[r + 8 * SSTF]);
                af[mi][2] = __float_as_uint(xs[r + 4]);
                af[mi][3] = __float_as_uint(xs[r + 8 * SSTF + 4]);
            }
            #pragma unroll
            for (int m = 0; m < 3; m++) {
                #pragma unroll
                for (int ni = 0; ni < 4; ni++) {
                    uint32_t bf[2];
                    const int r = m * 64 * SSTF + (wn * 32 + ni * 8 + g) * SSTF + kk + t4;
                    bf[0] = __float_as_uint(ws[r]);
                    bf[1] = __float_as_uint(ws[r + 4]);
                    #pragma unroll
                    for (int mi = 0; mi < 4; mi++)
                        mma_tf32(acc[m][mi][ni], af[mi], bf);
                }
            }
        }
    }

    // --- phase switch: GEMM smem reads done; region becomes attn tiles ---
    cp_async_wait<0>();
    __syncthreads();

    // dump ALL 6 tiles (p=0,1 x Q,K,V) so acc registers die before attention
    float* aw = smem + warp * (6 * 32 * ATS2);
    #pragma unroll
    for (int p = 0; p < 2; p++) {
        #pragma unroll
        for (int m = 0; m < 3; m++) {
            float* buf = aw + (p * 3 + m) * (32 * ATS2);
            #pragma unroll
            for (int miL = 0; miL < 2; miL++) {
                const int mi = p * 2 + miL;
                #pragma unroll
                for (int ni = 0; ni < 4; ni++) {
                    const int r = miL * 16 + g;
                    const int c = ni * 8 + t4 * 2;
                    *(float2*)&buf[r * ATS2 + c] =
                        make_float2(tf32f(acc[m][mi][ni][0]), tf32f(acc[m][mi][ni][1]));
                    *(float2*)&buf[(r + 8) * ATS2 + c] =
                        make_float2(tf32f(acc[m][mi][ni][2]), tf32f(acc[m][mi][ni][3]));
                }
            }
        }
    }
    __syncwarp();

    const float scale = 0.17677669529663689f;  // 32^-0.5

    for (int p = 0; p < 2; p++) {
        float* Qb = aw + (p * 3 + 0) * (32 * ATS2);
        float* Kb = aw + (p * 3 + 1) * (32 * ATS2);
        float* Vb = aw + (p * 3 + 2) * (32 * ATS2);

        // ---- S = Q K^T (m16n8k8 over d=32) ----
        float sacc[2][4][4];
        #pragma unroll
        for (int mi = 0; mi < 2; mi++)
            #pragma unroll
            for (int ni = 0; ni < 4; ni++)
                #pragma unroll
                for (int r = 0; r < 4; r++) sacc[mi][ni][r] = 0.f;

        #pragma unroll
        for (int kk = 0; kk < 32; kk += 8) {
            uint32_t af[2][4];
            #pragma unroll
            for (int mi = 0; mi < 2; mi++) {
                const int r = (mi * 16 + g) * ATS2 + kk + t4;
                af[mi][0] = __float_as_uint(Qb[r]);
                af[mi][1] = __float_as_uint(Qb[r + 8 * ATS2]);
                af[mi][2] = __float_as_uint(Qb[r + 4]);
                af[mi][3] = __float_as_uint(Qb[r + 8 * ATS2 + 4]);
            }
            #pragma unroll
            for (int ni = 0; ni < 4; ni++) {
                uint32_t bf[2];
                const int r = (ni * 8 + g) * ATS2 + kk + t4;
                bf[0] = __float_as_uint(Kb[r]);
                bf[1] = __float_as_uint(Kb[r + 4]);
                #pragma unroll
                for (int mi = 0; mi < 2; mi++)
                    mma_tf32(sacc[mi][ni], af[mi], bf);
            }
        }

        // ---- mask + scale + softmax (rows across t4 quad) ----
        float rmax[2][2] = {{-1e30f, -1e30f}, {-1e30f, -1e30f}};
        #pragma unroll
        for (int mi = 0; mi < 2; mi++)
            #pragma unroll
            for (int ni = 0; ni < 4; ni++)
                #pragma unroll
                for (int j = 0; j < 4; j++) {
                    const int row = mi * 16 + g + (j >> 1) * 8;
                    const int col = ni * 8 + t4 * 2 + (j & 1);
                    float v = (col <= row) ? sacc[mi][ni][j] * scale : -1e30f;
                    sacc[mi][ni][j] = v;
                    rmax[mi][j >> 1] = fmaxf(rmax[mi][j >> 1], v);
                }
        #pragma unroll
        for (int mi = 0; mi < 2; mi++)
            #pragma unroll
            for (int h8 = 0; h8 < 2; h8++) {
                float m = rmax[mi][h8];
                m = fmaxf(m, __shfl_xor_sync(0xffffffffu, m, 1));
                m = fmaxf(m, __shfl_xor_sync(0xffffffffu, m, 2));
                rmax[mi][h8] = m;
            }
        float rsum[2][2] = {{0.f, 0.f}, {0.f, 0.f}};
        #pragma unroll
        for (int mi = 0; mi < 2; mi++)
            #pragma unroll
            for (int ni = 0; ni < 4; ni++)
                #pragma unroll
                for (int j = 0; j < 4; j++) {
                    float e = __expf(sacc[mi][ni][j] - rmax[mi][j >> 1]);
                    sacc[mi][ni][j] = e;
                    rsum[mi][j >> 1] += e;
                }
        float inv[2][2];
        #pragma unroll
        for (int mi = 0; mi < 2; mi++)
            #pragma unroll
            for (int h8 = 0; h8 < 2; h8++) {
                float s = rsum[mi][h8];
                s += __shfl_xor_sync(0xffffffffu, s, 1);
                s += __shfl_xor_sync(0xffffffffu, s, 2);
                inv[mi][h8] = 1.0f / s;
            }

        // ---- unnormalized P (tf32) into Qb (Q dead) ----
        __syncwarp();
        #pragma unroll
        for (int mi = 0; mi < 2; mi++)
            #pragma unroll
            for (int ni = 0; ni < 4; ni++) {
                const int r = mi * 16 + g;
                const int c = ni * 8 + t4 * 2;
                *(float2*)&Qb[r * ATS2 + c] =
                    make_float2(tf32f(sacc[mi][ni][0]), tf32f(sacc[mi][ni][1]));
                *(float2*)&Qb[(r + 8) * ATS2 + c] =
                    make_float2(tf32f(sacc[mi][ni][2]), tf32f(sacc[mi][ni][3]));
            }
        __syncwarp();

        // ---- O = P V (B-frag reads V[s][d] transposed) ----
        float oacc[2][4][4];
        #pragma unroll
        for (int mi = 0; mi < 2; mi++)
            #pragma unroll
            for (int ni = 0; ni < 4; ni++)
                #pragma unroll
                for (int r = 0; r < 4; r++) oacc[mi][ni][r] = 0.f;

        #pragma unroll
        for (int kk = 0; kk < 32; kk += 8) {
            uint32_t af[2][4];
            #pragma unroll
            for (int mi = 0; mi < 2; mi++) {
                const int r = (mi * 16 + g) * ATS2 + kk + t4;
                af[mi][0] = __float_as_uint(Qb[r]);
                af[mi][1] = __float_as_uint(Qb[r + 8 * ATS2]);
                af[mi][2] = __float_as_uint(Qb[r + 4]);
                af[mi][3] = __float_as_uint(Qb[r + 8 * ATS2 + 4]);
            }
            #pragma unroll
            for (int ni = 0; ni < 4; ni++) {
                uint32_t bf[2];
                bf[0] = __float_as_uint(Vb[(kk + t4) * ATS2 + ni * 8 + g]);
                bf[1] = __float_as_uint(Vb[(kk + 4 + t4) * ATS2 + ni * 8 + g]);
                #pragma unroll
                for (int mi = 0; mi < 2; mi++)
                    mma_tf32(oacc[mi][ni], af[mi], bf);
            }
        }

        // ---- normalize, dump O to Kb (K dead), coalesced store ----
        __syncwarp();
        #pragma unroll
        for (int mi = 0; mi < 2; mi++)
            #pragma unroll
            for (int ni = 0; ni < 4; ni++) {
                const int r = mi * 16 + g;
                const int c = ni * 8 + t4 * 2;
                *(float2*)&Kb[r * ATS2 + c] =
                    make_float2(tf32f(oacc[mi][ni][0] * inv[mi][0]),
                                tf32f(oacc[mi][ni][1] * inv[mi][0]));
                *(float2*)&Kb[(r + 8) * ATS2 + c] =
                    make_float2(tf32f(oacc[mi][ni][2] * inv[mi][1]),
                                tf32f(oacc[mi][ni][3] * inv[mi][1]));
            }
        __syncwarp();

        const int b = blockIdx.y * 8 + wm * 2 + p;
        const int h = blockIdx.x * 2 + wn;
        #pragma unroll
        for (int d4 = 0; d4 < 8; d4++) {
            float4 v = *(const float4*)&Kb[lane * ATS2 + d4 * 4];
            Ot[(size_t)(b * 32 + d4 * 4 + 0) * 512 + h * 32 + lane] = v.x;
            Ot[(size_t)(b * 32 + d4 * 4 + 1) * 512 + h * 32 + lane] = v.y;
            Ot[(size_t)(b * 32 + d4 * 4 + 2) * 512 + h * 32 + lane] = v.z;
            Ot[(size_t)(b * 32 + d4 * 4 + 3) * 512 + h * 32 + lane] = v.w;
        }
        __syncwarp();
    }
}

// ===========================================================================
// Projection NT GEMM: out = Ot @ Wp^T + bp
// BM=256, BN=128, BK=16, 256 threads, warp tile 64x64 (4x2 warps),
// 3-stage cp.async. Loader: 6 cp.async16/thread — each row slot gets BOTH
// 16B chunks (+0 and +16B), covering all 16 floats of the k-tile row.
// ===========================================================================
#define BK 16
#define SST 20
#define NSTAGE 3
#define PROJ_STAGE_FLOATS ((256 + 128) * SST)            // 7680
#define PROJ_SMEM_BYTES (NSTAGE * PROJ_STAGE_FLOATS * 4) // 92160

__global__ void __launch_bounds__(256, 1) proj_gemm_tf32(
    const float* __restrict__ A, const float* __restrict__ Bw,
    float* __restrict__ C, const float* __restrict__ bias)
{
    extern __shared__ float smem[];

    const int tid  = threadIdx.x;
    const int lane = tid & 31;
    const int warp = tid >> 5;
    const int wm   = warp & 3;    // 64-row stripe
    const int wn   = warp >> 2;   // 64-col stripe
    const int g    = lane >> 2;
    const int t4   = lane & 3;

    const int m0 = blockIdx.y * 256;
    const int n0 = blockIdx.x * 128;

    const int ldrow = tid >> 1;        // 0..127
    const int ldcol = (tid & 1) * 8;   // 0 or 8

    const uint32_t smem_u = (uint32_t)__cvta_generic_to_shared(smem);

    float acc[4][8][4];
    #pragma unroll
    for (int mi = 0; mi < 4; mi++)
        #pragma unroll
        for (int ni = 0; ni < 8; ni++)
            #pragma unroll
            for (int r = 0; r < 4; r++) acc[mi][ni][r] = 0.f;

    // loader: A rows ldrow & ldrow+128, B row ldrow; 2 x 16B chunks each
    auto load_chunk = [&](int s, int kt) {
        const uint32_t base = smem_u + (uint32_t)(s * PROJ_STAGE_FLOATS) * 4u;
        const float* a0 = A  + (size_t)(m0 + ldrow) * KDIM + kt + ldcol;
        const float* a1 = A  + (size_t)(m0 + ldrow + 128) * KDIM + kt + ldcol;
        const float* b0 = Bw + (size_t)(n0 + ldrow) * KDIM + kt + ldcol;
        const uint32_t ao0 = base + (uint32_t)(ldrow * SST + ldcol) * 4u;
        const uint32_t ao1 = base + (uint32_t)((ldrow + 128) * SST + ldcol) * 4u;
        const uint32_t bo0 = base + (uint32_t)(256 * SST + ldrow * SST + ldcol) * 4u;
        cp_async16(ao0,      a0);
        cp_async16(ao0 + 16, a0 + 4);
        cp_async16(ao1,      a1);
        cp_async16(ao1 + 16, a1 + 4);
        cp_async16(bo0,      b0);
        cp_async16(bo0 + 16, b0 + 4);
    };

    const int NT = KDIM / BK;   // 32

    load_chunk(0, 0);  cp_async_commit();
    load_chunk(1, BK); cp_async_commit();

    for (int i = 0; i < NT; i++) {
        cp_async_wait<1>();
        __syncthreads();

        const int lt = i + 2;
        if (lt < NT) load_chunk(lt % 3, lt * BK);
        cp_async_commit();

        const float* As = smem + (i % 3) * PROJ_STAGE_FLOATS;
        const float* Bs = As + 256 * SST;

        #pragma unroll
        for (int kk = 0; kk < BK; kk += 8) {
            uint32_t af[4][4];
            #pragma unroll
            for (int mi = 0; mi < 4; mi++) {
                const int r = (wm * 64 + mi * 16 + g) * SST + kk + t4;
                af[mi][0] = __float_as_uint(As[r]);
                af[mi][1] = __float_as_uint(As[r + 8 * SST]);
                af[mi][2] = __float_as_uint(As[r + 4]);
                af[mi][3] = __float_as_uint(As[r + 8 * SST + 4]);
            }
            uint32_t bf[8][2];
            #pragma unroll
            for (int ni = 0; ni < 8; ni++) {
                const int r = (wn * 64 + ni * 8 + g) * SST + kk + t4;
                bf[ni][0] = __float_as_uint(Bs[r]);
                bf[ni][1] = __float_as_uint(Bs[r + 4]);
            }
            #pragma unroll
            for (int mi = 0; mi < 4; mi++)
                #pragma unroll
                for (int ni = 0; ni < 8; ni++)
                    mma_tf32(acc[mi][ni], af[mi], bf[ni]);
        }
    }

    #pragma unroll
    for (int mi = 0; mi < 4; mi++) {
        #pragma unroll
        for (int ni = 0; ni < 8; ni++) {
            const int m = m0 + wm * 64 + mi * 16 + g;
            const int n = n0 + wn * 64 + ni * 8 + t4 * 2;
            const float bv0 = bias[n];
            const float bv1 = bias[n + 1];
            float2 v01 = make_float2(acc[mi][ni][0] + bv0, acc[mi][ni][1] + bv1);
            float2 v23 = make_float2(acc[mi][ni][2] + bv0, acc[mi][ni][3] + bv1);
            *(float2*)(&C[(size_t)m * NDIM + n])       = v01;
            *(float2*)(&C[(size_t)(m + 8) * NDIM + n]) = v23;
        }
    }
}

// ---------------------------------------------------------------------------
// Launch
// ---------------------------------------------------------------------------
extern "C" void kernel_launch(void* const* d_in, const int* in_sizes, int n_in,
                              void* d_out, int out_size) {
    const float* x  = (const float*)d_in[0];
    const float* Wq = (const float*)d_in[1];
    const float* Wk = (const float*)d_in[2];
    const float* Wv = (const float*)d_in[3];
    const float* Wp = (const float*)d_in[4];
    const float* bp = (const float*)d_in[5];
    float* out = (float*)d_out;

    float *gx, *go, *gwq, *gwk, *gwv, *gwp;
    cudaGetSymbolAddress((void**)&gx,  g_Xr);
    cudaGetSymbolAddress((void**)&go,  g_Ot);
    cudaGetSymbolAddress((void**)&gwq, g_Wq);
    cudaGetSymbolAddress((void**)&gwk, g_Wk);
    cudaGetSymbolAddress((void**)&gwv, g_Wv);
    cudaGetSymbolAddress((void**)&gwp, g_Wp);

    static bool attr_set = false;
    if (!attr_set) {
        cudaFuncSetAttribute(fused_qkv_attn,
                             cudaFuncAttributeMaxDynamicSharedMemorySize,
                             FUSED_SMEM_BYTES);
        cudaFuncSetAttribute(proj_gemm_tf32,
                             cudaFuncAttributeMaxDynamicSharedMemorySize,
                             PROJ_SMEM_BYTES);
        attr_set = true;
    }

    // pre-round inputs to tf32 (RNA) once
    const int xn4 = (MDIM * KDIM) / 4;
    const int wn4 = (NDIM * KDIM) / 4;
    round_tf32_kernel<<<xn4 / 256, 256>>>((const float4*)x,  (float4*)gx,  xn4);
    round_tf32_kernel<<<wn4 / 256, 256>>>((const float4*)Wq, (float4*)gwq, wn4);
    round_tf32_kernel<<<wn4 / 256, 256>>>((const float4*)Wk, (float4*)gwk, wn4);
    round_tf32_kernel<<<wn4 / 256, 256>>>((const float4*)Wv, (float4*)gwv, wn4);
    round_tf32_kernel<<<wn4 / 256, 256>>>((const float4*)Wp, (float4*)gwp, wn4);

    dim3 fgrid(NDIM / 64, MDIM / 256);   // (8, 512)
    fused_qkv_attn<<<fgrid, 256, FUSED_SMEM_BYTES>>>(gx, gwq, gwk, gwv, go);

    dim3 pgrid(NDIM / 128, MDIM / 256);  // (4, 512)
    proj_gemm_tf32<<<pgrid, 256, PROJ_SMEM_BYTES>>>(go, gwp, out, bp);
}

// round 11
// speedup vs baseline: 1.6524x; 1.0174x over previous
#include <cuda_runtime.h>
#include <cstdint>
#include <cstddef>

// Problem dims (fixed): B=4096, T=32, H=16, HS=32, E=512
//   M = B*T = 131072, N = H*HS = 512, K = E = 512
#define MDIM 131072
#define NDIM 512
#define KDIM 512

// Scratch: pre-rounded (tf32) inputs + attention output (proj-ready layout).
__device__ float g_Xr[(size_t)MDIM * KDIM];
__device__ float g_Ot[(size_t)MDIM * NDIM];
__device__ float g_Wq[NDIM * KDIM];
__device__ float g_Wk[NDIM * KDIM];
__device__ float g_Wv[NDIM * KDIM];
__device__ float g_Wp[NDIM * KDIM];

// ---------------------------------------------------------------------------
// helpers
// ---------------------------------------------------------------------------
__device__ __forceinline__ uint32_t tf32_rna(float x) {
    uint32_t y;
    asm("cvt.rna.tf32.f32 %0, %1;" : "=r"(y) : "f"(x));
    return y;
}
__device__ __forceinline__ float tf32f(float x) {
    return __uint_as_float(tf32_rna(x));
}

__device__ __forceinline__ void mma_tf32(float c[4], const uint32_t a[4], const uint32_t b[2]) {
    asm volatile(
        "mma.sync.aligned.m16n8k8.row.col.f32.tf32.tf32.f32 "
        "{%0,%1,%2,%3}, {%4,%5,%6,%7}, {%8,%9}, {%0,%1,%2,%3};\n"
        : "+f"(c[0]), "+f"(c[1]), "+f"(c[2]), "+f"(c[3])
        : "r"(a[0]), "r"(a[1]), "r"(a[2]), "r"(a[3]), "r"(b[0]), "r"(b[1]));
}

__device__ __forceinline__ void cp_async16(uint32_t smem_addr, const void* gptr) {
    asm volatile("cp.async.cg.shared.global [%0], [%1], 16;\n"
                 :: "r"(smem_addr), "l"(gptr));
}
__device__ __forceinline__ void cp_async_commit() {
    asm volatile("cp.async.commit_group;\n" ::: "memory");
}
template <int N>
__device__ __forceinline__ void cp_async_wait() {
    asm volatile("cp.async.wait_group %0;\n" :: "n"(N) : "memory");
}

// ---------------------------------------------------------------------------
// Pre-round pass: out[i] = tf32_rna(in[i]), float4-vectorized.
// ---------------------------------------------------------------------------
__global__ void __launch_bounds__(256) round_tf32_kernel(
    const float4* __restrict__ in, float4* __restrict__ out, int n4)
{
    int i = blockIdx.x * 256 + threadIdx.x;
    if (i < n4) {
        float4 v = in[i];
        v.x = tf32f(v.x); v.y = tf32f(v.y);
        v.z = tf32f(v.z); v.w = tf32f(v.w);
        out[i] = v;
    }
}

// ===========================================================================
// Fused QKV GEMM + tensor-core attention (legacy mma.sync tf32).
// Grid (8, 512). Block: 512 threads = 16 warps (8 wm x 2 wn).
// CTA tile: M=256 rows (8 batches), N=64 (2 heads) x 3 matrices.
// Warp tile: 32x32 per matrix (acc 96 regs) -> 4 warps/SMSP for latency
// hiding. Each warp owns exactly 1 attention problem (batch wm, head wn).
// BK=32, 3-stage cp.async. smem: stages 3x64512B inside 221184B attn region.
// ===========================================================================
#define BK2 32
#define SSTF 36             // 32 + 4 pad; frag banks 4g+t4, conflict-free
#define ATS2 36             // attention tile stride
#define F_STAGE_FLOATS (256 * SSTF + 3 * 64 * SSTF)   // 16128
#define FUSED_SMEM_BYTES (16 * 3 * 32 * ATS2 * 4)     // 221184

extern "C" __global__ void __launch_bounds__(512, 1) fused_qkv_attn(
    const float* __restrict__ X,
    const float* __restrict__ Wq, const float* __restrict__ Wk,
    const float* __restrict__ Wv, float* __restrict__ Ot)
{
    extern __shared__ float smem[];

    const int tid  = threadIdx.x;
    const int lane = tid & 31;
    const int warp = tid >> 5;
    const int wm   = warp & 7;    // batch within CTA (32-row stripe)
    const int wn   = warp >> 3;   // head within CTA (32-col stripe)
    const int g    = lane >> 2;
    const int t4   = lane & 3;

    const int m0 = blockIdx.y * 256;
    const int n0 = blockIdx.x * 64;

    const uint32_t smem_u = (uint32_t)__cvta_generic_to_shared(smem);

    float acc[3][2][4][4];
    #pragma unroll
    for (int m = 0; m < 3; m++)
        #pragma unroll
        for (int mi = 0; mi < 2; mi++)
            #pragma unroll
            for (int ni = 0; ni < 4; ni++)
                #pragma unroll
                for (int r = 0; r < 4; r++) acc[m][mi][ni][r] = 0.f;

    const float* Wg[3] = {Wq, Wk, Wv};

    // ---- chunk loader: 4 A + 3 B cp.async16 per thread (512 threads) ----
    auto load_chunk = [&](int c) {
        const uint32_t st = smem_u + (uint32_t)((c % 3) * F_STAGE_FLOATS) * 4u;
        const int kt = c * BK2;
        #pragma unroll
        for (int j = 0; j < 4; j++) {
            const int idx = tid + 512 * j;          // 0..2047
            const int row = idx >> 3, c16 = idx & 7;
            cp_async16(st + (uint32_t)(row * SSTF + c16 * 4) * 4u,
                       X + (size_t)(m0 + row) * KDIM + kt + c16 * 4);
        }
        #pragma unroll
        for (int j = 0; j < 3; j++) {
            const int idx = tid + 512 * j;          // 0..1535
            const int m = idx >> 9, row = (idx >> 3) & 63, c16 = idx & 7;
            cp_async16(st + (uint32_t)(256 * SSTF + m * 64 * SSTF + row * SSTF + c16 * 4) * 4u,
                       Wg[m] + (size_t)(n0 + row) * KDIM + kt + c16 * 4);
        }
    };

    const int NT = KDIM / BK2;   // 16

    load_chunk(0); cp_async_commit();
    load_chunk(1); cp_async_commit();

    for (int i = 0; i < NT; i++) {
        cp_async_wait<1>();
        __syncthreads();

        const int lt = i + 2;
        if (lt < NT) load_chunk(lt);
        cp_async_commit();

        const float* xs = smem + (i % 3) * F_STAGE_FLOATS;
        const float* ws = xs + 256 * SSTF;

        #pragma unroll
        for (int kk = 0; kk < BK2; kk += 8) {
            uint32_t af[2][4];
            #pragma unroll
            for (int mi = 0; mi < 2; mi++) {
                const int r = (wm * 32 + mi * 16 + g) * SSTF + kk + t4;
                af[mi][0] = __float_as_uint(xs[r]);
                af[mi][1] = __float_as_uint(xs[r + 8 * SSTF]);
                af[mi][2] = __float_as_uint(xs[r + 4]);
                af[mi][3] = __float_as_uint(xs[r + 8 * SSTF + 4]);
            }
            #pragma unroll
            for (int m = 0; m < 3; m++) {
                #pragma unroll
                for (int ni = 0; ni < 4; ni++) {
                    uint32_t bf[2];
                    const int r = m * 64 * SSTF + (wn * 32 + ni * 8 + g) * SSTF + kk + t4;
                    bf[0] = __float_as_uint(ws[r]);
                    bf[1] = __float_as_uint(ws[r + 4]);
                    #pragma unroll
                    for (int mi = 0; mi < 2; mi++)
                        mma_tf32(acc[m][mi][ni], af[mi], bf);
                }
            }
        }
    }

    // --- phase switch: GEMM smem reads done; region becomes attn tiles ---
    cp_async_wait<0>();
    __syncthreads();

    // dump Q,K,V (tf32-rounded) to per-warp tiles (acc regs die here)
    float* aw = smem + warp * (3 * 32 * ATS2);
    float* Qb = aw;                 // later reused as P
    float* Kb = aw + 32 * ATS2;     // later reused as O
    float* Vb = aw + 2 * 32 * ATS2;
    float* bufs[3] = {Qb, Kb, Vb};

    #pragma unroll
    for (int m = 0; m < 3; m++) {
        #pragma unroll
        for (int mi = 0; mi < 2; mi++) {
            #pragma unroll
            for (int ni = 0; ni < 4; ni++) {
                const int r = mi * 16 + g;
                const int c = ni * 8 + t4 * 2;
                *(float2*)&bufs[m][r * ATS2 + c] =
                    make_float2(tf32f(acc[m][mi][ni][0]), tf32f(acc[m][mi][ni][1]));
                *(float2*)&bufs[m][(r + 8) * ATS2 + c] =
                    make_float2(tf32f(acc[m][mi][ni][2]), tf32f(acc[m][mi][ni][3]));
            }
        }
    }
    __syncwarp();

    const float scale = 0.17677669529663689f;  // 32^-0.5

    // ---- S = Q K^T (m16n8k8 over d=32) ----
    float sacc[2][4][4];
    #pragma unroll
    for (int mi = 0; mi < 2; mi++)
        #pragma unroll
        for (int ni = 0; ni < 4; ni++)
            #pragma unroll
            for (int r = 0; r < 4; r++) sacc[mi][ni][r] = 0.f;

    #pragma unroll
    for (int kk = 0; kk < 32; kk += 8) {
        uint32_t af[2][4];
        #pragma unroll
        for (int mi = 0; mi < 2; mi++) {
            const int r = (mi * 16 + g) * ATS2 + kk + t4;
            af[mi][0] = __float_as_uint(Qb[r]);
            af[mi][1] = __float_as_uint(Qb[r + 8 * ATS2]);
            af[mi][2] = __float_as_uint(Qb[r + 4]);
            af[mi][3] = __float_as_uint(Qb[r + 8 * ATS2 + 4]);
        }
        #pragma unroll
        for (int ni = 0; ni < 4; ni++) {
            uint32_t bf[2];
            const int r = (ni * 8 + g) * ATS2 + kk + t4;
            bf[0] = __float_as_uint(Kb[r]);
            bf[1] = __float_as_uint(Kb[r + 4]);
            #pragma unroll
            for (int mi = 0; mi < 2; mi++)
                mma_tf32(sacc[mi][ni], af[mi], bf);
        }
    }

    // ---- mask + scale + softmax (rows across t4 quad) ----
    float rmax[2][2] = {{-1e30f, -1e30f}, {-1e30f, -1e30f}};
    #pragma unroll
    for (int mi = 0; mi < 2; mi++)
        #pragma unroll
        for (int ni = 0; ni < 4; ni++)
            #pragma unroll
            for (int j = 0; j < 4; j++) {
                const int row = mi * 16 + g + (j >> 1) * 8;
                const int col = ni * 8 + t4 * 2 + (j & 1);
                float v = (col <= row) ? sacc[mi][ni][j] * scale : -1e30f;
                sacc[mi][ni][j] = v;
                rmax[mi][j >> 1] = fmaxf(rmax[mi][j >> 1], v);
            }
    #pragma unroll
    for (int mi = 0; mi < 2; mi++)
        #pragma unroll
        for (int h8 = 0; h8 < 2; h8++) {
            float m = rmax[mi][h8];
            m = fmaxf(m, __shfl_xor_sync(0xffffffffu, m, 1));
            m = fmaxf(m, __shfl_xor_sync(0xffffffffu, m, 2));
            rmax[mi][h8] = m;
        }
    float rsum[2][2] = {{0.f, 0.f}, {0.f, 0.f}};
    #pragma unroll
    for (int mi = 0; mi < 2; mi++)
        #pragma unroll
        for (int ni = 0; ni < 4; ni++)
            #pragma unroll
            for (int j = 0; j < 4; j++) {
                float e = __expf(sacc[mi][ni][j] - rmax[mi][j >> 1]);
                sacc[mi][ni][j] = e;
                rsum[mi][j >> 1] += e;
            }
    float inv[2][2];
    #pragma unroll
    for (int mi = 0; mi < 2; mi++)
        #pragma unroll
        for (int h8 = 0; h8 < 2; h8++) {
            float s = rsum[mi][h8];
            s += __shfl_xor_sync(0xffffffffu, s, 1);
            s += __shfl_xor_sync(0xffffffffu, s, 2);
            inv[mi][h8] = 1.0f / s;
        }

    // ---- unnormalized P (tf32) into Qb (Q dead) ----
    __syncwarp();
    #pragma unroll
    for (int mi = 0; mi < 2; mi++)
        #pragma unroll
        for (int ni = 0; ni < 4; ni++) {
            const int r = mi * 16 + g;
            const int c = ni * 8 + t4 * 2;
            *(float2*)&Qb[r * ATS2 + c] =
                make_float2(tf32f(sacc[mi][ni][0]), tf32f(sacc[mi][ni][1]));
            *(float2*)&Qb[(r + 8) * ATS2 + c] =
                make_float2(tf32f(sacc[mi][ni][2]), tf32f(sacc[mi][ni][3]));
        }
    __syncwarp();

    // ---- O = P V (B-frag reads V[s][d] transposed) ----
    float oacc[2][4][4];
    #pragma unroll
    for (int mi = 0; mi < 2; mi++)
        #pragma unroll
        for (int ni = 0; ni < 4; ni++)
            #pragma unroll
            for (int r = 0; r < 4; r++) oacc[mi][ni][r] = 0.f;

    #pragma unroll
    for (int kk = 0; kk < 32; kk += 8) {
        uint32_t af[2][4];
        #pragma unroll
        for (int mi = 0; mi < 2; mi++) {
            const int r = (mi * 16 + g) * ATS2 + kk + t4;
            af[mi][0] = __float_as_uint(Qb[r]);
            af[mi][1] = __float_as_uint(Qb[r + 8 * ATS2]);
            af[mi][2] = __float_as_uint(Qb[r + 4]);
            af[mi][3] = __float_as_uint(Qb[r + 8 * ATS2 + 4]);
        }
        #pragma unroll
        for (int ni = 0; ni < 4; ni++) {
            uint32_t bf[2];
            bf[0] = __float_as_uint(Vb[(kk + t4) * ATS2 + ni * 8 + g]);
            bf[1] = __float_as_uint(Vb[(kk + 4 + t4) * ATS2 + ni * 8 + g]);
            #pragma unroll
            for (int mi = 0; mi < 2; mi++)
                mma_tf32(oacc[mi][ni], af[mi], bf);
        }
    }

    // ---- normalize, dump O to Kb (K dead), coalesced store ----
    __syncwarp();
    #pragma unroll
    for (int mi = 0; mi < 2; mi++)
        #pragma unroll
        for (int ni = 0; ni < 4; ni++) {
            const int r = mi * 16 + g;
            const int c = ni * 8 + t4 * 2;
            *(float2*)&Kb[r * ATS2 + c] =
                make_float2(tf32f(oacc[mi][ni][0] * inv[mi][0]),
                            tf32f(oacc[mi][ni][1] * inv[mi][0]));
            *(float2*)&Kb[(r + 8) * ATS2 + c] =
                make_float2(tf32f(oacc[mi][ni][2] * inv[mi][1]),
                            tf32f(oacc[mi][ni][3] * inv[mi][1]));
        }
    __syncwarp();

    const int b = blockIdx.y * 8 + wm;
    const int h = blockIdx.x * 2 + wn;
    #pragma unroll
    for (int d4 = 0; d4 < 8; d4++) {
        float4 v = *(const float4*)&Kb[lane * ATS2 + d4 * 4];
        Ot[(size_t)(b * 32 + d4 * 4 + 0) * 512 + h * 32 + lane] = v.x;
        Ot[(size_t)(b * 32 + d4 * 4 + 1) * 512 + h * 32 + lane] = v.y;
        Ot[(size_t)(b * 32 + d4 * 4 + 2) * 512 + h * 32 + lane] = v.z;
        Ot[(size_t)(b * 32 + d4 * 4 + 3) * 512 + h * 32 + lane] = v.w;
    }
}

// ===========================================================================
// Projection NT GEMM: out = Ot @ Wp^T + bp
// BM=256, BN=64, BK=16, 512 threads = 16 warps (8 wm x 2 wn), warp tile
// 32x32 (acc 32 regs), 3-stage cp.async, launch_bounds(512,2) ->
// 2 CTAs/SM = 32 warps/SM (8/SMSP).
// ===========================================================================
#define BK 16
#define SST 20
#define PROJ_STAGE_FLOATS ((256 + 64) * SST)             // 6400
#define PROJ_SMEM_BYTES (3 * PROJ_STAGE_FLOATS * 4)      // 76800

__global__ void __launch_bounds__(512, 2) proj_gemm_tf32(
    const float* __restrict__ A, const float* __restrict__ Bw,
    float* __restrict__ C, const float* __restrict__ bias)
{
    extern __shared__ float smem[];

    const int tid  = threadIdx.x;
    const int lane = tid & 31;
    const int warp = tid >> 5;
    const int wm   = warp & 7;    // 32-row stripe
    const int wn   = warp >> 3;   // 32-col stripe
    const int g    = lane >> 2;
    const int t4   = lane & 3;

    const int m0 = blockIdx.y * 256;
    const int n0 = blockIdx.x * 64;

    const uint32_t smem_u = (uint32_t)__cvta_generic_to_shared(smem);

    float acc[2][4][4];
    #pragma unroll
    for (int mi = 0; mi < 2; mi++)
        #pragma unroll
        for (int ni = 0; ni < 4; ni++)
            #pragma unroll
            for (int r = 0; r < 4; r++) acc[mi][ni][r] = 0.f;

    // loader: A 256 rows x 4 chunks = 1024 (2/thread); B 64 x 4 = 256 (tid<256)
    auto load_chunk = [&](int s, int kt) {
        const uint32_t base = smem_u + (uint32_t)(s * PROJ_STAGE_FLOATS) * 4u;
        #pragma unroll
        for (int j = 0; j < 2; j++) {
            const int idx = tid + 512 * j;        // 0..1023
            const int row = idx >> 2, c16 = idx & 3;
            cp_async16(base + (uint32_t)(row * SST + c16 * 4) * 4u,
                       A + (size_t)(m0 + row) * KDIM + kt + c16 * 4);
        }
        if (tid < 256) {
            const int row = tid >> 2, c16 = tid & 3;
            cp_async16(base + (uint32_t)(256 * SST + row * SST + c16 * 4) * 4u,
                       Bw + (size_t)(n0 + row) * KDIM + kt + c16 * 4);
        }
    };

    const int NT = KDIM / BK;   // 32

    load_chunk(0, 0);  cp_async_commit();
    load_chunk(1, BK); cp_async_commit();

    for (int i = 0; i < NT; i++) {
        cp_async_wait<1>();
        __syncthreads();

        const int lt = i + 2;
        if (lt < NT) load_chunk(lt % 3, lt * BK);
        cp_async_commit();

        const float* As = smem + (i % 3) * PROJ_STAGE_FLOATS;
        const float* Bs = As + 256 * SST;

        #pragma unroll
        for (int kk = 0; kk < BK; kk += 8) {
            uint32_t af[2][4];
            #pragma unroll
            for (int mi = 0; mi < 2; mi++) {
                const int r = (wm * 32 + mi * 16 + g) * SST + kk + t4;
                af[mi][0] = __float_as_uint(As[r]);
                af[mi][1] = __float_as_uint(As[r + 8 * SST]);
                af[mi][2] = __float_as_uint(As[r + 4]);
                af[mi][3] = __float_as_uint(As[r + 8 * SST + 4]);
            }
            uint32_t bf[4][2];
            #pragma unroll
            for (int ni = 0; ni < 4; ni++) {
                const int r = (wn * 32 + ni * 8 + g) * SST + kk + t4;
                bf[ni][0] = __float_as_uint(Bs[r]);
                bf[ni][1] = __float_as_uint(Bs[r + 4]);
            }
            #pragma unroll
            for (int mi = 0; mi < 2; mi++)
                #pragma unroll
                for (int ni = 0; ni < 4; ni++)
                    mma_tf32(acc[mi][ni], af[mi], bf[ni]);
        }
    }

    #pragma unroll
    for (int mi = 0; mi < 2; mi++) {
        #pragma unroll
        for (int ni = 0; ni < 4; ni++) {
            const int m = m0 + wm * 32 + mi * 16 + g;
            const int n = n0 + wn * 32 + ni * 8 + t4 * 2;
            const float bv0 = bias[n];
            const float bv1 = bias[n + 1];
            float2 v01 = make_float2(acc[mi][ni][0] + bv0, acc[mi][ni][1] + bv1);
            float2 v23 = make_float2(acc[mi][ni][2] + bv0, acc[mi][ni][3] + bv1);
            *(float2*)(&C[(size_t)m * NDIM + n])       = v01;
            *(float2*)(&C[(size_t)(m + 8) * NDIM + n]) = v23;
        }
    }
}

// ---------------------------------------------------------------------------
// Launch
// ---------------------------------------------------------------------------
extern "C" void kernel_launch(void* const* d_in, const int* in_sizes, int n_in,
                              void* d_out, int out_size) {
    const float* x  = (const float*)d_in[0];
    const float* Wq = (const float*)d_in[1];
    const float* Wk = (const float*)d_in[2];
    const float* Wv = (const float*)d_in[3];
    const float* Wp = (const float*)d_in[4];
    const float* bp = (const float*)d_in[5];
    float* out = (float*)d_out;

    float *gx, *go, *gwq, *gwk, *gwv, *gwp;
    cudaGetSymbolAddress((void**)&gx,  g_Xr);
    cudaGetSymbolAddress((void**)&go,  g_Ot);
    cudaGetSymbolAddress((void**)&gwq, g_Wq);
    cudaGetSymbolAddress((void**)&gwk, g_Wk);
    cudaGetSymbolAddress((void**)&gwv, g_Wv);
    cudaGetSymbolAddress((void**)&gwp, g_Wp);

    static bool attr_set = false;
    if (!attr_set) {
        cudaFuncSetAttribute(fused_qkv_attn,
                             cudaFuncAttributeMaxDynamicSharedMemorySize,
                             FUSED_SMEM_BYTES);
        cudaFuncSetAttribute(proj_gemm_tf32,
                             cudaFuncAttributeMaxDynamicSharedMemorySize,
                             PROJ_SMEM_BYTES);
        attr_set = true;
    }

    // pre-round inputs to tf32 (RNA) once
    const int xn4 = (MDIM * KDIM) / 4;
    const int wn4 = (NDIM * KDIM) / 4;
    round_tf32_kernel<<<xn4 / 256, 256>>>((const float4*)x,  (float4*)gx,  xn4);
    round_tf32_kernel<<<wn4 / 256, 256>>>((const float4*)Wq, (float4*)gwq, wn4);
    round_tf32_kernel<<<wn4 / 256, 256>>>((const float4*)Wk, (float4*)gwk, wn4);
    round_tf32_kernel<<<wn4 / 256, 256>>>((const float4*)Wv, (float4*)gwv, wn4);
    round_tf32_kernel<<<wn4 / 256, 256>>>((const float4*)Wp, (float4*)gwp, wn4);

    dim3 fgrid(NDIM / 64, MDIM / 256);   // (8, 512)
    fused_qkv_attn<<<fgrid, 512, FUSED_SMEM_BYTES>>>(gx, gwq, gwk, gwv, go);

    dim3 pgrid(NDIM / 64, MDIM / 256);   // (8, 512)
    proj_gemm_tf32<<<pgrid, 512, PROJ_SMEM_BYTES>>>(go, gwp, out, bp);
}

// round 13
// speedup vs baseline: 3.1410x; 1.9009x over previous
#include <cuda_runtime.h>
#include <cuda_fp16.h>
#include <cstdint>
#include <cstddef>

// Problem dims (fixed): B=4096, T=32, H=16, HS=32, E=512
//   M = B*T = 131072, N = H*HS = 512, K = E = 512
#define MDIM 131072
#define NDIM 512
#define KDIM 512

// Scratch: fp16-rounded inputs + attention output (proj-ready layout, fp16).
__device__ __half g_Xh[(size_t)MDIM * KDIM];
__device__ __half g_Oth[(size_t)MDIM * NDIM];
__device__ __half g_Wqh[NDIM * KDIM];
__device__ __half g_Wkh[NDIM * KDIM];
__device__ __half g_Wvh[NDIM * KDIM];
__device__ __half g_Wph[NDIM * KDIM];

// ---------------------------------------------------------------------------
// helpers
// ---------------------------------------------------------------------------
__device__ __forceinline__ void mma_f16(float c[4], const uint32_t a[4], const uint32_t b[2]) {
    asm volatile(
        "mma.sync.aligned.m16n8k16.row.col.f32.f16.f16.f32 "
        "{%0,%1,%2,%3}, {%4,%5,%6,%7}, {%8,%9}, {%0,%1,%2,%3};\n"
        : "+f"(c[0]), "+f"(c[1]), "+f"(c[2]), "+f"(c[3])
        : "r"(a[0]), "r"(a[1]), "r"(a[2]), "r"(a[3]), "r"(b[0]), "r"(b[1]));
}

__device__ __forceinline__ uint32_t ld32h(const __half* p) {
    return *(const uint32_t*)p;
}

__device__ __forceinline__ void cp_async16(uint32_t smem_addr, const void* gptr) {
    asm volatile("cp.async.cg.shared.global [%0], [%1], 16;\n"
                 :: "r"(smem_addr), "l"(gptr));
}
__device__ __forceinline__ void cp_async_commit() {
    asm volatile("cp.async.commit_group;\n" ::: "memory");
}
template <int N>
__device__ __forceinline__ void cp_async_wait() {
    asm volatile("cp.async.wait_group %0;\n" :: "n"(N) : "memory");
}

// ---------------------------------------------------------------------------
// Convert pass: fp32 -> fp16 (RN), 8 elements/thread.
// ---------------------------------------------------------------------------
__global__ void __launch_bounds__(256) round_f16_kernel(
    const float4* __restrict__ in, __half2* __restrict__ out, int n8)
{
    int i = blockIdx.x * 256 + threadIdx.x;
    if (i < n8) {
        float4 a = in[2 * i], b = in[2 * i + 1];
        out[4 * i + 0] = __floats2half2_rn(a.x, a.y);
        out[4 * i + 1] = __floats2half2_rn(a.z, a.w);
        out[4 * i + 2] = __floats2half2_rn(b.x, b.y);
        out[4 * i + 3] = __floats2half2_rn(b.z, b.w);
    }
}

// ===========================================================================
// Fused QKV GEMM + tensor-core attention (fp16 mma.sync m16n8k16).
// Grid (8, 512). Block: 512 threads = 16 warps (8 wm x 2 wn).
// CTA tile: M=256 rows (8 batches), N=64 (2 heads) x 3 matrices.
// Warp tile: 32x32 per matrix. BK=64 halves (8 k-tiles of 4 k16-steps).
// Each warp owns exactly 1 attention problem (batch wm, head wn).
// smem: GEMM stages 3 x 64512B = 193536B; attn tiles 16x3x32x40 halves
// = 122880B aliased inside.
// ===========================================================================
#define BK2 64              // halves per k-tile
#define SH 72               // GEMM smem row stride in halves (64 + 8 pad)
#define AH 40               // attention tile stride in halves (32 + 8 pad)
#define F_STAGE_HALVES ((256 + 3 * 64) * SH)          // 32256
#define FUSED_SMEM_BYTES (3 * F_STAGE_HALVES * 2)     // 193536

extern "C" __global__ void __launch_bounds__(512, 1) fused_qkv_attn(
    const __half* __restrict__ X,
    const __half* __restrict__ Wq, const __half* __restrict__ Wk,
    const __half* __restrict__ Wv, __half* __restrict__ Ot)
{
    extern __shared__ __half smem_h[];

    const int tid  = threadIdx.x;
    const int lane = tid & 31;
    const int warp = tid >> 5;
    const int wm   = warp & 7;    // batch within CTA (32-row stripe)
    const int wn   = warp >> 3;   // head within CTA (32-col stripe)
    const int g    = lane >> 2;
    const int t4   = lane & 3;

    const int m0 = blockIdx.y * 256;
    const int n0 = blockIdx.x * 64;

    const uint32_t smem_u = (uint32_t)__cvta_generic_to_shared(smem_h);

    float acc[3][2][4][4];
    #pragma unroll
    for (int m = 0; m < 3; m++)
        #pragma unroll
        for (int mi = 0; mi < 2; mi++)
            #pragma unroll
            for (int ni = 0; ni < 4; ni++)
                #pragma unroll
                for (int r = 0; r < 4; r++) acc[m][mi][ni][r] = 0.f;

    const __half* Wg[3] = {Wq, Wk, Wv};

    // ---- chunk loader: 4 A + 3 B cp.async16 per thread ----
    // A: 256 rows x 128B (8 chunks) = 2048 chunks; B: 3 x 64 x 8 = 1536.
    auto load_chunk = [&](int c) {
        const uint32_t st = smem_u + (uint32_t)((c % 3) * F_STAGE_HALVES) * 2u;
        const int kt = c * BK2;
        #pragma unroll
        for (int j = 0; j < 4; j++) {
            const int idx = tid + 512 * j;          // 0..2047
            const int row = idx >> 3, c16 = idx & 7;
            cp_async16(st + (uint32_t)(row * SH + c16 * 8) * 2u,
                       X + (size_t)(m0 + row) * KDIM + kt + c16 * 8);
        }
        #pragma unroll
        for (int j = 0; j < 3; j++) {
            const int idx = tid + 512 * j;          // 0..1535
            const int m = idx >> 9, row = (idx >> 3) & 63, c16 = idx & 7;
            cp_async16(st + (uint32_t)(256 * SH + m * 64 * SH + row * SH + c16 * 8) * 2u,
                       Wg[m] + (size_t)(n0 + row) * KDIM + kt + c16 * 8);
        }
    };

    const int NT = KDIM / BK2;   // 8

    load_chunk(0); cp_async_commit();
    load_chunk(1); cp_async_commit();

    for (int i = 0; i < NT; i++) {
        cp_async_wait<1>();
        __syncthreads();

        const int lt = i + 2;
        if (lt < NT) load_chunk(lt);
        cp_async_commit();

        const __half* xs = smem_h + (i % 3) * F_STAGE_HALVES;
        const __half* ws = xs + 256 * SH;

        #pragma unroll
        for (int kk = 0; kk < BK2; kk += 16) {
            uint32_t af[2][4];
            #pragma unroll
            for (int mi = 0; mi < 2; mi++) {
                const int r0 = (wm * 32 + mi * 16 + g) * SH + kk + 2 * t4;
                af[mi][0] = ld32h(xs + r0);
                af[mi][1] = ld32h(xs + r0 + 8 * SH);
                af[mi][2] = ld32h(xs + r0 + 8);
                af[mi][3] = ld32h(xs + r0 + 8 * SH + 8);
            }
            #pragma unroll
            for (int m = 0; m < 3; m++) {
                #pragma unroll
                for (int ni = 0; ni < 4; ni++) {
                    uint32_t bf[2];
                    const int rb = m * 64 * SH + (wn * 32 + ni * 8 + g) * SH + kk + 2 * t4;
                    bf[0] = ld32h(ws + rb);
                    bf[1] = ld32h(ws + rb + 8);
                    #pragma unroll
                    for (int mi = 0; mi < 2; mi++)
                        mma_f16(acc[m][mi][ni], af[mi], bf);
                }
            }
        }
    }

    // --- phase switch: GEMM smem reads done; region becomes attn tiles ---
    cp_async_wait<0>();
    __syncthreads();

    // per-warp tiles: Q[t][d], K[s][d], Vt[d][s]  (stride AH halves)
    __half* aw = smem_h + warp * (3 * 32 * AH);
    __half* Qb = aw;                 // later reused as P
    __half* Kb = aw + 32 * AH;       // later reused as O
    __half* Vb = aw + 2 * 32 * AH;   // V stored TRANSPOSED: Vt[d][s]

    #pragma unroll
    for (int mi = 0; mi < 2; mi++) {
        #pragma unroll
        for (int ni = 0; ni < 4; ni++) {
            const int r = mi * 16 + g;
            const int c = ni * 8 + t4 * 2;
            // Q, K: [row][col] half2 pairs
            *(__half2*)&Qb[r * AH + c] =
                __floats2half2_rn(acc[0][mi][ni][0], acc[0][mi][ni][1]);
            *(__half2*)&Qb[(r + 8) * AH + c] =
                __floats2half2_rn(acc[0][mi][ni][2], acc[0][mi][ni][3]);
            *(__half2*)&Kb[r * AH + c] =
                __floats2half2_rn(acc[1][mi][ni][0], acc[1][mi][ni][1]);
            *(__half2*)&Kb[(r + 8) * AH + c] =
                __floats2half2_rn(acc[1][mi][ni][2], acc[1][mi][ni][3]);
            // V transposed: Vt[col][row] scalar halves
            Vb[c * AH + r]             = __float2half_rn(acc[2][mi][ni][0]);
            Vb[(c + 1) * AH + r]       = __float2half_rn(acc[2][mi][ni][1]);
            Vb[c * AH + r + 8]         = __float2half_rn(acc[2][mi][ni][2]);
            Vb[(c + 1) * AH + r + 8]   = __float2half_rn(acc[2][mi][ni][3]);
        }
    }
    __syncwarp();

    const float scale = 0.17677669529663689f;  // 32^-0.5

    // ---- S = Q K^T (m16n8k16 over d=32, 2 steps) ----
    float sacc[2][4][4];
    #pragma unroll
    for (int mi = 0; mi < 2; mi++)
        #pragma unroll
        for (int ni = 0; ni < 4; ni++)
            #pragma unroll
            for (int r = 0; r < 4; r++) sacc[mi][ni][r] = 0.f;

    #pragma unroll
    for (int kk = 0; kk < 32; kk += 16) {
        uint32_t af[2][4];
        #pragma unroll
        for (int mi = 0; mi < 2; mi++) {
            const int r0 = (mi * 16 + g) * AH + kk + 2 * t4;
            af[mi][0] = ld32h(Qb + r0);
            af[mi][1] = ld32h(Qb + r0 + 8 * AH);
            af[mi][2] = ld32h(Qb + r0 + 8);
            af[mi][3] = ld32h(Qb + r0 + 8 * AH + 8);
        }
        #pragma unroll
        for (int ni = 0; ni < 4; ni++) {
            uint32_t bf[2];
            const int rb = (ni * 8 + g) * AH + kk + 2 * t4;
            bf[0] = ld32h(Kb + rb);
            bf[1] = ld32h(Kb + rb + 8);
            #pragma unroll
            for (int mi = 0; mi < 2; mi++)
                mma_f16(sacc[mi][ni], af[mi], bf);
        }
    }

    // ---- mask + scale + softmax (rows across t4 quad), fp32 ----
    float rmax[2][2] = {{-1e30f, -1e30f}, {-1e30f, -1e30f}};
    #pragma unroll
    for (int mi = 0; mi < 2; mi++)
        #pragma unroll
        for (int ni = 0; ni < 4; ni++)
            #pragma unroll
            for (int j = 0; j < 4; j++) {
                const int row = mi * 16 + g + (j >> 1) * 8;
                const int col = ni * 8 + t4 * 2 + (j & 1);
                float v = (col <= row) ? sacc[mi][ni][j] * scale : -1e30f;
                sacc[mi][ni][j] = v;
                rmax[mi][j >> 1] = fmaxf(rmax[mi][j >> 1], v);
            }
    #pragma unroll
    for (int mi = 0; mi < 2; mi++)
        #pragma unroll
        for (int h8 = 0; h8 < 2; h8++) {
            float m = rmax[mi][h8];
            m = fmaxf(m, __shfl_xor_sync(0xffffffffu, m, 1));
            m = fmaxf(m, __shfl_xor_sync(0xffffffffu, m, 2));
            rmax[mi][h8] = m;
        }
    float rsum[2][2] = {{0.f, 0.f}, {0.f, 0.f}};
    #pragma unroll
    for (int mi = 0; mi < 2; mi++)
        #pragma unroll
        for (int ni = 0; ni < 4; ni++)
            #pragma unroll
            for (int j = 0; j < 4; j++) {
                float e = __expf(sacc[mi][ni][j] - rmax[mi][j >> 1]);
                sacc[mi][ni][j] = e;
                rsum[mi][j >> 1] += e;
            }
    float inv[2][2];
    #pragma unroll
    for (int mi = 0; mi < 2; mi++)
        #pragma unroll
        for (int h8 = 0; h8 < 2; h8++) {
            float s = rsum[mi][h8];
            s += __shfl_xor_sync(0xffffffffu, s, 1);
            s += __shfl_xor_sync(0xffffffffu, s, 2);
            inv[mi][h8] = 1.0f / s;
        }

    // ---- unnormalized P (fp16) into Qb (Q dead) ----
    __syncwarp();
    #pragma unroll
    for (int mi = 0; mi < 2; mi++)
        #pragma unroll
        for (int ni = 0; ni < 4; ni++) {
            const int r = mi * 16 + g;
            const int c = ni * 8 + t4 * 2;
            *(__half2*)&Qb[r * AH + c] =
                __floats2half2_rn(sacc[mi][ni][0], sacc[mi][ni][1]);
            *(__half2*)&Qb[(r + 8) * AH + c] =
                __floats2half2_rn(sacc[mi][ni][2], sacc[mi][ni][3]);
        }
    __syncwarp();

    // ---- O = P V  (B-frags contiguous from Vt[d][s]) ----
    float oacc[2][4][4];
    #pragma unroll
    for (int mi = 0; mi < 2; mi++)
        #pragma unroll
        for (int ni = 0; ni < 4; ni++)
            #pragma unroll
            for (int r = 0; r < 4; r++) oacc[mi][ni][r] = 0.f;

    #pragma unroll
    for (int kk = 0; kk < 32; kk += 16) {
        uint32_t af[2][4];
        #pragma unroll
        for (int mi = 0; mi < 2; mi++) {
            const int r0 = (mi * 16 + g) * AH + kk + 2 * t4;
            af[mi][0] = ld32h(Qb + r0);
            af[mi][1] = ld32h(Qb + r0 + 8 * AH);
            af[mi][2] = ld32h(Qb + r0 + 8);
            af[mi][3] = ld32h(Qb + r0 + 8 * AH + 8);
        }
        #pragma unroll
        for (int ni = 0; ni < 4; ni++) {
            uint32_t bf[2];
            const int rb = (ni * 8 + g) * AH + kk + 2 * t4;   // row d, k = s
            bf[0] = ld32h(Vb + rb);
            bf[1] = ld32h(Vb + rb + 8);
            #pragma unroll
            for (int mi = 0; mi < 2; mi++)
                mma_f16(oacc[mi][ni], af[mi], bf);
        }
    }

    // ---- normalize, dump O[t][d] (fp16) to Kb (K dead), coalesced store ----
    __syncwarp();
    #pragma unroll
    for (int mi = 0; mi < 2; mi++)
        #pragma unroll
        for (int ni = 0; ni < 4; ni++) {
            const int r = mi * 16 + g;
            const int c = ni * 8 + t4 * 2;
            *(__half2*)&Kb[r * AH + c] =
                __floats2half2_rn(oacc[mi][ni][0] * inv[mi][0],
                                  oacc[mi][ni][1] * inv[mi][0]);
            *(__half2*)&Kb[(r + 8) * AH + c] =
                __floats2half2_rn(oacc[mi][ni][2] * inv[mi][1],
                                  oacc[mi][ni][3] * inv[mi][1]);
        }
    __syncwarp();

    // Ot[(b*32+d)*512 + h*32 + t], t = lane -> lanes contiguous per d
    const int b = blockIdx.y * 8 + wm;
    const int h = blockIdx.x * 2 + wn;
    #pragma unroll
    for (int d = 0; d < 32; d++)
        Ot[(size_t)(b * 32 + d) * 512 + h * 32 + lane] = Kb[lane * AH + d];
}

// ===========================================================================
// Projection NT GEMM (fp16 mma m16n8k16): out = Ot @ Wp^T + bp (f32 out)
// BM=256, BN=64, BK=32 halves, 512 threads = 16 warps (8 wm x 2 wn),
// warp tile 32x32, 3-stage cp.async, launch_bounds(512,2).
// ===========================================================================
#define PBK 32
#define SH2 40              // 32 + 8 pad halves (80 B rows)
#define PROJ_STAGE_HALVES ((256 + 64) * SH2)             // 12800
#define PROJ_SMEM_BYTES (3 * PROJ_STAGE_HALVES * 2)      // 76800

__global__ void __launch_bounds__(512, 2) proj_gemm_f16(
    const __half* __restrict__ A, const __half* __restrict__ Bw,
    float* __restrict__ C, const float* __restrict__ bias)
{
    extern __shared__ __half smem_h[];

    const int tid  = threadIdx.x;
    const int lane = tid & 31;
    const int warp = tid >> 5;
    const int wm   = warp & 7;    // 32-row stripe
    const int wn   = warp >> 3;   // 32-col stripe
    const int g    = lane >> 2;
    const int t4   = lane & 3;

    const int m0 = blockIdx.y * 256;
    const int n0 = blockIdx.x * 64;

    const uint32_t smem_u = (uint32_t)__cvta_generic_to_shared(smem_h);

    float acc[2][4][4];
    #pragma unroll
    for (int mi = 0; mi < 2; mi++)
        #pragma unroll
        for (int ni = 0; ni < 4; ni++)
            #pragma unroll
            for (int r = 0; r < 4; r++) acc[mi][ni][r] = 0.f;

    // loader: A 256 rows x 4 chunks(16B) = 1024 (2/thread); B 64x4 = 256
    auto load_chunk = [&](int s, int kt) {
        const uint32_t base = smem_u + (uint32_t)(s * PROJ_STAGE_HALVES) * 2u;
        #pragma unroll
        for (int j = 0; j < 2; j++) {
            const int idx = tid + 512 * j;        // 0..1023
            const int row = idx >> 2, c16 = idx & 3;
            cp_async16(base + (uint32_t)(row * SH2 + c16 * 8) * 2u,
                       A + (size_t)(m0 + row) * KDIM + kt + c16 * 8);
        }
        if (tid < 256) {
            const int row = tid >> 2, c16 = tid & 3;
            cp_async16(base + (uint32_t)(256 * SH2 + row * SH2 + c16 * 8) * 2u,
                       Bw + (size_t)(n0 + row) * KDIM + kt + c16 * 8);
        }
    };

    const int NT = KDIM / PBK;   // 16

    load_chunk(0, 0);   cp_async_commit();
    load_chunk(1, PBK); cp_async_commit();

    for (int i = 0; i < NT; i++) {
        cp_async_wait<1>();
        __syncthreads();

        const int lt = i + 2;
        if (lt < NT) load_chunk(lt % 3, lt * PBK);
        cp_async_commit();

        const __half* As = smem_h + (i % 3) * PROJ_STAGE_HALVES;
        const __half* Bs = As + 256 * SH2;

        #pragma unroll
        for (int kk = 0; kk < PBK; kk += 16) {
            uint32_t af[2][4];
            #pragma unroll
            for (int mi = 0; mi < 2; mi++) {
                const int r0 = (wm * 32 + mi * 16 + g) * SH2 + kk + 2 * t4;
                af[mi][0] = ld32h(As + r0);
                af[mi][1] = ld32h(As + r0 + 8 * SH2);
                af[mi][2] = ld32h(As + r0 + 8);
                af[mi][3] = ld32h(As + r0 + 8 * SH2 + 8);
            }
            uint32_t bf[4][2];
            #pragma unroll
            for (int ni = 0; ni < 4; ni++) {
                const int rb = (wn * 32 + ni * 8 + g) * SH2 + kk + 2 * t4;
                bf[ni][0] = ld32h(Bs + rb);
                bf[ni][1] = ld32h(Bs + rb + 8);
            }
            #pragma unroll
            for (int mi = 0; mi < 2; mi++)
                #pragma unroll
                for (int ni = 0; ni < 4; ni++)
                    mma_f16(acc[mi][ni], af[mi], bf[ni]);
        }
    }

    #pragma unroll
    for (int mi = 0; mi < 2; mi++) {
        #pragma unroll
        for (int ni = 0; ni < 4; ni++) {
            const int m = m0 + wm * 32 + mi * 16 + g;
            const int n = n0 + wn * 32 + ni * 8 + t4 * 2;
            const float bv0 = bias[n];
            const float bv1 = bias[n + 1];
            float2 v01 = make_float2(acc[mi][ni][0] + bv0, acc[mi][ni][1] + bv1);
            float2 v23 = make_float2(acc[mi][ni][2] + bv0, acc[mi][ni][3] + bv1);
            *(float2*)(&C[(size_t)m * NDIM + n])       = v01;
            *(float2*)(&C[(size_t)(m + 8) * NDIM + n]) = v23;
        }
    }
}

// ---------------------------------------------------------------------------
// Launch
// ---------------------------------------------------------------------------
extern "C" void kernel_launch(void* const* d_in, const int* in_sizes, int n_in,
                              void* d_out, int out_size) {
    const float* x  = (const float*)d_in[0];
    const float* Wq = (const float*)d_in[1];
    const float* Wk = (const float*)d_in[2];
    const float* Wv = (const float*)d_in[3];
    const float* Wp = (const float*)d_in[4];
    const float* bp = (const float*)d_in[5];
    float* out = (float*)d_out;

    __half *gx, *go, *gwq, *gwk, *gwv, *gwp;
    cudaGetSymbolAddress((void**)&gx,  g_Xh);
    cudaGetSymbolAddress((void**)&go,  g_Oth);
    cudaGetSymbolAddress((void**)&gwq, g_Wqh);
    cudaGetSymbolAddress((void**)&gwk, g_Wkh);
    cudaGetSymbolAddress((void**)&gwv, g_Wvh);
    cudaGetSymbolAddress((void**)&gwp, g_Wph);

    static bool attr_set = false;
    if (!attr_set) {
        cudaFuncSetAttribute(fused_qkv_attn,
                             cudaFuncAttributeMaxDynamicSharedMemorySize,
                             FUSED_SMEM_BYTES);
        cudaFuncSetAttribute(proj_gemm_f16,
                             cudaFuncAttributeMaxDynamicSharedMemorySize,
                             PROJ_SMEM_BYTES);
        attr_set = true;
    }

    // convert inputs to fp16 once
    const int xn8 = (MDIM * KDIM) / 8;   // 8388608
    const int wn8 = (NDIM * KDIM) / 8;   // 32768
    round_f16_kernel<<<xn8 / 256, 256>>>((const float4*)x,  (__half2*)gx,  xn8);
    round_f16_kernel<<<wn8 / 256, 256>>>((const float4*)Wq, (__half2*)gwq, wn8);
    round_f16_kernel<<<wn8 / 256, 256>>>((const float4*)Wk, (__half2*)gwk, wn8);
    round_f16_kernel<<<wn8 / 256, 256>>>((const float4*)Wv, (__half2*)gwv, wn8);
    round_f16_kernel<<<wn8 / 256, 256>>>((const float4*)Wp, (__half2*)gwp, wn8);

    dim3 fgrid(NDIM / 64, MDIM / 256);   // (8, 512)
    fused_qkv_attn<<<fgrid, 512, FUSED_SMEM_BYTES>>>(gx, gwq, gwk, gwv, go);

    dim3 pgrid(NDIM / 64, MDIM / 256);   // (8, 512)
    proj_gemm_f16<<<pgrid, 512, PROJ_SMEM_BYTES>>>(go, gwp, out, bp);
}

// round 14
// speedup vs baseline: 3.1544x; 1.0043x over previous
#include <cuda_runtime.h>
#include <cuda_fp16.h>
#include <cstdint>
#include <cstddef>

// Problem dims (fixed): B=4096, T=32, H=16, HS=32, E=512
//   M = B*T = 131072, N = H*HS = 512, K = E = 512
#define MDIM 131072
#define NDIM 512
#define KDIM 512

// Scratch: fp16-rounded inputs + attention output (proj-ready layout, fp16).
__device__ __half g_Xh[(size_t)MDIM * KDIM];
__device__ __half g_Oth[(size_t)MDIM * NDIM];
__device__ __half g_Wqh[NDIM * KDIM];
__device__ __half g_Wkh[NDIM * KDIM];
__device__ __half g_Wvh[NDIM * KDIM];
__device__ __half g_Wph[NDIM * KDIM];

// ---------------------------------------------------------------------------
// helpers
// ---------------------------------------------------------------------------
__device__ __forceinline__ void mma_f16(float c[4], const uint32_t a[4], const uint32_t b[2]) {
    asm volatile(
        "mma.sync.aligned.m16n8k16.row.col.f32.f16.f16.f32 "
        "{%0,%1,%2,%3}, {%4,%5,%6,%7}, {%8,%9}, {%0,%1,%2,%3};\n"
        : "+f"(c[0]), "+f"(c[1]), "+f"(c[2]), "+f"(c[3])
        : "r"(a[0]), "r"(a[1]), "r"(a[2]), "r"(a[3]), "r"(b[0]), "r"(b[1]));
}

__device__ __forceinline__ uint32_t ld32h(const __half* p) {
    return *(const uint32_t*)p;
}

__device__ __forceinline__ void cp_async16(uint32_t smem_addr, const void* gptr) {
    asm volatile("cp.async.cg.shared.global [%0], [%1], 16;\n"
                 :: "r"(smem_addr), "l"(gptr));
}
__device__ __forceinline__ void cp_async_commit() {
    asm volatile("cp.async.commit_group;\n" ::: "memory");
}
template <int N>
__device__ __forceinline__ void cp_async_wait() {
    asm volatile("cp.async.wait_group %0;\n" :: "n"(N) : "memory");
}

// ---------------------------------------------------------------------------
// Convert pass: fp32 -> fp16 (RN), 8 elements/thread.
// ---------------------------------------------------------------------------
__global__ void __launch_bounds__(256) round_f16_kernel(
    const float4* __restrict__ in, __half2* __restrict__ out, int n8)
{
    int i = blockIdx.x * 256 + threadIdx.x;
    if (i < n8) {
        float4 a = in[2 * i], b = in[2 * i + 1];
        out[4 * i + 0] = __floats2half2_rn(a.x, a.y);
        out[4 * i + 1] = __floats2half2_rn(a.z, a.w);
        out[4 * i + 2] = __floats2half2_rn(b.x, b.y);
        out[4 * i + 3] = __floats2half2_rn(b.z, b.w);
    }
}

// ===========================================================================
// Fused QKV GEMM + tensor-core attention (fp16 mma m16n8k16).
// Grid (8, 512). Block: 256 threads = 8 warps (4 wm x 2 wn).
// CTA tile: M=256 rows (8 batches), N=64 (2 heads) x 3 matrices.
// Warp tile: WM=64, WN=32 per matrix -> 0.83 LDS/MMA (was 1.33).
// Each warp owns 2 attention problems: (batch wm*2+p, head wn), p=0,1.
// smem: GEMM stages 3 x 64512B = 193536B; attn tiles 8x6x32x40 halves
// = 122880B aliased inside.
// ===========================================================================
#define BK2 64              // halves per k-tile (128B rows)
#define SH 72               // GEMM smem row stride in halves (64 + 8 pad)
#define AH 40               // attention tile stride in halves (32 + 8 pad)
#define F_STAGE_HALVES ((256 + 3 * 64) * SH)          // 32256
#define FUSED_SMEM_BYTES (3 * F_STAGE_HALVES * 2)     // 193536

extern "C" __global__ void __launch_bounds__(256, 1) fused_qkv_attn(
    const __half* __restrict__ X,
    const __half* __restrict__ Wq, const __half* __restrict__ Wk,
    const __half* __restrict__ Wv, __half* __restrict__ Ot)
{
    extern __shared__ __half smem_h[];

    const int tid  = threadIdx.x;
    const int lane = tid & 31;
    const int warp = tid >> 5;
    const int wm   = warp & 3;    // 64-row stripe (2 batches)
    const int wn   = warp >> 2;   // head within CTA
    const int g    = lane >> 2;
    const int t4   = lane & 3;

    const int m0 = blockIdx.y * 256;
    const int n0 = blockIdx.x * 64;

    const uint32_t smem_u = (uint32_t)__cvta_generic_to_shared(smem_h);

    float acc[3][4][4][4];
    #pragma unroll
    for (int m = 0; m < 3; m++)
        #pragma unroll
        for (int mi = 0; mi < 4; mi++)
            #pragma unroll
            for (int ni = 0; ni < 4; ni++)
                #pragma unroll
                for (int r = 0; r < 4; r++) acc[m][mi][ni][r] = 0.f;

    const __half* Wg[3] = {Wq, Wk, Wv};

    // ---- chunk loader: 8 A + 6 B cp.async16 per thread ----
    auto load_chunk = [&](int c) {
        const uint32_t st = smem_u + (uint32_t)((c % 3) * F_STAGE_HALVES) * 2u;
        const int kt = c * BK2;
        #pragma unroll
        for (int j = 0; j < 8; j++) {
            const int idx = tid + 256 * j;          // 0..2047
            const int row = idx >> 3, c16 = idx & 7;
            cp_async16(st + (uint32_t)(row * SH + c16 * 8) * 2u,
                       X + (size_t)(m0 + row) * KDIM + kt + c16 * 8);
        }
        #pragma unroll
        for (int j = 0; j < 6; j++) {
            const int idx = tid + 256 * j;          // 0..1535
            const int m = idx >> 9, row = (idx >> 3) & 63, c16 = idx & 7;
            cp_async16(st + (uint32_t)(256 * SH + m * 64 * SH + row * SH + c16 * 8) * 2u,
                       Wg[m] + (size_t)(n0 + row) * KDIM + kt + c16 * 8);
        }
    };

    const int NT = KDIM / BK2;   // 8

    load_chunk(0); cp_async_commit();
    load_chunk(1); cp_async_commit();

    for (int i = 0; i < NT; i++) {
        cp_async_wait<1>();
        __syncthreads();

        const int lt = i + 2;
        if (lt < NT) load_chunk(lt);
        cp_async_commit();

        const __half* xs = smem_h + (i % 3) * F_STAGE_HALVES;
        const __half* ws = xs + 256 * SH;

        #pragma unroll
        for (int kk = 0; kk < BK2; kk += 16) {
            uint32_t af[4][4];
            #pragma unroll
            for (int mi = 0; mi < 4; mi++) {
                const int r0 = (wm * 64 + mi * 16 + g) * SH + kk + 2 * t4;
                af[mi][0] = ld32h(xs + r0);
                af[mi][1] = ld32h(xs + r0 + 8 * SH);
                af[mi][2] = ld32h(xs + r0 + 8);
                af[mi][3] = ld32h(xs + r0 + 8 * SH + 8);
            }
            #pragma unroll
            for (int m = 0; m < 3; m++) {
                #pragma unroll
                for (int ni = 0; ni < 4; ni++) {
                    uint32_t bf[2];
                    const int rb = m * 64 * SH + (wn * 32 + ni * 8 + g) * SH + kk + 2 * t4;
                    bf[0] = ld32h(ws + rb);
                    bf[1] = ld32h(ws + rb + 8);
                    #pragma unroll
                    for (int mi = 0; mi < 4; mi++)
                        mma_f16(acc[m][mi][ni], af[mi], bf);
                }
            }
        }
    }

    // --- phase switch: GEMM smem reads done; region becomes attn tiles ---
    cp_async_wait<0>();
    __syncthreads();

    // per-warp tiles for 2 problems: [p][Q|K|Vt], stride AH halves
    __half* aw = smem_h + warp * (6 * 32 * AH);

    #pragma unroll
    for (int p = 0; p < 2; p++) {
        __half* Qb = aw + (p * 3 + 0) * (32 * AH);
        __half* Kb = aw + (p * 3 + 1) * (32 * AH);
        __half* Vb = aw + (p * 3 + 2) * (32 * AH);   // V TRANSPOSED: Vt[d][s]
        #pragma unroll
        for (int miL = 0; miL < 2; miL++) {
            const int mi = p * 2 + miL;
            #pragma unroll
            for (int ni = 0; ni < 4; ni++) {
                const int r = miL * 16 + g;
                const int c = ni * 8 + t4 * 2;
                *(__half2*)&Qb[r * AH + c] =
                    __floats2half2_rn(acc[0][mi][ni][0], acc[0][mi][ni][1]);
                *(__half2*)&Qb[(r + 8) * AH + c] =
                    __floats2half2_rn(acc[0][mi][ni][2], acc[0][mi][ni][3]);
                *(__half2*)&Kb[r * AH + c] =
                    __floats2half2_rn(acc[1][mi][ni][0], acc[1][mi][ni][1]);
                *(__half2*)&Kb[(r + 8) * AH + c] =
                    __floats2half2_rn(acc[1][mi][ni][2], acc[1][mi][ni][3]);
                Vb[c * AH + r]           = __float2half_rn(acc[2][mi][ni][0]);
                Vb[(c + 1) * AH + r]     = __float2half_rn(acc[2][mi][ni][1]);
                Vb[c * AH + r + 8]       = __float2half_rn(acc[2][mi][ni][2]);
                Vb[(c + 1) * AH + r + 8] = __float2half_rn(acc[2][mi][ni][3]);
            }
        }
    }
    __syncwarp();

    const float scale = 0.17677669529663689f;  // 32^-0.5

    for (int p = 0; p < 2; p++) {
        __half* Qb = aw + (p * 3 + 0) * (32 * AH);
        __half* Kb = aw + (p * 3 + 1) * (32 * AH);
        __half* Vb = aw + (p * 3 + 2) * (32 * AH);

        // ---- S = Q K^T (m16n8k16 over d=32, 2 steps) ----
        float sacc[2][4][4];
        #pragma unroll
        for (int mi = 0; mi < 2; mi++)
            #pragma unroll
            for (int ni = 0; ni < 4; ni++)
                #pragma unroll
                for (int r = 0; r < 4; r++) sacc[mi][ni][r] = 0.f;

        #pragma unroll
        for (int kk = 0; kk < 32; kk += 16) {
            uint32_t af[2][4];
            #pragma unroll
            for (int mi = 0; mi < 2; mi++) {
                const int r0 = (mi * 16 + g) * AH + kk + 2 * t4;
                af[mi][0] = ld32h(Qb + r0);
                af[mi][1] = ld32h(Qb + r0 + 8 * AH);
                af[mi][2] = ld32h(Qb + r0 + 8);
                af[mi][3] = ld32h(Qb + r0 + 8 * AH + 8);
            }
            #pragma unroll
            for (int ni = 0; ni < 4; ni++) {
                uint32_t bf[2];
                const int rb = (ni * 8 + g) * AH + kk + 2 * t4;
                bf[0] = ld32h(Kb + rb);
                bf[1] = ld32h(Kb + rb + 8);
                #pragma unroll
                for (int mi = 0; mi < 2; mi++)
                    mma_f16(sacc[mi][ni], af[mi], bf);
            }
        }

        // ---- mask + scale + softmax (rows across t4 quad), fp32 ----
        float rmax[2][2] = {{-1e30f, -1e30f}, {-1e30f, -1e30f}};
        #pragma unroll
        for (int mi = 0; mi < 2; mi++)
            #pragma unroll
            for (int ni = 0; ni < 4; ni++)
                #pragma unroll
                for (int j = 0; j < 4; j++) {
                    const int row = mi * 16 + g + (j >> 1) * 8;
                    const int col = ni * 8 + t4 * 2 + (j & 1);
                    float v = (col <= row) ? sacc[mi][ni][j] * scale : -1e30f;
                    sacc[mi][ni][j] = v;
                    rmax[mi][j >> 1] = fmaxf(rmax[mi][j >> 1], v);
                }
        #pragma unroll
        for (int mi = 0; mi < 2; mi++)
            #pragma unroll
            for (int h8 = 0; h8 < 2; h8++) {
                float m = rmax[mi][h8];
                m = fmaxf(m, __shfl_xor_sync(0xffffffffu, m, 1));
                m = fmaxf(m, __shfl_xor_sync(0xffffffffu, m, 2));
                rmax[mi][h8] = m;
            }
        float rsum[2][2] = {{0.f, 0.f}, {0.f, 0.f}};
        #pragma unroll
        for (int mi = 0; mi < 2; mi++)
            #pragma unroll
            for (int ni = 0; ni < 4; ni++)
                #pragma unroll
                for (int j = 0; j < 4; j++) {
                    float e = __expf(sacc[mi][ni][j] - rmax[mi][j >> 1]);
                    sacc[mi][ni][j] = e;
                    rsum[mi][j >> 1] += e;
                }
        float inv[2][2];
        #pragma unroll
        for (int mi = 0; mi < 2; mi++)
            #pragma unroll
            for (int h8 = 0; h8 < 2; h8++) {
                float s = rsum[mi][h8];
                s += __shfl_xor_sync(0xffffffffu, s, 1);
                s += __shfl_xor_sync(0xffffffffu, s, 2);
                inv[mi][h8] = 1.0f / s;
            }

        // ---- unnormalized P (fp16) into Qb (Q dead) ----
        __syncwarp();
        #pragma unroll
        for (int mi = 0; mi < 2; mi++)
            #pragma unroll
            for (int ni = 0; ni < 4; ni++) {
                const int r = mi * 16 + g;
                const int c = ni * 8 + t4 * 2;
                *(__half2*)&Qb[r * AH + c] =
                    __floats2half2_rn(sacc[mi][ni][0], sacc[mi][ni][1]);
                *(__half2*)&Qb[(r + 8) * AH + c] =
                    __floats2half2_rn(sacc[mi][ni][2], sacc[mi][ni][3]);
            }
        __syncwarp();

        // ---- O = P V  (B-frags contiguous from Vt[d][s]) ----
        float oacc[2][4][4];
        #pragma unroll
        for (int mi = 0; mi < 2; mi++)
            #pragma unroll
            for (int ni = 0; ni < 4; ni++)
                #pragma unroll
                for (int r = 0; r < 4; r++) oacc[mi][ni][r] = 0.f;

        #pragma unroll
        for (int kk = 0; kk < 32; kk += 16) {
            uint32_t af[2][4];
            #pragma unroll
            for (int mi = 0; mi < 2; mi++) {
                const int r0 = (mi * 16 + g) * AH + kk + 2 * t4;
                af[mi][0] = ld32h(Qb + r0);
                af[mi][1] = ld32h(Qb + r0 + 8 * AH);
                af[mi][2] = ld32h(Qb + r0 + 8);
                af[mi][3] = ld32h(Qb + r0 + 8 * AH + 8);
            }
            #pragma unroll
            for (int ni = 0; ni < 4; ni++) {
                uint32_t bf[2];
                const int rb = (ni * 8 + g) * AH + kk + 2 * t4;   // row d, k = s
                bf[0] = ld32h(Vb + rb);
                bf[1] = ld32h(Vb + rb + 8);
                #pragma unroll
                for (int mi = 0; mi < 2; mi++)
                    mma_f16(oacc[mi][ni], af[mi], bf);
            }
        }

        // ---- normalize, dump O[t][d] (fp16) to Kb (K dead), store ----
        __syncwarp();
        #pragma unroll
        for (int mi = 0; mi < 2; mi++)
            #pragma unroll
            for (int ni = 0; ni < 4; ni++) {
                const int r = mi * 16 + g;
                const int c = ni * 8 + t4 * 2;
                *(__half2*)&Kb[r * AH + c] =
                    __floats2half2_rn(oacc[mi][ni][0] * inv[mi][0],
                                      oacc[mi][ni][1] * inv[mi][0]);
                *(__half2*)&Kb[(r + 8) * AH + c] =
                    __floats2half2_rn(oacc[mi][ni][2] * inv[mi][1],
                                      oacc[mi][ni][3] * inv[mi][1]);
            }
        __syncwarp();

        const int b = blockIdx.y * 8 + wm * 2 + p;
        const int h = blockIdx.x * 2 + wn;
        #pragma unroll
        for (int d = 0; d < 32; d++)
            Ot[(size_t)(b * 32 + d) * 512 + h * 32 + lane] = Kb[lane * AH + d];
        __syncwarp();
    }
}

// ===========================================================================
// Projection NT GEMM (fp16 mma m16n8k16): out = Ot @ Wp^T + bp (f32 out)
// BM=256, BN=128, BK=32 halves, 256 threads = 8 warps (4 wm x 2 wn),
// warp tile 64x64 -> 1.0 LDS/MMA. 3-stage cp.async.
// ===========================================================================
#define PBK 32
#define SH2 40              // 32 + 8 pad halves (80 B rows)
#define PROJ_STAGE_HALVES ((256 + 128) * SH2)            // 15360
#define PROJ_SMEM_BYTES (3 * PROJ_STAGE_HALVES * 2)      // 92160

__global__ void __launch_bounds__(256, 1) proj_gemm_f16(
    const __half* __restrict__ A, const __half* __restrict__ Bw,
    float* __restrict__ C, const float* __restrict__ bias)
{
    extern __shared__ __half smem_h[];

    const int tid  = threadIdx.x;
    const int lane = tid & 31;
    const int warp = tid >> 5;
    const int wm   = warp & 3;    // 64-row stripe
    const int wn   = warp >> 2;   // 64-col stripe
    const int g    = lane >> 2;
    const int t4   = lane & 3;

    const int m0 = blockIdx.y * 256;
    const int n0 = blockIdx.x * 128;

    const uint32_t smem_u = (uint32_t)__cvta_generic_to_shared(smem_h);

    float acc[4][8][4];
    #pragma unroll
    for (int mi = 0; mi < 4; mi++)
        #pragma unroll
        for (int ni = 0; ni < 8; ni++)
            #pragma unroll
            for (int r = 0; r < 4; r++) acc[mi][ni][r] = 0.f;

    // loader: A 256 rows x 4 chunks = 1024 (4/thread); B 128 x 4 = 512 (2/thread)
    auto load_chunk = [&](int s, int kt) {
        const uint32_t base = smem_u + (uint32_t)(s * PROJ_STAGE_HALVES) * 2u;
        #pragma unroll
        for (int j = 0; j < 4; j++) {
            const int idx = tid + 256 * j;        // 0..1023
            const int row = idx >> 2, c16 = idx & 3;
            cp_async16(base + (uint32_t)(row * SH2 + c16 * 8) * 2u,
                       A + (size_t)(m0 + row) * KDIM + kt + c16 * 8);
        }
        #pragma unroll
        for (int j = 0; j < 2; j++) {
            const int idx = tid + 256 * j;        // 0..511
            const int row = idx >> 2, c16 = idx & 3;
            cp_async16(base + (uint32_t)(256 * SH2 + row * SH2 + c16 * 8) * 2u,
                       Bw + (size_t)(n0 + row) * KDIM + kt + c16 * 8);
        }
    };

    const int NT = KDIM / PBK;   // 16

    load_chunk(0, 0);   cp_async_commit();
    load_chunk(1, PBK); cp_async_commit();

    for (int i = 0; i < NT; i++) {
        cp_async_wait<1>();
        __syncthreads();

        const int lt = i + 2;
        if (lt < NT) load_chunk(lt % 3, lt * PBK);
        cp_async_commit();

        const __half* As = smem_h + (i % 3) * PROJ_STAGE_HALVES;
        const __half* Bs = As + 256 * SH2;

        #pragma unroll
        for (int kk = 0; kk < PBK; kk += 16) {
            uint32_t af[4][4];
            #pragma unroll
            for (int mi = 0; mi < 4; mi++) {
                const int r0 = (wm * 64 + mi * 16 + g) * SH2 + kk + 2 * t4;
                af[mi][0] = ld32h(As + r0);
                af[mi][1] = ld32h(As + r0 + 8 * SH2);
                af[mi][2] = ld32h(As + r0 + 8);
                af[mi][3] = ld32h(As + r0 + 8 * SH2 + 8);
            }
            uint32_t bf[8][2];
            #pragma unroll
            for (int ni = 0; ni < 8; ni++) {
                const int rb = (wn * 64 + ni * 8 + g) * SH2 + kk + 2 * t4;
                bf[ni][0] = ld32h(Bs + rb);
                bf[ni][1] = ld32h(Bs + rb + 8);
            }
            #pragma unroll
            for (int mi = 0; mi < 4; mi++)
                #pragma unroll
                for (int ni = 0; ni < 8; ni++)
                    mma_f16(acc[mi][ni], af[mi], bf[ni]);
        }
    }

    #pragma unroll
    for (int mi = 0; mi < 4; mi++) {
        #pragma unroll
        for (int ni = 0; ni < 8; ni++) {
            const int m = m0 + wm * 64 + mi * 16 + g;
            const int n = n0 + wn * 64 + ni * 8 + t4 * 2;
            const float bv0 = bias[n];
            const float bv1 = bias[n + 1];
            float2 v01 = make_float2(acc[mi][ni][0] + bv0, acc[mi][ni][1] + bv1);
            float2 v23 = make_float2(acc[mi][ni][2] + bv0, acc[mi][ni][3] + bv1);
            *(float2*)(&C[(size_t)m * NDIM + n])       = v01;
            *(float2*)(&C[(size_t)(m + 8) * NDIM + n]) = v23;
        }
    }
}

// ---------------------------------------------------------------------------
// Launch
// ---------------------------------------------------------------------------
extern "C" void kernel_launch(void* const* d_in, const int* in_sizes, int n_in,
                              void* d_out, int out_size) {
    const float* x  = (const float*)d_in[0];
    const float* Wq = (const float*)d_in[1];
    const float* Wk = (const float*)d_in[2];
    const float* Wv = (const float*)d_in[3];
    const float* Wp = (const float*)d_in[4];
    const float* bp = (const float*)d_in[5];
    float* out = (float*)d_out;

    __half *gx, *go, *gwq, *gwk, *gwv, *gwp;
    cudaGetSymbolAddress((void**)&gx,  g_Xh);
    cudaGetSymbolAddress((void**)&go,  g_Oth);
    cudaGetSymbolAddress((void**)&gwq, g_Wqh);
    cudaGetSymbolAddress((void**)&gwk, g_Wkh);
    cudaGetSymbolAddress((void**)&gwv, g_Wvh);
    cudaGetSymbolAddress((void**)&gwp, g_Wph);

    static bool attr_set = false;
    if (!attr_set) {
        cudaFuncSetAttribute(fused_qkv_attn,
                             cudaFuncAttributeMaxDynamicSharedMemorySize,
                             FUSED_SMEM_BYTES);
        cudaFuncSetAttribute(proj_gemm_f16,
                             cudaFuncAttributeMaxDynamicSharedMemorySize,
                             PROJ_SMEM_BYTES);
        attr_set = true;
    }

    // convert inputs to fp16 once
    const int xn8 = (MDIM * KDIM) / 8;   // 8388608
    const int wn8 = (NDIM * KDIM) / 8;   // 32768
    round_f16_kernel<<<xn8 / 256, 256>>>((const float4*)x,  (__half2*)gx,  xn8);
    round_f16_kernel<<<wn8 / 256, 256>>>((const float4*)Wq, (__half2*)gwq, wn8);
    round_f16_kernel<<<wn8 / 256, 256>>>((const float4*)Wk, (__half2*)gwk, wn8);
    round_f16_kernel<<<wn8 / 256, 256>>>((const float4*)Wv, (__half2*)gwv, wn8);
    round_f16_kernel<<<wn8 / 256, 256>>>((const float4*)Wp, (__half2*)gwp, wn8);

    dim3 fgrid(NDIM / 64, MDIM / 256);   // (8, 512)
    fused_qkv_attn<<<fgrid, 256, FUSED_SMEM_BYTES>>>(gx, gwq, gwk, gwv, go);

    dim3 pgrid(NDIM / 128, MDIM / 256);  // (4, 512)
    proj_gemm_f16<<<pgrid, 256, PROJ_SMEM_BYTES>>>(go, gwp, out, bp);
}

// round 16
// speedup vs baseline: 3.3534x; 1.0631x over previous
#include <cuda_runtime.h>
#include <cuda_fp16.h>
#include <cstdint>
#include <cstddef>

// Problem dims (fixed): B=4096, T=32, H=16, HS=32, E=512
#define MDIM 131072
#define NDIM 512
#define KDIM 512

// Scratch: fp16-rounded inputs + attention output (proj-ready layout, fp16).
__device__ __half g_Xh[(size_t)MDIM * KDIM];
__device__ __half g_Oth[(size_t)MDIM * NDIM];
__device__ __half g_Wqh[NDIM * KDIM];
__device__ __half g_Wkh[NDIM * KDIM];
__device__ __half g_Wvh[NDIM * KDIM];
__device__ __half g_Wph[NDIM * KDIM];

// ---------------------------------------------------------------------------
// helpers
// ---------------------------------------------------------------------------
__device__ __forceinline__ void mma_f16(float c[4], const uint32_t a[4], const uint32_t b[2]) {
    asm volatile(
        "mma.sync.aligned.m16n8k16.row.col.f32.f16.f16.f32 "
        "{%0,%1,%2,%3}, {%4,%5,%6,%7}, {%8,%9}, {%0,%1,%2,%3};\n"
        : "+f"(c[0]), "+f"(c[1]), "+f"(c[2]), "+f"(c[3])
        : "r"(a[0]), "r"(a[1]), "r"(a[2]), "r"(a[3]), "r"(b[0]), "r"(b[1]));
}

// ldmatrix x4: loads 4 8x8 b16 matrices; lane l supplies row address of
// matrix (l/8), row (l%8). Register r_j gets matrix j's fragment with the
// standard (row=l/4, col=2*(l%4)) per-lane layout.
__device__ __forceinline__ void ldsm_x4(uint32_t& r0, uint32_t& r1,
                                        uint32_t& r2, uint32_t& r3, uint32_t addr) {
    asm volatile("ldmatrix.sync.aligned.m8n8.x4.shared.b16 {%0,%1,%2,%3}, [%4];"
                 : "=r"(r0), "=r"(r1), "=r"(r2), "=r"(r3) : "r"(addr));
}

__device__ __forceinline__ void cp_async16(uint32_t smem_addr, const void* gptr) {
    asm volatile("cp.async.cg.shared.global [%0], [%1], 16;\n"
                 :: "r"(smem_addr), "l"(gptr));
}
__device__ __forceinline__ void cp_async_commit() {
    asm volatile("cp.async.commit_group;\n" ::: "memory");
}
template <int N>
__device__ __forceinline__ void cp_async_wait() {
    asm volatile("cp.async.wait_group %0;\n" :: "n"(N) : "memory");
}

// ---------------------------------------------------------------------------
// Convert passes: fp32 -> fp16 (RN), 8 elements/thread.
// ---------------------------------------------------------------------------
__global__ void __launch_bounds__(256) round_f16_kernel(
    const float4* __restrict__ in, __half2* __restrict__ out, int n8)
{
    int i = blockIdx.x * 256 + threadIdx.x;
    if (i < n8) {
        float4 a = in[2 * i], b = in[2 * i + 1];
        out[4 * i + 0] = __floats2half2_rn(a.x, a.y);
        out[4 * i + 1] = __floats2half2_rn(a.z, a.w);
        out[4 * i + 2] = __floats2half2_rn(b.x, b.y);
        out[4 * i + 3] = __floats2half2_rn(b.z, b.w);
    }
}

// merged 4-weight convert: blockIdx.y selects which weight matrix
__global__ void __launch_bounds__(256) round_f16_w4_kernel(
    const float4* __restrict__ wq, const float4* __restrict__ wk,
    const float4* __restrict__ wv, const float4* __restrict__ wp,
    __half2* __restrict__ oq, __half2* __restrict__ ok,
    __half2* __restrict__ ov, __half2* __restrict__ op, int n8)
{
    const float4* in;
    __half2* out;
    switch (blockIdx.y) {
        case 0: in = wq; out = oq; break;
        case 1: in = wk; out = ok; break;
        case 2: in = wv; out = ov; break;
        default: in = wp; out = op; break;
    }
    int i = blockIdx.x * 256 + threadIdx.x;
    if (i < n8) {
        float4 a = in[2 * i], b = in[2 * i + 1];
        out[4 * i + 0] = __floats2half2_rn(a.x, a.y);
        out[4 * i + 1] = __floats2half2_rn(a.z, a.w);
        out[4 * i + 2] = __floats2half2_rn(b.x, b.y);
        out[4 * i + 3] = __floats2half2_rn(b.z, b.w);
    }
}

// ===========================================================================
// Fused QKV GEMM + tensor-core attention (fp16 mma m16n8k16, ldmatrix frags).
// Grid (8, 512). Block: 256 threads = 8 warps (4 wm x 2 wn).
// CTA tile: M=256 (8 batches), N=64 (2 heads) x 3 matrices.
// Warp tile: WM=64, WN=32. Each warp owns 2 attention problems.
// ===========================================================================
#define BK2 64              // halves per k-tile (128B rows)
#define SH 72               // GEMM smem row stride in halves (64 + 8 pad)
#define AH 40               // attention tile stride in halves (32 + 8 pad)
#define F_STAGE_HALVES ((256 + 3 * 64) * SH)          // 32256
#define FUSED_SMEM_BYTES (3 * F_STAGE_HALVES * 2)     // 193536

extern "C" __global__ void __launch_bounds__(256, 1) fused_qkv_attn(
    const __half* __restrict__ X,
    const __half* __restrict__ Wq, const __half* __restrict__ Wk,
    const __half* __restrict__ Wv, __half* __restrict__ Ot)
{
    extern __shared__ __half smem_h[];

    const int tid  = threadIdx.x;
    const int lane = tid & 31;
    const int warp = tid >> 5;
    const int wm   = warp & 3;    // 64-row stripe (2 batches)
    const int wn   = warp >> 2;   // head within CTA
    const int g    = lane >> 2;
    const int t4   = lane & 3;

    const int m0 = blockIdx.y * 256;
    const int n0 = blockIdx.x * 64;

    const uint32_t smem_u = (uint32_t)__cvta_generic_to_shared(smem_h);

    // ldmatrix per-lane address components
    const int arow_l = lane & 15;                 // A: row offset within 16
    const int acol_l = (lane >> 4) << 3;          // A: k-half select (0/8)
    const int brow_l = (lane & 7) + ((lane >> 4) << 3);   // B: row within 16
    const int bcol_l = ((lane >> 3) & 1) << 3;            // B: k-half select

    float acc[3][4][4][4];
    #pragma unroll
    for (int m = 0; m < 3; m++)
        #pragma unroll
        for (int mi = 0; mi < 4; mi++)
            #pragma unroll
            for (int ni = 0; ni < 4; ni++)
                #pragma unroll
                for (int r = 0; r < 4; r++) acc[m][mi][ni][r] = 0.f;

    const __half* Wg[3] = {Wq, Wk, Wv};

    auto load_chunk = [&](int c) {
        const uint32_t st = smem_u + (uint32_t)((c % 3) * F_STAGE_HALVES) * 2u;
        const int kt = c * BK2;
        #pragma unroll
        for (int j = 0; j < 8; j++) {
            const int idx = tid + 256 * j;
            const int row = idx >> 3, c16 = idx & 7;
            cp_async16(st + (uint32_t)(row * SH + c16 * 8) * 2u,
                       X + (size_t)(m0 + row) * KDIM + kt + c16 * 8);
        }
        #pragma unroll
        for (int j = 0; j < 6; j++) {
            const int idx = tid + 256 * j;
            const int m = idx >> 9, row = (idx >> 3) & 63, c16 = idx & 7;
            cp_async16(st + (uint32_t)(256 * SH + m * 64 * SH + row * SH + c16 * 8) * 2u,
                       Wg[m] + (size_t)(n0 + row) * KDIM + kt + c16 * 8);
        }
    };

    const int NT = KDIM / BK2;   // 8

    load_chunk(0); cp_async_commit();
    load_chunk(1); cp_async_commit();

    for (int i = 0; i < NT; i++) {
        cp_async_wait<1>();
        __syncthreads();

        const int lt = i + 2;
        if (lt < NT) load_chunk(lt);
        cp_async_commit();

        const uint32_t stg = smem_u + (uint32_t)((i % 3) * F_STAGE_HALVES) * 2u;

        #pragma unroll
        for (int kk = 0; kk < BK2; kk += 16) {
            uint32_t af[4][4];
            #pragma unroll
            for (int mi = 0; mi < 4; mi++) {
                const uint32_t a_addr = stg +
                    (uint32_t)((wm * 64 + mi * 16 + arow_l) * SH + kk + acol_l) * 2u;
                ldsm_x4(af[mi][0], af[mi][1], af[mi][2], af[mi][3], a_addr);
            }
            uint32_t bf[3][4][2];
            #pragma unroll
            for (int m = 0; m < 3; m++) {
                #pragma unroll
                for (int np = 0; np < 2; np++) {   // ni pairs (0,1) and (2,3)
                    const uint32_t b_addr = stg +
                        (uint32_t)(256 * SH + m * 64 * SH +
                                   (wn * 32 + np * 16 + brow_l) * SH + kk + bcol_l) * 2u;
                    ldsm_x4(bf[m][2 * np][0], bf[m][2 * np][1],
                            bf[m][2 * np + 1][0], bf[m][2 * np + 1][1], b_addr);
                }
            }
            #pragma unroll
            for (int m = 0; m < 3; m++)
                #pragma unroll
                for (int ni = 0; ni < 4; ni++)
                    #pragma unroll
                    for (int mi = 0; mi < 4; mi++)
                        mma_f16(acc[m][mi][ni], af[mi], bf[m][ni]);
        }
    }

    // --- phase switch ---
    cp_async_wait<0>();
    __syncthreads();

    __half* aw = smem_h + warp * (6 * 32 * AH);
    const uint32_t aw_u = smem_u + (uint32_t)(warp * (6 * 32 * AH)) * 2u;

    #pragma unroll
    for (int p = 0; p < 2; p++) {
        __half* Qb = aw + (p * 3 + 0) * (32 * AH);
        __half* Kb = aw + (p * 3 + 1) * (32 * AH);
        __half* Vb = aw + (p * 3 + 2) * (32 * AH);   // V TRANSPOSED: Vt[d][s]
        #pragma unroll
        for (int miL = 0; miL < 2; miL++) {
            const int mi = p * 2 + miL;
            #pragma unroll
            for (int ni = 0; ni < 4; ni++) {
                const int r = miL * 16 + g;
                const int c = ni * 8 + t4 * 2;
                *(__half2*)&Qb[r * AH + c] =
                    __floats2half2_rn(acc[0][mi][ni][0], acc[0][mi][ni][1]);
                *(__half2*)&Qb[(r + 8) * AH + c] =
                    __floats2half2_rn(acc[0][mi][ni][2], acc[0][mi][ni][3]);
                *(__half2*)&Kb[r * AH + c] =
                    __floats2half2_rn(acc[1][mi][ni][0], acc[1][mi][ni][1]);
                *(__half2*)&Kb[(r + 8) * AH + c] =
                    __floats2half2_rn(acc[1][mi][ni][2], acc[1][mi][ni][3]);
                Vb[c * AH + r]           = __float2half_rn(acc[2][mi][ni][0]);
                Vb[(c + 1) * AH + r]     = __float2half_rn(acc[2][mi][ni][1]);
                Vb[c * AH + r + 8]       = __float2half_rn(acc[2][mi][ni][2]);
                Vb[(c + 1) * AH + r + 8] = __float2half_rn(acc[2][mi][ni][3]);
            }
        }
    }
    __syncwarp();

    const float scale = 0.17677669529663689f;  // 32^-0.5

    for (int p = 0; p < 2; p++) {
        __half* Qb = aw + (p * 3 + 0) * (32 * AH);
        __half* Kb = aw + (p * 3 + 1) * (32 * AH);
        const uint32_t Qb_u = aw_u + (uint32_t)((p * 3 + 0) * (32 * AH)) * 2u;
        const uint32_t Kb_u = aw_u + (uint32_t)((p * 3 + 1) * (32 * AH)) * 2u;
        const uint32_t Vb_u = aw_u + (uint32_t)((p * 3 + 2) * (32 * AH)) * 2u;

        // ---- S = Q K^T ----
        float sacc[2][4][4];
        #pragma unroll
        for (int mi = 0; mi < 2; mi++)
            #pragma unroll
            for (int ni = 0; ni < 4; ni++)
                #pragma unroll
                for (int r = 0; r < 4; r++) sacc[mi][ni][r] = 0.f;

        #pragma unroll
        for (int kk = 0; kk < 32; kk += 16) {
            uint32_t af[2][4];
            #pragma unroll
            for (int mi = 0; mi < 2; mi++)
                ldsm_x4(af[mi][0], af[mi][1], af[mi][2], af[mi][3],
                        Qb_u + (uint32_t)((mi * 16 + arow_l) * AH + kk + acol_l) * 2u);
            uint32_t bf[4][2];
            #pragma unroll
            for (int np = 0; np < 2; np++)
                ldsm_x4(bf[2 * np][0], bf[2 * np][1], bf[2 * np + 1][0], bf[2 * np + 1][1],
                        Kb_u + (uint32_t)((np * 16 + brow_l) * AH + kk + bcol_l) * 2u);
            #pragma unroll
            for (int ni = 0; ni < 4; ni++)
                #pragma unroll
                for (int mi = 0; mi < 2; mi++)
                    mma_f16(sacc[mi][ni], af[mi], bf[ni]);
        }

        // ---- mask + scale + softmax ----
        float rmax[2][2] = {{-1e30f, -1e30f}, {-1e30f, -1e30f}};
        #pragma unroll
        for (int mi = 0; mi < 2; mi++)
            #pragma unroll
            for (int ni = 0; ni < 4; ni++)
                #pragma unroll
                for (int j = 0; j < 4; j++) {
                    const int row = mi * 16 + g + (j >> 1) * 8;
                    const int col = ni * 8 + t4 * 2 + (j & 1);
                    float v = (col <= row) ? sacc[mi][ni][j] * scale : -1e30f;
                    sacc[mi][ni][j] = v;
                    rmax[mi][j >> 1] = fmaxf(rmax[mi][j >> 1], v);
                }
        #pragma unroll
        for (int mi = 0; mi < 2; mi++)
            #pragma unroll
            for (int h8 = 0; h8 < 2; h8++) {
                float m = rmax[mi][h8];
                m = fmaxf(m, __shfl_xor_sync(0xffffffffu, m, 1));
                m = fmaxf(m, __shfl_xor_sync(0xffffffffu, m, 2));
                rmax[mi][h8] = m;
            }
        float rsum[2][2] = {{0.f, 0.f}, {0.f, 0.f}};
        #pragma unroll
        for (int mi = 0; mi < 2; mi++)
            #pragma unroll
            for (int ni = 0; ni < 4; ni++)
                #pragma unroll
                for (int j = 0; j < 4; j++) {
                    float e = __expf(sacc[mi][ni][j] - rmax[mi][j >> 1]);
                    sacc[mi][ni][j] = e;
                    rsum[mi][j >> 1] += e;
                }
        float inv[2][2];
        #pragma unroll
        for (int mi = 0; mi < 2; mi++)
            #pragma unroll
            for (int h8 = 0; h8 < 2; h8++) {
                float s = rsum[mi][h8];
                s += __shfl_xor_sync(0xffffffffu, s, 1);
                s += __shfl_xor_sync(0xffffffffu, s, 2);
                inv[mi][h8] = 1.0f / s;
            }

        // ---- unnormalized P (fp16) into Qb ----
        __syncwarp();
        #pragma unroll
        for (int mi = 0; mi < 2; mi++)
            #pragma unroll
            for (int ni = 0; ni < 4; ni++) {
                const int r = mi * 16 + g;
                const int c = ni * 8 + t4 * 2;
                *(__half2*)&Qb[r * AH + c] =
                    __floats2half2_rn(sacc[mi][ni][0], sacc[mi][ni][1]);
                *(__half2*)&Qb[(r + 8) * AH + c] =
                    __floats2half2_rn(sacc[mi][ni][2], sacc[mi][ni][3]);
            }
        __syncwarp();

        // ---- O = P V ----
        float oacc[2][4][4];
        #pragma unroll
        for (int mi = 0; mi < 2; mi++)
            #pragma unroll
            for (int ni = 0; ni < 4; ni++)
                #pragma unroll
                for (int r = 0; r < 4; r++) oacc[mi][ni][r] = 0.f;

        #pragma unroll
        for (int kk = 0; kk < 32; kk += 16) {
            uint32_t af[2][4];
            #pragma unroll
            for (int mi = 0; mi < 2; mi++)
                ldsm_x4(af[mi][0], af[mi][1], af[mi][2], af[mi][3],
                        Qb_u + (uint32_t)((mi * 16 + arow_l) * AH + kk + acol_l) * 2u);
            uint32_t bf[4][2];
            #pragma unroll
            for (int np = 0; np < 2; np++)
                ldsm_x4(bf[2 * np][0], bf[2 * np][1], bf[2 * np + 1][0], bf[2 * np + 1][1],
                        Vb_u + (uint32_t)((np * 16 + brow_l) * AH + kk + bcol_l) * 2u);
            #pragma unroll
            for (int ni = 0; ni < 4; ni++)
                #pragma unroll
                for (int mi = 0; mi < 2; mi++)
                    mma_f16(oacc[mi][ni], af[mi], bf[ni]);
        }

        // ---- normalize, dump O[t][d] to Kb, store ----
        __syncwarp();
        #pragma unroll
        for (int mi = 0; mi < 2; mi++)
            #pragma unroll
            for (int ni = 0; ni < 4; ni++) {
                const int r = mi * 16 + g;
                const int c = ni * 8 + t4 * 2;
                *(__half2*)&Kb[r * AH + c] =
                    __floats2half2_rn(oacc[mi][ni][0] * inv[mi][0],
                                      oacc[mi][ni][1] * inv[mi][0]);
                *(__half2*)&Kb[(r + 8) * AH + c] =
                    __floats2half2_rn(oacc[mi][ni][2] * inv[mi][1],
                                      oacc[mi][ni][3] * inv[mi][1]);
            }
        __syncwarp();

        const int b = blockIdx.y * 8 + wm * 2 + p;
        const int h = blockIdx.x * 2 + wn;
        #pragma unroll
        for (int d = 0; d < 32; d++)
            Ot[(size_t)(b * 32 + d) * 512 + h * 32 + lane] = Kb[lane * AH + d];
        __syncwarp();
    }
}

// ===========================================================================
// Projection NT GEMM (fp16 mma m16n8k16, ldmatrix frags)
// BM=256, BN=128, BK=32 halves, 256 threads, warp tile 64x64.
// ===========================================================================
#define PBK 32
#define SH2 40
#define PROJ_STAGE_HALVES ((256 + 128) * SH2)            // 15360
#define PROJ_SMEM_BYTES (3 * PROJ_STAGE_HALVES * 2)      // 92160

__global__ void __launch_bounds__(256, 1) proj_gemm_f16(
    const __half* __restrict__ A, const __half* __restrict__ Bw,
    float* __restrict__ C, const float* __restrict__ bias)
{
    extern __shared__ __half smem_h[];

    const int tid  = threadIdx.x;
    const int lane = tid & 31;
    const int warp = tid >> 5;
    const int wm   = warp & 3;
    const int wn   = warp >> 2;
    const int g    = lane >> 2;
    const int t4   = lane & 3;

    const int m0 = blockIdx.y * 256;
    const int n0 = blockIdx.x * 128;

    const uint32_t smem_u = (uint32_t)__cvta_generic_to_shared(smem_h);

    const int arow_l = lane & 15;
    const int acol_l = (lane >> 4) << 3;
    const int brow_l = (lane & 7) + ((lane >> 4) << 3);
    const int bcol_l = ((lane >> 3) & 1) << 3;

    float acc[4][8][4];
    #pragma unroll
    for (int mi = 0; mi < 4; mi++)
        #pragma unroll
        for (int ni = 0; ni < 8; ni++)
            #pragma unroll
            for (int r = 0; r < 4; r++) acc[mi][ni][r] = 0.f;

    auto load_chunk = [&](int s, int kt) {
        const uint32_t base = smem_u + (uint32_t)(s * PROJ_STAGE_HALVES) * 2u;
        #pragma unroll
        for (int j = 0; j < 4; j++) {
            const int idx = tid + 256 * j;
            const int row = idx >> 2, c16 = idx & 3;
            cp_async16(base + (uint32_t)(row * SH2 + c16 * 8) * 2u,
                       A + (size_t)(m0 + row) * KDIM + kt + c16 * 8);
        }
        #pragma unroll
        for (int j = 0; j < 2; j++) {
            const int idx = tid + 256 * j;
            const int row = idx >> 2, c16 = idx & 3;
            cp_async16(base + (uint32_t)(256 * SH2 + row * SH2 + c16 * 8) * 2u,
                       Bw + (size_t)(n0 + row) * KDIM + kt + c16 * 8);
        }
    };

    const int NT = KDIM / PBK;   // 16

    load_chunk(0, 0);   cp_async_commit();
    load_chunk(1, PBK); cp_async_commit();

    for (int i = 0; i < NT; i++) {
        cp_async_wait<1>();
        __syncthreads();

        const int lt = i + 2;
        if (lt < NT) load_chunk(lt % 3, lt * PBK);
        cp_async_commit();

        const uint32_t stg = smem_u + (uint32_t)((i % 3) * PROJ_STAGE_HALVES) * 2u;

        #pragma unroll
        for (int kk = 0; kk < PBK; kk += 16) {
            uint32_t af[4][4];
            #pragma unroll
            for (int mi = 0; mi < 4; mi++)
                ldsm_x4(af[mi][0], af[mi][1], af[mi][2], af[mi][3],
                        stg + (uint32_t)((wm * 64 + mi * 16 + arow_l) * SH2 + kk + acol_l) * 2u);
            uint32_t bf[8][2];
            #pragma unroll
            for (int np = 0; np < 4; np++)
                ldsm_x4(bf[2 * np][0], bf[2 * np][1], bf[2 * np + 1][0], bf[2 * np + 1][1],
                        stg + (uint32_t)(256 * SH2 + (wn * 64 + np * 16 + brow_l) * SH2 + kk + bcol_l) * 2u);
            #pragma unroll
            for (int mi = 0; mi < 4; mi++)
                #pragma unroll
                for (int ni = 0; ni < 8; ni++)
                    mma_f16(acc[mi][ni], af[mi], bf[ni]);
        }
    }

    #pragma unroll
    for (int mi = 0; mi < 4; mi++) {
        #pragma unroll
        for (int ni = 0; ni < 8; ni++) {
            const int m = m0 + wm * 64 + mi * 16 + g;
            const int n = n0 + wn * 64 + ni * 8 + t4 * 2;
            const float bv0 = bias[n];
            const float bv1 = bias[n + 1];
            float2 v01 = make_float2(acc[mi][ni][0] + bv0, acc[mi][ni][1] + bv1);
            float2 v23 = make_float2(acc[mi][ni][2] + bv0, acc[mi][ni][3] + bv1);
            *(float2*)(&C[(size_t)m * NDIM + n])       = v01;
            *(float2*)(&C[(size_t)(m + 8) * NDIM + n]) = v23;
        }
    }
}

// ---------------------------------------------------------------------------
// Launch
// ---------------------------------------------------------------------------
extern "C" void kernel_launch(void* const* d_in, const int* in_sizes, int n_in,
                              void* d_out, int out_size) {
    const float* x  = (const float*)d_in[0];
    const float* Wq = (const float*)d_in[1];
    const float* Wk = (const float*)d_in[2];
    const float* Wv = (const float*)d_in[3];
    const float* Wp = (const float*)d_in[4];
    const float* bp = (const float*)d_in[5];
    float* out = (float*)d_out;

    __half *gx, *go, *gwq, *gwk, *gwv, *gwp;
    cudaGetSymbolAddress((void**)&gx,  g_Xh);
    cudaGetSymbolAddress((void**)&go,  g_Oth);
    cudaGetSymbolAddress((void**)&gwq, g_Wqh);
    cudaGetSymbolAddress((void**)&gwk, g_Wkh);
    cudaGetSymbolAddress((void**)&gwv, g_Wvh);
    cudaGetSymbolAddress((void**)&gwp, g_Wph);

    static bool attr_set = false;
    if (!attr_set) {
        cudaFuncSetAttribute(fused_qkv_attn,
                             cudaFuncAttributeMaxDynamicSharedMemorySize,
                             FUSED_SMEM_BYTES);
        cudaFuncSetAttribute(proj_gemm_f16,
                             cudaFuncAttributeMaxDynamicSharedMemorySize,
                             PROJ_SMEM_BYTES);
        attr_set = true;
    }

    // convert inputs to fp16 once (2 launches)
    const int xn8 = (MDIM * KDIM) / 8;   // 8388608
    const int wn8 = (NDIM * KDIM) / 8;   // 32768
    round_f16_kernel<<<xn8 / 256, 256>>>((const float4*)x, (__half2*)gx, xn8);
    dim3 wgrid(wn8 / 256, 4);
    round_f16_w4_kernel<<<wgrid, 256>>>(
        (const float4*)Wq, (const float4*)Wk, (const float4*)Wv, (const float4*)Wp,
        (__half2*)gwq, (__half2*)gwk, (__half2*)gwv, (__half2*)gwp, wn8);

    dim3 fgrid(NDIM / 64, MDIM / 256);   // (8, 512)
    fused_qkv_attn<<<fgrid, 256, FUSED_SMEM_BYTES>>>(gx, gwq, gwk, gwv, go);

    dim3 pgrid(NDIM / 128, MDIM / 256);  // (4, 512)
    proj_gemm_f16<<<pgrid, 256, PROJ_SMEM_BYTES>>>(go, gwp, out, bp);
}

// round 17
// speedup vs baseline: 3.5411x; 1.0560x over previous
#include <cuda_runtime.h>
#include <cuda_fp16.h>
#include <cstdint>
#include <cstddef>

// Problem dims (fixed): B=4096, T=32, H=16, HS=32, E=512
#define MDIM 131072
#define NDIM 512
#define KDIM 512

// Scratch: fp16-rounded inputs + attention output (proj-ready layout, fp16).
__device__ __half g_Xh[(size_t)MDIM * KDIM];
__device__ __half g_Oth[(size_t)MDIM * NDIM];
__device__ __half g_Wqh[NDIM * KDIM];
__device__ __half g_Wkh[NDIM * KDIM];
__device__ __half g_Wvh[NDIM * KDIM];
__device__ __half g_Wph[NDIM * KDIM];

// ---------------------------------------------------------------------------
// helpers
// ---------------------------------------------------------------------------
__device__ __forceinline__ void mma_f16(float c[4], const uint32_t a[4], const uint32_t b[2]) {
    asm volatile(
        "mma.sync.aligned.m16n8k16.row.col.f32.f16.f16.f32 "
        "{%0,%1,%2,%3}, {%4,%5,%6,%7}, {%8,%9}, {%0,%1,%2,%3};\n"
        : "+f"(c[0]), "+f"(c[1]), "+f"(c[2]), "+f"(c[3])
        : "r"(a[0]), "r"(a[1]), "r"(a[2]), "r"(a[3]), "r"(b[0]), "r"(b[1]));
}

__device__ __forceinline__ void ldsm_x4(uint32_t& r0, uint32_t& r1,
                                        uint32_t& r2, uint32_t& r3, uint32_t addr) {
    asm volatile("ldmatrix.sync.aligned.m8n8.x4.shared.b16 {%0,%1,%2,%3}, [%4];"
                 : "=r"(r0), "=r"(r1), "=r"(r2), "=r"(r3) : "r"(addr));
}

__device__ __forceinline__ void cp_async16(uint32_t smem_addr, const void* gptr) {
    asm volatile("cp.async.cg.shared.global [%0], [%1], 16;\n"
                 :: "r"(smem_addr), "l"(gptr));
}
__device__ __forceinline__ void cp_async_commit() {
    asm volatile("cp.async.commit_group;\n" ::: "memory");
}
template <int N>
__device__ __forceinline__ void cp_async_wait() {
    asm volatile("cp.async.wait_group %0;\n" :: "n"(N) : "memory");
}

// ---------------------------------------------------------------------------
// Convert passes: fp32 -> fp16 (RN), 8 elements/thread.
// ---------------------------------------------------------------------------
__global__ void __launch_bounds__(256) round_f16_kernel(
    const float4* __restrict__ in, __half2* __restrict__ out, int n8)
{
    int i = blockIdx.x * 256 + threadIdx.x;
    if (i < n8) {
        float4 a = in[2 * i], b = in[2 * i + 1];
        out[4 * i + 0] = __floats2half2_rn(a.x, a.y);
        out[4 * i + 1] = __floats2half2_rn(a.z, a.w);
        out[4 * i + 2] = __floats2half2_rn(b.x, b.y);
        out[4 * i + 3] = __floats2half2_rn(b.z, b.w);
    }
}

__global__ void __launch_bounds__(256) round_f16_w4_kernel(
    const float4* __restrict__ wq, const float4* __restrict__ wk,
    const float4* __restrict__ wv, const float4* __restrict__ wp,
    __half2* __restrict__ oq, __half2* __restrict__ ok,
    __half2* __restrict__ ov, __half2* __restrict__ op, int n8)
{
    const float4* in;
    __half2* out;
    switch (blockIdx.y) {
        case 0: in = wq; out = oq; break;
        case 1: in = wk; out = ok; break;
        case 2: in = wv; out = ov; break;
        default: in = wp; out = op; break;
    }
    int i = blockIdx.x * 256 + threadIdx.x;
    if (i < n8) {
        float4 a = in[2 * i], b = in[2 * i + 1];
        out[4 * i + 0] = __floats2half2_rn(a.x, a.y);
        out[4 * i + 1] = __floats2half2_rn(a.z, a.w);
        out[4 * i + 2] = __floats2half2_rn(b.x, b.y);
        out[4 * i + 3] = __floats2half2_rn(b.z, b.w);
    }
}

// ===========================================================================
// Fused QKV GEMM + tensor-core attention (fp16 mma m16n8k16, ldmatrix frags).
// Grid (8, 512). Block: 256 threads = 8 warps (4 wm x 2 wn).
// CTA tile: M=256 (8 batches), N=64 (2 heads) x 3 matrices.
// Warp tile: WM=64, WN=32. Each warp owns 2 attention problems.
// (unchanged from R16)
// ===========================================================================
#define BK2 64
#define SH 72
#define AH 40
#define F_STAGE_HALVES ((256 + 3 * 64) * SH)          // 32256
#define FUSED_SMEM_BYTES (3 * F_STAGE_HALVES * 2)     // 193536

extern "C" __global__ void __launch_bounds__(256, 1) fused_qkv_attn(
    const __half* __restrict__ X,
    const __half* __restrict__ Wq, const __half* __restrict__ Wk,
    const __half* __restrict__ Wv, __half* __restrict__ Ot)
{
    extern __shared__ __half smem_h[];

    const int tid  = threadIdx.x;
    const int lane = tid & 31;
    const int warp = tid >> 5;
    const int wm   = warp & 3;
    const int wn   = warp >> 2;
    const int g    = lane >> 2;
    const int t4   = lane & 3;

    const int m0 = blockIdx.y * 256;
    const int n0 = blockIdx.x * 64;

    const uint32_t smem_u = (uint32_t)__cvta_generic_to_shared(smem_h);

    const int arow_l = lane & 15;
    const int acol_l = (lane >> 4) << 3;
    const int brow_l = (lane & 7) + ((lane >> 4) << 3);
    const int bcol_l = ((lane >> 3) & 1) << 3;

    float acc[3][4][4][4];
    #pragma unroll
    for (int m = 0; m < 3; m++)
        #pragma unroll
        for (int mi = 0; mi < 4; mi++)
            #pragma unroll
            for (int ni = 0; ni < 4; ni++)
                #pragma unroll
                for (int r = 0; r < 4; r++) acc[m][mi][ni][r] = 0.f;

    const __half* Wg[3] = {Wq, Wk, Wv};

    auto load_chunk = [&](int c) {
        const uint32_t st = smem_u + (uint32_t)((c % 3) * F_STAGE_HALVES) * 2u;
        const int kt = c * BK2;
        #pragma unroll
        for (int j = 0; j < 8; j++) {
            const int idx = tid + 256 * j;
            const int row = idx >> 3, c16 = idx & 7;
            cp_async16(st + (uint32_t)(row * SH + c16 * 8) * 2u,
                       X + (size_t)(m0 + row) * KDIM + kt + c16 * 8);
        }
        #pragma unroll
        for (int j = 0; j < 6; j++) {
            const int idx = tid + 256 * j;
            const int m = idx >> 9, row = (idx >> 3) & 63, c16 = idx & 7;
            cp_async16(st + (uint32_t)(256 * SH + m * 64 * SH + row * SH + c16 * 8) * 2u,
                       Wg[m] + (size_t)(n0 + row) * KDIM + kt + c16 * 8);
        }
    };

    const int NT = KDIM / BK2;   // 8

    load_chunk(0); cp_async_commit();
    load_chunk(1); cp_async_commit();

    for (int i = 0; i < NT; i++) {
        cp_async_wait<1>();
        __syncthreads();

        const int lt = i + 2;
        if (lt < NT) load_chunk(lt);
        cp_async_commit();

        const uint32_t stg = smem_u + (uint32_t)((i % 3) * F_STAGE_HALVES) * 2u;

        #pragma unroll
        for (int kk = 0; kk < BK2; kk += 16) {
            uint32_t af[4][4];
            #pragma unroll
            for (int mi = 0; mi < 4; mi++) {
                const uint32_t a_addr = stg +
                    (uint32_t)((wm * 64 + mi * 16 + arow_l) * SH + kk + acol_l) * 2u;
                ldsm_x4(af[mi][0], af[mi][1], af[mi][2], af[mi][3], a_addr);
            }
            uint32_t bf[3][4][2];
            #pragma unroll
            for (int m = 0; m < 3; m++) {
                #pragma unroll
                for (int np = 0; np < 2; np++) {
                    const uint32_t b_addr = stg +
                        (uint32_t)(256 * SH + m * 64 * SH +
                                   (wn * 32 + np * 16 + brow_l) * SH + kk + bcol_l) * 2u;
                    ldsm_x4(bf[m][2 * np][0], bf[m][2 * np][1],
                            bf[m][2 * np + 1][0], bf[m][2 * np + 1][1], b_addr);
                }
            }
            #pragma unroll
            for (int m = 0; m < 3; m++)
                #pragma unroll
                for (int ni = 0; ni < 4; ni++)
                    #pragma unroll
                    for (int mi = 0; mi < 4; mi++)
                        mma_f16(acc[m][mi][ni], af[mi], bf[m][ni]);
        }
    }

    // --- phase switch ---
    cp_async_wait<0>();
    __syncthreads();

    __half* aw = smem_h + warp * (6 * 32 * AH);
    const uint32_t aw_u = smem_u + (uint32_t)(warp * (6 * 32 * AH)) * 2u;

    #pragma unroll
    for (int p = 0; p < 2; p++) {
        __half* Qb = aw + (p * 3 + 0) * (32 * AH);
        __half* Kb = aw + (p * 3 + 1) * (32 * AH);
        __half* Vb = aw + (p * 3 + 2) * (32 * AH);   // Vt[d][s]
        #pragma unroll
        for (int miL = 0; miL < 2; miL++) {
            const int mi = p * 2 + miL;
            #pragma unroll
            for (int ni = 0; ni < 4; ni++) {
                const int r = miL * 16 + g;
                const int c = ni * 8 + t4 * 2;
                *(__half2*)&Qb[r * AH + c] =
                    __floats2half2_rn(acc[0][mi][ni][0], acc[0][mi][ni][1]);
                *(__half2*)&Qb[(r + 8) * AH + c] =
                    __floats2half2_rn(acc[0][mi][ni][2], acc[0][mi][ni][3]);
                *(__half2*)&Kb[r * AH + c] =
                    __floats2half2_rn(acc[1][mi][ni][0], acc[1][mi][ni][1]);
                *(__half2*)&Kb[(r + 8) * AH + c] =
                    __floats2half2_rn(acc[1][mi][ni][2], acc[1][mi][ni][3]);
                Vb[c * AH + r]           = __float2half_rn(acc[2][mi][ni][0]);
                Vb[(c + 1) * AH + r]     = __float2half_rn(acc[2][mi][ni][1]);
                Vb[c * AH + r + 8]       = __float2half_rn(acc[2][mi][ni][2]);
                Vb[(c + 1) * AH + r + 8] = __float2half_rn(acc[2][mi][ni][3]);
            }
        }
    }
    __syncwarp();

    const float scale = 0.17677669529663689f;  // 32^-0.5

    for (int p = 0; p < 2; p++) {
        __half* Qb = aw + (p * 3 + 0) * (32 * AH);
        __half* Kb = aw + (p * 3 + 1) * (32 * AH);
        const uint32_t Qb_u = aw_u + (uint32_t)((p * 3 + 0) * (32 * AH)) * 2u;
        const uint32_t Kb_u = aw_u + (uint32_t)((p * 3 + 1) * (32 * AH)) * 2u;
        const uint32_t Vb_u = aw_u + (uint32_t)((p * 3 + 2) * (32 * AH)) * 2u;

        // ---- S = Q K^T ----
        float sacc[2][4][4];
        #pragma unroll
        for (int mi = 0; mi < 2; mi++)
            #pragma unroll
            for (int ni = 0; ni < 4; ni++)
                #pragma unroll
                for (int r = 0; r < 4; r++) sacc[mi][ni][r] = 0.f;

        #pragma unroll
        for (int kk = 0; kk < 32; kk += 16) {
            uint32_t af[2][4];
            #pragma unroll
            for (int mi = 0; mi < 2; mi++)
                ldsm_x4(af[mi][0], af[mi][1], af[mi][2], af[mi][3],
                        Qb_u + (uint32_t)((mi * 16 + arow_l) * AH + kk + acol_l) * 2u);
            uint32_t bf[4][2];
            #pragma unroll
            for (int np = 0; np < 2; np++)
                ldsm_x4(bf[2 * np][0], bf[2 * np][1], bf[2 * np + 1][0], bf[2 * np + 1][1],
                        Kb_u + (uint32_t)((np * 16 + brow_l) * AH + kk + bcol_l) * 2u);
            #pragma unroll
            for (int ni = 0; ni < 4; ni++)
                #pragma unroll
                for (int mi = 0; mi < 2; mi++)
                    mma_f16(sacc[mi][ni], af[mi], bf[ni]);
        }

        // ---- mask + scale + softmax ----
        float rmax[2][2] = {{-1e30f, -1e30f}, {-1e30f, -1e30f}};
        #pragma unroll
        for (int mi = 0; mi < 2; mi++)
            #pragma unroll
            for (int ni = 0; ni < 4; ni++)
                #pragma unroll
                for (int j = 0; j < 4; j++) {
                    const int row = mi * 16 + g + (j >> 1) * 8;
                    const int col = ni * 8 + t4 * 2 + (j & 1);
                    float v = (col <= row) ? sacc[mi][ni][j] * scale : -1e30f;
                    sacc[mi][ni][j] = v;
                    rmax[mi][j >> 1] = fmaxf(rmax[mi][j >> 1], v);
                }
        #pragma unroll
        for (int mi = 0; mi < 2; mi++)
            #pragma unroll
            for (int h8 = 0; h8 < 2; h8++) {
                float m = rmax[mi][h8];
                m = fmaxf(m, __shfl_xor_sync(0xffffffffu, m, 1));
                m = fmaxf(m, __shfl_xor_sync(0xffffffffu, m, 2));
                rmax[mi][h8] = m;
            }
        float rsum[2][2] = {{0.f, 0.f}, {0.f, 0.f}};
        #pragma unroll
        for (int mi = 0; mi < 2; mi++)
            #pragma unroll
            for (int ni = 0; ni < 4; ni++)
                #pragma unroll
                for (int j = 0; j < 4; j++) {
                    float e = __expf(sacc[mi][ni][j] - rmax[mi][j >> 1]);
                    sacc[mi][ni][j] = e;
                    rsum[mi][j >> 1] += e;
                }
        float inv[2][2];
        #pragma unroll
        for (int mi = 0; mi < 2; mi++)
            #pragma unroll
            for (int h8 = 0; h8 < 2; h8++) {
                float s = rsum[mi][h8];
                s += __shfl_xor_sync(0xffffffffu, s, 1);
                s += __shfl_xor_sync(0xffffffffu, s, 2);
                inv[mi][h8] = 1.0f / s;
            }

        // ---- unnormalized P (fp16) into Qb ----
        __syncwarp();
        #pragma unroll
        for (int mi = 0; mi < 2; mi++)
            #pragma unroll
            for (int ni = 0; ni < 4; ni++) {
                const int r = mi * 16 + g;
                const int c = ni * 8 + t4 * 2;
                *(__half2*)&Qb[r * AH + c] =
                    __floats2half2_rn(sacc[mi][ni][0], sacc[mi][ni][1]);
                *(__half2*)&Qb[(r + 8) * AH + c] =
                    __floats2half2_rn(sacc[mi][ni][2], sacc[mi][ni][3]);
            }
        __syncwarp();

        // ---- O = P V ----
        float oacc[2][4][4];
        #pragma unroll
        for (int mi = 0; mi < 2; mi++)
            #pragma unroll
            for (int ni = 0; ni < 4; ni++)
                #pragma unroll
                for (int r = 0; r < 4; r++) oacc[mi][ni][r] = 0.f;

        #pragma unroll
        for (int kk = 0; kk < 32; kk += 16) {
            uint32_t af[2][4];
            #pragma unroll
            for (int mi = 0; mi < 2; mi++)
                ldsm_x4(af[mi][0], af[mi][1], af[mi][2], af[mi][3],
                        Qb_u + (uint32_t)((mi * 16 + arow_l) * AH + kk + acol_l) * 2u);
            uint32_t bf[4][2];
            #pragma unroll
            for (int np = 0; np < 2; np++)
                ldsm_x4(bf[2 * np][0], bf[2 * np][1], bf[2 * np + 1][0], bf[2 * np + 1][1],
                        Vb_u + (uint32_t)((np * 16 + brow_l) * AH + kk + bcol_l) * 2u);
            #pragma unroll
            for (int ni = 0; ni < 4; ni++)
                #pragma unroll
                for (int mi = 0; mi < 2; mi++)
                    mma_f16(oacc[mi][ni], af[mi], bf[ni]);
        }

        // ---- normalize, dump O[t][d] to Kb, store ----
        __syncwarp();
        #pragma unroll
        for (int mi = 0; mi < 2; mi++)
            #pragma unroll
            for (int ni = 0; ni < 4; ni++) {
                const int r = mi * 16 + g;
                const int c = ni * 8 + t4 * 2;
                *(__half2*)&Kb[r * AH + c] =
                    __floats2half2_rn(oacc[mi][ni][0] * inv[mi][0],
                                      oacc[mi][ni][1] * inv[mi][0]);
                *(__half2*)&Kb[(r + 8) * AH + c] =
                    __floats2half2_rn(oacc[mi][ni][2] * inv[mi][1],
                                      oacc[mi][ni][3] * inv[mi][1]);
            }
        __syncwarp();

        const int b = blockIdx.y * 8 + wm * 2 + p;
        const int h = blockIdx.x * 2 + wn;
        #pragma unroll
        for (int d = 0; d < 32; d++)
            Ot[(size_t)(b * 32 + d) * 512 + h * 32 + lane] = Kb[lane * AH + d];
        __syncwarp();
    }
}

// ===========================================================================
// Projection NT GEMM (fp16 mma m16n8k16, ldmatrix frags)
// BM=256, BN=64, BK=32 halves, 256 threads = 8 warps (4 wm x 2 wn),
// warp tile 64x32 (acc 64 regs) -> launch_bounds(256,2): 2 CTAs/SM,
// 4 warps/SMSP for HMMA latency hiding.
// ===========================================================================
#define PBK 32
#define SH2 40
#define PROJ_STAGE_HALVES ((256 + 64) * SH2)             // 12800
#define PROJ_SMEM_BYTES (3 * PROJ_STAGE_HALVES * 2)      // 76800

__global__ void __launch_bounds__(256, 2) proj_gemm_f16(
    const __half* __restrict__ A, const __half* __restrict__ Bw,
    float* __restrict__ C, const float* __restrict__ bias)
{
    extern __shared__ __half smem_h[];

    const int tid  = threadIdx.x;
    const int lane = tid & 31;
    const int warp = tid >> 5;
    const int wm   = warp & 3;    // 64-row stripe
    const int wn   = warp >> 2;   // 32-col stripe
    const int g    = lane >> 2;
    const int t4   = lane & 3;

    const int m0 = blockIdx.y * 256;
    const int n0 = blockIdx.x * 64;

    const uint32_t smem_u = (uint32_t)__cvta_generic_to_shared(smem_h);

    const int arow_l = lane & 15;
    const int acol_l = (lane >> 4) << 3;
    const int brow_l = (lane & 7) + ((lane >> 4) << 3);
    const int bcol_l = ((lane >> 3) & 1) << 3;

    float acc[4][4][4];
    #pragma unroll
    for (int mi = 0; mi < 4; mi++)
        #pragma unroll
        for (int ni = 0; ni < 4; ni++)
            #pragma unroll
            for (int r = 0; r < 4; r++) acc[mi][ni][r] = 0.f;

    // loader: A 256 rows x 4 chunks = 1024 (4/thread); B 64 x 4 = 256 (1/thread)
    auto load_chunk = [&](int s, int kt) {
        const uint32_t base = smem_u + (uint32_t)(s * PROJ_STAGE_HALVES) * 2u;
        #pragma unroll
        for (int j = 0; j < 4; j++) {
            const int idx = tid + 256 * j;
            const int row = idx >> 2, c16 = idx & 3;
            cp_async16(base + (uint32_t)(row * SH2 + c16 * 8) * 2u,
                       A + (size_t)(m0 + row) * KDIM + kt + c16 * 8);
        }
        {
            const int row = tid >> 2, c16 = tid & 3;
            cp_async16(base + (uint32_t)(256 * SH2 + row * SH2 + c16 * 8) * 2u,
                       Bw + (size_t)(n0 + row) * KDIM + kt + c16 * 8);
        }
    };

    const int NT = KDIM / PBK;   // 16

    load_chunk(0, 0);   cp_async_commit();
    load_chunk(1, PBK); cp_async_commit();

    for (int i = 0; i < NT; i++) {
        cp_async_wait<1>();
        __syncthreads();

        const int lt = i + 2;
        if (lt < NT) load_chunk(lt % 3, lt * PBK);
        cp_async_commit();

        const uint32_t stg = smem_u + (uint32_t)((i % 3) * PROJ_STAGE_HALVES) * 2u;

        #pragma unroll
        for (int kk = 0; kk < PBK; kk += 16) {
            uint32_t af[4][4];
            #pragma unroll
            for (int mi = 0; mi < 4; mi++)
                ldsm_x4(af[mi][0], af[mi][1], af[mi][2], af[mi][3],
                        stg + (uint32_t)((wm * 64 + mi * 16 + arow_l) * SH2 + kk + acol_l) * 2u);
            uint32_t bf[4][2];
            #pragma unroll
            for (int np = 0; np < 2; np++)
                ldsm_x4(bf[2 * np][0], bf[2 * np][1], bf[2 * np + 1][0], bf[2 * np + 1][1],
                        stg + (uint32_t)(256 * SH2 + (wn * 32 + np * 16 + brow_l) * SH2 + kk + bcol_l) * 2u);
            #pragma unroll
            for (int mi = 0; mi < 4; mi++)
                #pragma unroll
                for (int ni = 0; ni < 4; ni++)
                    mma_f16(acc[mi][ni], af[mi], bf[ni]);
        }
    }

    #pragma unroll
    for (int mi = 0; mi < 4; mi++) {
        #pragma unroll
        for (int ni = 0; ni < 4; ni++) {
            const int m = m0 + wm * 64 + mi * 16 + g;
            const int n = n0 + wn * 32 + ni * 8 + t4 * 2;
            const float bv0 = bias[n];
            const float bv1 = bias[n + 1];
            float2 v01 = make_float2(acc[mi][ni][0] + bv0, acc[mi][ni][1] + bv1);
            float2 v23 = make_float2(acc[mi][ni][2] + bv0, acc[mi][ni][3] + bv1);
            *(float2*)(&C[(size_t)m * NDIM + n])       = v01;
            *(float2*)(&C[(size_t)(m + 8) * NDIM + n]) = v23;
        }
    }
}

// ---------------------------------------------------------------------------
// Launch
// ---------------------------------------------------------------------------
extern "C" void kernel_launch(void* const* d_in, const int* in_sizes, int n_in,
                              void* d_out, int out_size) {
    const float* x  = (const float*)d_in[0];
    const float* Wq = (const float*)d_in[1];
    const float* Wk = (const float*)d_in[2];
    const float* Wv = (const float*)d_in[3];
    const float* Wp = (const float*)d_in[4];
    const float* bp = (const float*)d_in[5];
    float* out = (float*)d_out;

    __half *gx, *go, *gwq, *gwk, *gwv, *gwp;
    cudaGetSymbolAddress((void**)&gx,  g_Xh);
    cudaGetSymbolAddress((void**)&go,  g_Oth);
    cudaGetSymbolAddress((void**)&gwq, g_Wqh);
    cudaGetSymbolAddress((void**)&gwk, g_Wkh);
    cudaGetSymbolAddress((void**)&gwv, g_Wvh);
    cudaGetSymbolAddress((void**)&gwp, g_Wph);

    static bool attr_set = false;
    if (!attr_set) {
        cudaFuncSetAttribute(fused_qkv_attn,
                             cudaFuncAttributeMaxDynamicSharedMemorySize,
                             FUSED_SMEM_BYTES);
        cudaFuncSetAttribute(proj_gemm_f16,
                             cudaFuncAttributeMaxDynamicSharedMemorySize,
                             PROJ_SMEM_BYTES);
        attr_set = true;
    }

    const int xn8 = (MDIM * KDIM) / 8;
    const int wn8 = (NDIM * KDIM) / 8;
    round_f16_kernel<<<xn8 / 256, 256>>>((const float4*)x, (__half2*)gx, xn8);
    dim3 wgrid(wn8 / 256, 4);
    round_f16_w4_kernel<<<wgrid, 256>>>(
        (const float4*)Wq, (const float4*)Wk, (const float4*)Wv, (const float4*)Wp,
        (__half2*)gwq, (__half2*)gwk, (__half2*)gwv, (__half2*)gwp, wn8);

    dim3 fgrid(NDIM / 64, MDIM / 256);   // (8, 512)
    fused_qkv_attn<<<fgrid, 256, FUSED_SMEM_BYTES>>>(gx, gwq, gwk, gwv, go);

    dim3 pgrid(NDIM / 64, MDIM / 256);   // (8, 512)
    proj_gemm_f16<<<pgrid, 256, PROJ_SMEM_BYTES>>>(go, gwp, out, bp);
}